// round 1
// baseline (speedup 1.0000x reference)
#include <cuda_runtime.h>
#include <math.h>

#define NB 2
#define DD 16
#define HH 32
#define WW 32
#define CC 64
#define GG 4
#define GCH 16
#define PP 27
#define DINP 18
#define HINP 34
#define WINP 34

// padded value-projection scratch: (N, Din, Hin, Win, C), ~10.65 MB
__device__ float g_xp[(size_t)NB * DINP * HINP * WINP * CC];

// ---------------------------------------------------------------------------
// Kernel 1: x = input @ in_w^T + in_b, written into zero-padded buffer.
// One block of 64 threads per PADDED voxel (border voxels just write 0).
// ---------------------------------------------------------------------------
__global__ void __launch_bounds__(64) proj_pad_kernel(
    const float* __restrict__ input,
    const float* __restrict__ in_w,
    const float* __restrict__ in_b)
{
    int v = blockIdx.x;           // padded voxel index
    int c = threadIdx.x;          // output channel
    int x = v % WINP; int t = v / WINP;
    int y = t % HINP; t /= HINP;
    int z = t % DINP; int n = t / DINP;

    size_t out_idx = (size_t)v * CC + c;
    int xi = x - 1, yi = y - 1, zi = z - 1;
    if (xi < 0 || xi >= WW || yi < 0 || yi >= HH || zi < 0 || zi >= DD) {
        g_xp[out_idx] = 0.0f;
        return;                   // branch is uniform across the block
    }

    __shared__ float sh[CC];
    const float* ip = input + ((size_t)((n * DD + zi) * HH + yi) * WW + xi) * CC;
    sh[c] = ip[c];
    __syncthreads();

    float acc = in_b[c];
    const float* wr = in_w + c * CC;
#pragma unroll 16
    for (int k = 0; k < CC; k++) acc = fmaf(sh[k], wr[k], acc);
    g_xp[out_idx] = acc;
}

// ---------------------------------------------------------------------------
// Kernel 2: fused dwconv -> LN -> GELU -> offset/mask heads -> softmax ->
//           deformable trilinear sampling -> output projection.
// One block of 128 threads per output voxel.
// ---------------------------------------------------------------------------
__global__ void __launch_bounds__(128) dcnv3_fused_kernel(
    const float* __restrict__ input,
    const float* __restrict__ dw_w,
    const float* __restrict__ dw_b,
    const float* __restrict__ ln_g,
    const float* __restrict__ ln_b,
    const float* __restrict__ off_w,
    const float* __restrict__ off_b,
    const float* __restrict__ mask_w,
    const float* __restrict__ mask_b,
    const float* __restrict__ out_w,
    const float* __restrict__ out_b,
    float* __restrict__ out)
{
    int v = blockIdx.x;           // output voxel (N*D*H*W)
    int tid = threadIdx.x;
    int x = v % WW; int t = v / WW;
    int y = t % HH; t /= HH;
    int z = t % DD; int n = t / DD;

    __shared__ float x1[CC];            // x1 vector (dwconv -> LN -> GELU)
    __shared__ float offs[GG * PP * 3]; // 324 offsets
    __shared__ float maskv[GG * PP];    // 108 mask values
    __shared__ float outv[CC];          // sampled per-channel output
    __shared__ float red[4];            // LN reduction scratch

    // ---- phase 1: depthwise 3x3x3 conv, 'same' zero padding ----
    if (tid < CC) {
        int c = tid;
        float acc = dw_b[c];
        const float* wp = dw_w + c * 27;
#pragma unroll
        for (int a = 0; a < 3; a++) {
            int zz = z + a - 1; if (zz < 0 || zz >= DD) continue;
#pragma unroll
            for (int b = 0; b < 3; b++) {
                int yy = y + b - 1; if (yy < 0 || yy >= HH) continue;
#pragma unroll
                for (int e = 0; e < 3; e++) {
                    int xx = x + e - 1; if (xx < 0 || xx >= WW) continue;
                    float iv = input[((size_t)((n * DD + zz) * HH + yy) * WW + xx) * CC + c];
                    acc = fmaf(iv, wp[a * 9 + b * 3 + e], acc);
                }
            }
        }
        x1[c] = acc;
    }
    __syncthreads();

    // ---- phase 2: LayerNorm over C + exact GELU ----
    if (tid < CC) {
        float val = x1[tid];
        float s = val, s2 = val * val;
#pragma unroll
        for (int o = 16; o > 0; o >>= 1) {
            s  += __shfl_down_sync(0xffffffffu, s,  o);
            s2 += __shfl_down_sync(0xffffffffu, s2, o);
        }
        if ((tid & 31) == 0) { red[(tid >> 5) * 2] = s; red[(tid >> 5) * 2 + 1] = s2; }
    }
    __syncthreads();
    float mean = (red[0] + red[2]) * (1.0f / CC);
    float var  = (red[1] + red[3]) * (1.0f / CC) - mean * mean;
    float rstd = rsqrtf(var + 1e-6f);
    if (tid < CC) {
        float xv = (x1[tid] - mean) * rstd * ln_g[tid] + ln_b[tid];
        xv = 0.5f * xv * (1.0f + erff(xv * 0.70710678118654752f)); // exact GELU
        x1[tid] = xv;
    }
    __syncthreads();

    // ---- phase 3: offset head (324 rows) + mask head (108 rows) ----
    for (int r = tid; r < 324 + 108; r += 128) {
        const float* wr;
        float acc;
        if (r < 324) { wr = off_w  + (size_t)r * CC;         acc = off_b[r]; }
        else         { wr = mask_w + (size_t)(r - 324) * CC; acc = mask_b[r - 324]; }
#pragma unroll 16
        for (int k = 0; k < CC; k++) acc = fmaf(x1[k], wr[k], acc);
        if (r < 324) offs[r] = acc; else maskv[r - 324] = acc;
    }
    __syncthreads();

    // ---- phase 4: softmax over P per group ----
    if (tid < GG) {
        float mx = -1e30f;
        for (int p = 0; p < PP; p++) mx = fmaxf(mx, maskv[tid * PP + p]);
        float s = 0.0f;
        for (int p = 0; p < PP; p++) {
            float e = __expf(maskv[tid * PP + p] - mx);
            maskv[tid * PP + p] = e; s += e;
        }
        float inv = 1.0f / s;
        for (int p = 0; p < PP; p++) maskv[tid * PP + p] *= inv;
    }
    __syncthreads();

    // ---- phase 5: deformable trilinear sampling ----
    // warp = group; within warp: c = lane&15, half = lane>>4 splits the 27 points
    {
        int g = tid >> 5, lane = tid & 31, c = lane & 15, half = lane >> 4;
        const float* xpg = g_xp + (size_t)n * (DINP * HINP * WINP * CC) + g * GCH + c;
        float acc = 0.0f;
        for (int p = half; p < PP; p += 2) {
            int i0 = p / 9, i1 = (p / 3) % 3, i2 = p % 3; // (kw, kh, kd)
            int gp = g * PP + p;
            // exact collapse of the normalized-coordinate chain:
            float px = (float)(x + i0) + offs[gp * 3 + 0];
            float py = (float)(y + i1) + offs[gp * 3 + 1];
            float pz = (float)(z + i2) + offs[gp * 3 + 2];
            float m  = maskv[gp];
            float fx0 = floorf(px), fy0 = floorf(py), fz0 = floorf(pz);
            int x0 = (int)fx0, y0 = (int)fy0, z0 = (int)fz0;
            float fx = px - fx0, fy = py - fy0, fz = pz - fz0;
            float s = 0.0f;
#pragma unroll
            for (int dz = 0; dz < 2; dz++) {
                int zi = z0 + dz; if (zi < 0 || zi >= DINP) continue;
                float wz = dz ? fz : 1.0f - fz;
#pragma unroll
                for (int dy = 0; dy < 2; dy++) {
                    int yi = y0 + dy; if (yi < 0 || yi >= HINP) continue;
                    float wy = dy ? fy : 1.0f - fy;
#pragma unroll
                    for (int dx = 0; dx < 2; dx++) {
                        int xi = x0 + dx; if (xi < 0 || xi >= WINP) continue;
                        float wx = dx ? fx : 1.0f - fx;
                        float val = xpg[((size_t)(zi * HINP + yi) * WINP + xi) * CC];
                        s = fmaf(wz * wy * wx, val, s);
                    }
                }
            }
            acc = fmaf(m, s, acc);
        }
        acc += __shfl_down_sync(0xffffffffu, acc, 16);
        if (half == 0) outv[g * GCH + c] = acc;
    }
    __syncthreads();

    // ---- phase 6: output projection ----
    if (tid < CC) {
        float acc = out_b[tid];
        const float* wr = out_w + (size_t)tid * CC;
#pragma unroll 16
        for (int k = 0; k < CC; k++) acc = fmaf(outv[k], wr[k], acc);
        out[(size_t)v * CC + tid] = acc;
    }
}

extern "C" void kernel_launch(void* const* d_in, const int* in_sizes, int n_in,
                              void* d_out, int out_size)
{
    const float* input  = (const float*)d_in[0];
    const float* dw_w   = (const float*)d_in[1];
    const float* dw_b   = (const float*)d_in[2];
    const float* ln_g   = (const float*)d_in[3];
    const float* ln_b   = (const float*)d_in[4];
    const float* off_w  = (const float*)d_in[5];
    const float* off_b  = (const float*)d_in[6];
    const float* mask_w = (const float*)d_in[7];
    const float* mask_b = (const float*)d_in[8];
    const float* in_w   = (const float*)d_in[9];
    const float* in_b   = (const float*)d_in[10];
    const float* out_w  = (const float*)d_in[11];
    const float* out_b  = (const float*)d_in[12];
    float* out = (float*)d_out;

    int padded_voxels = NB * DINP * HINP * WINP;   // 41616
    int out_voxels    = NB * DD * HH * WW;         // 32768

    proj_pad_kernel<<<padded_voxels, 64>>>(input, in_w, in_b);
    dcnv3_fused_kernel<<<out_voxels, 128>>>(
        input, dw_w, dw_b, ln_g, ln_b,
        off_w, off_b, mask_w, mask_b,
        out_w, out_b, out);
}

// round 2
// speedup vs baseline: 5.7062x; 5.7062x over previous
#include <cuda_runtime.h>
#include <math.h>

#define NB 2
#define DD 16
#define HH 32
#define WW 32
#define CC 64
#define GG 4
#define GCH 16
#define PP 27
#define DINP 18
#define HINP 34
#define WINP 34

// padded value-projection scratch: (N, Din, Hin, Win, C), ~10.65 MB
__device__ float g_xp[(size_t)NB * DINP * HINP * WINP * CC];

// ---------------------------------------------------------------------------
// Kernel 1: x = input @ in_w^T + in_b into zero-padded buffer.
// 128 threads per padded voxel. GEMV: 2 rows per warp, float4 per lane,
// half-warp shuffle reduce (fully coalesced weight reads).
// ---------------------------------------------------------------------------
__global__ void __launch_bounds__(128) proj_pad_kernel(
    const float* __restrict__ input,
    const float* __restrict__ in_w,
    const float* __restrict__ in_b)
{
    int v = blockIdx.x;           // padded voxel index
    int tid = threadIdx.x;
    int x = v % WINP; int t = v / WINP;
    int y = t % HINP; t /= HINP;
    int z = t % DINP; int n = t / DINP;

    float* outp = g_xp + (size_t)v * CC;
    int xi = x - 1, yi = y - 1, zi = z - 1;
    if (xi < 0 || xi >= WW || yi < 0 || yi >= HH || zi < 0 || zi >= DD) {
        if (tid < 16) ((float4*)outp)[tid] = make_float4(0.f, 0.f, 0.f, 0.f);
        return;                   // uniform branch across block
    }

    __shared__ __align__(16) float sh[CC];
    __shared__ float res[CC];
    if (tid < CC) {
        const float* ip = input + ((size_t)((n * DD + zi) * HH + yi) * WW + xi) * CC;
        sh[tid] = ip[tid];
    }
    __syncthreads();

    int lane = tid & 31, warp = tid >> 5;
    int half = lane >> 4, hl = lane & 15;
    float4 xv = ((const float4*)sh)[hl];
#pragma unroll
    for (int i = 0; i < 8; i++) {
        int r = i * 8 + warp * 2 + half;
        float4 w = ((const float4*)(in_w + (size_t)r * CC))[hl];
        float p = fmaf(w.x, xv.x, fmaf(w.y, xv.y, fmaf(w.z, xv.z, w.w * xv.w)));
        p += __shfl_xor_sync(0xffffffffu, p, 8);
        p += __shfl_xor_sync(0xffffffffu, p, 4);
        p += __shfl_xor_sync(0xffffffffu, p, 2);
        p += __shfl_xor_sync(0xffffffffu, p, 1);
        if (hl == 0) res[r] = p + in_b[r];
    }
    __syncthreads();
    if (tid < CC) outp[tid] = res[tid];
}

// ---------------------------------------------------------------------------
// Kernel 2: fused dwconv -> LN -> GELU -> heads -> softmax -> deformable
//           trilinear sampling -> output projection. 128 threads per voxel.
// ---------------------------------------------------------------------------
__global__ void __launch_bounds__(128) dcnv3_fused_kernel(
    const float* __restrict__ input,
    const float* __restrict__ dw_w,
    const float* __restrict__ dw_b,
    const float* __restrict__ ln_g,
    const float* __restrict__ ln_b,
    const float* __restrict__ off_w,
    const float* __restrict__ off_b,
    const float* __restrict__ mask_w,
    const float* __restrict__ mask_b,
    const float* __restrict__ out_w,
    const float* __restrict__ out_b,
    float* __restrict__ out)
{
    int v = blockIdx.x;           // output voxel (N*D*H*W)
    int tid = threadIdx.x;
    int x = v % WW; int t = v / WW;
    int y = t % HH; t /= HH;
    int z = t % DD; int n = t / DD;

    __shared__ __align__(16) float x1[CC];    // dwconv -> LN -> GELU vector
    __shared__ __align__(16) float outv[CC];  // sampled per-channel output
    __shared__ float offs[GG * PP * 3];       // 324 offsets
    __shared__ float maskv[GG * PP];          // 108 mask values
    __shared__ float res[CC];                 // final projection
    __shared__ float red[4];                  // LN reduction scratch

    int lane = tid & 31, warp = tid >> 5;
    int half = lane >> 4, hl = lane & 15;

    // ---- phase 1: depthwise 3x3x3 conv, 'same' zero padding ----
    if (tid < CC) {
        int c = tid;
        float acc = dw_b[c];
        const float* wp = dw_w + c * 27;
#pragma unroll
        for (int a = 0; a < 3; a++) {
            int zz = z + a - 1; if (zz < 0 || zz >= DD) continue;
#pragma unroll
            for (int b = 0; b < 3; b++) {
                int yy = y + b - 1; if (yy < 0 || yy >= HH) continue;
#pragma unroll
                for (int e = 0; e < 3; e++) {
                    int xx = x + e - 1; if (xx < 0 || xx >= WW) continue;
                    float iv = input[((size_t)((n * DD + zz) * HH + yy) * WW + xx) * CC + c];
                    acc = fmaf(iv, wp[a * 9 + b * 3 + e], acc);
                }
            }
        }
        x1[c] = acc;
    }
    __syncthreads();

    // ---- phase 2: LayerNorm over C + exact GELU ----
    if (tid < CC) {
        float val = x1[tid];
        float s = val, s2 = val * val;
#pragma unroll
        for (int o = 16; o > 0; o >>= 1) {
            s  += __shfl_down_sync(0xffffffffu, s,  o);
            s2 += __shfl_down_sync(0xffffffffu, s2, o);
        }
        if (lane == 0) { red[warp * 2] = s; red[warp * 2 + 1] = s2; }
    }
    __syncthreads();
    float mean = (red[0] + red[2]) * (1.0f / CC);
    float var  = (red[1] + red[3]) * (1.0f / CC) - mean * mean;
    float rstd = rsqrtf(var + 1e-6f);
    if (tid < CC) {
        float xv = (x1[tid] - mean) * rstd * ln_g[tid] + ln_b[tid];
        xv = 0.5f * xv * (1.0f + erff(xv * 0.70710678118654752f)); // exact GELU
        x1[tid] = xv;
    }
    __syncthreads();

    // ---- phase 3: offset head (324 rows) + mask head (108 rows) ----
    // 2 rows per warp per iter, float4 per lane, half-warp shuffle reduce.
    {
        float4 xv = ((const float4*)x1)[hl];
#pragma unroll 6
        for (int i = 0; i < 54; i++) {
            int r = i * 8 + warp * 2 + half;
            const float* wr;
            float b;
            if (r < 324) { wr = off_w  + (size_t)r * CC;         b = off_b[r]; }
            else         { wr = mask_w + (size_t)(r - 324) * CC; b = mask_b[r - 324]; }
            float4 w = ((const float4*)wr)[hl];
            float p = fmaf(w.x, xv.x, fmaf(w.y, xv.y, fmaf(w.z, xv.z, w.w * xv.w)));
            p += __shfl_xor_sync(0xffffffffu, p, 8);
            p += __shfl_xor_sync(0xffffffffu, p, 4);
            p += __shfl_xor_sync(0xffffffffu, p, 2);
            p += __shfl_xor_sync(0xffffffffu, p, 1);
            if (hl == 0) {
                if (r < 324) offs[r] = p + b;
                else         maskv[r - 324] = p + b;
            }
        }
    }
    __syncthreads();

    // ---- phase 4: softmax over P per group ----
    if (tid < GG) {
        float mx = -1e30f;
        for (int p = 0; p < PP; p++) mx = fmaxf(mx, maskv[tid * PP + p]);
        float s = 0.0f;
        for (int p = 0; p < PP; p++) {
            float e = __expf(maskv[tid * PP + p] - mx);
            maskv[tid * PP + p] = e; s += e;
        }
        float inv = 1.0f / s;
        for (int p = 0; p < PP; p++) maskv[tid * PP + p] *= inv;
    }
    __syncthreads();

    // ---- phase 5: deformable trilinear sampling ----
    // warp = group; within warp: c = lane&15, half splits the 27 points
    {
        int g = warp, c = hl;
        const float* xpg = g_xp + (size_t)n * (DINP * HINP * WINP * CC) + g * GCH + c;
        float acc = 0.0f;
        for (int p = half; p < PP; p += 2) {
            int i0 = p / 9, i1 = (p / 3) % 3, i2 = p % 3; // (kw, kh, kd)
            int gp = g * PP + p;
            // exact collapse of the normalized-coordinate chain:
            float px = (float)(x + i0) + offs[gp * 3 + 0];
            float py = (float)(y + i1) + offs[gp * 3 + 1];
            float pz = (float)(z + i2) + offs[gp * 3 + 2];
            float m  = maskv[gp];
            float fx0 = floorf(px), fy0 = floorf(py), fz0 = floorf(pz);
            int x0 = (int)fx0, y0 = (int)fy0, z0 = (int)fz0;
            float fx = px - fx0, fy = py - fy0, fz = pz - fz0;
            float s = 0.0f;
#pragma unroll
            for (int dz = 0; dz < 2; dz++) {
                int zi = z0 + dz; if (zi < 0 || zi >= DINP) continue;
                float wz = dz ? fz : 1.0f - fz;
#pragma unroll
                for (int dy = 0; dy < 2; dy++) {
                    int yi = y0 + dy; if (yi < 0 || yi >= HINP) continue;
                    float wy = dy ? fy : 1.0f - fy;
#pragma unroll
                    for (int dx = 0; dx < 2; dx++) {
                        int xi = x0 + dx; if (xi < 0 || xi >= WINP) continue;
                        float wx = dx ? fx : 1.0f - fx;
                        float val = xpg[((size_t)(zi * HINP + yi) * WINP + xi) * CC];
                        s = fmaf(wz * wy * wx, val, s);
                    }
                }
            }
            acc = fmaf(m, s, acc);
        }
        acc += __shfl_down_sync(0xffffffffu, acc, 16);
        if (half == 0) outv[g * GCH + c] = acc;
    }
    __syncthreads();

    // ---- phase 6: output projection (64 rows, same coalesced GEMV) ----
    {
        float4 ov = ((const float4*)outv)[hl];
#pragma unroll
        for (int i = 0; i < 8; i++) {
            int r = i * 8 + warp * 2 + half;
            float4 w = ((const float4*)(out_w + (size_t)r * CC))[hl];
            float p = fmaf(w.x, ov.x, fmaf(w.y, ov.y, fmaf(w.z, ov.z, w.w * ov.w)));
            p += __shfl_xor_sync(0xffffffffu, p, 8);
            p += __shfl_xor_sync(0xffffffffu, p, 4);
            p += __shfl_xor_sync(0xffffffffu, p, 2);
            p += __shfl_xor_sync(0xffffffffu, p, 1);
            if (hl == 0) res[r] = p + out_b[r];
        }
    }
    __syncthreads();
    if (tid < CC) out[(size_t)v * CC + tid] = res[tid];
}

extern "C" void kernel_launch(void* const* d_in, const int* in_sizes, int n_in,
                              void* d_out, int out_size)
{
    const float* input  = (const float*)d_in[0];
    const float* dw_w   = (const float*)d_in[1];
    const float* dw_b   = (const float*)d_in[2];
    const float* ln_g   = (const float*)d_in[3];
    const float* ln_b   = (const float*)d_in[4];
    const float* off_w  = (const float*)d_in[5];
    const float* off_b  = (const float*)d_in[6];
    const float* mask_w = (const float*)d_in[7];
    const float* mask_b = (const float*)d_in[8];
    const float* in_w   = (const float*)d_in[9];
    const float* in_b   = (const float*)d_in[10];
    const float* out_w  = (const float*)d_in[11];
    const float* out_b  = (const float*)d_in[12];
    float* out = (float*)d_out;

    int padded_voxels = NB * DINP * HINP * WINP;   // 41616
    int out_voxels    = NB * DD * HH * WW;         // 32768

    proj_pad_kernel<<<padded_voxels, 128>>>(input, in_w, in_b);
    dcnv3_fused_kernel<<<out_voxels, 128>>>(
        input, dw_w, dw_b, ln_g, ln_b,
        off_w, off_b, mask_w, mask_b,
        out_w, out_b, out);
}

// round 3
// speedup vs baseline: 11.0353x; 1.9339x over previous
#include <cuda_runtime.h>
#include <math.h>

#define NB 2
#define DD 16
#define HH 32
#define WW 32
#define CC 64
#define GG 4
#define GCH 16
#define PP 27
#define DINP 18
#define HINP 34
#define WINP 34
#define VX 8          // voxels per block

// padded value-projection scratch: (N, Din, Hin, Win, C), ~10.65 MB
__device__ float g_xp[(size_t)NB * DINP * HINP * WINP * CC];

// ---------------------------------------------------------------------------
// Multi-voxel half-warp reduction: p[v] holds partial dot (over the 16-lane
// k-split "hl") for voxel v. Returns, on lane hl (0..15), the full sum for
// voxel v = hl & 7 (lanes 8..15 hold duplicates of 0..7).
// 15 shuffles for 8 reductions.
// ---------------------------------------------------------------------------
__device__ __forceinline__ float multi_reduce8(float p[VX], int hl)
{
#pragma unroll
    for (int v = 0; v < 8; v++) p[v] += __shfl_xor_sync(0xffffffffu, p[v], 8);
    float q[4];
    bool b4 = (hl & 4) != 0;
#pragma unroll
    for (int j = 0; j < 4; j++) {
        float send = b4 ? p[j] : p[j + 4];
        float recv = __shfl_xor_sync(0xffffffffu, send, 4);
        q[j] = (b4 ? p[j + 4] : p[j]) + recv;
    }
    float s[2];
    bool b2 = (hl & 2) != 0;
#pragma unroll
    for (int j = 0; j < 2; j++) {
        float send = b2 ? q[j] : q[j + 2];
        float recv = __shfl_xor_sync(0xffffffffu, send, 2);
        s[j] = (b2 ? q[j + 2] : q[j]) + recv;
    }
    bool b1 = (hl & 1) != 0;
    float send = b1 ? s[0] : s[1];
    float recv = __shfl_xor_sync(0xffffffffu, send, 1);
    return (b1 ? s[1] : s[0]) + recv;
}

// ---------------------------------------------------------------------------
// Kernel 1: value projection into zero-padded buffer, 8 padded voxels/block.
// ---------------------------------------------------------------------------
__global__ void __launch_bounds__(256, 3) proj_pad_kernel(
    const float* __restrict__ input,
    const float* __restrict__ in_w,
    const float* __restrict__ in_b)
{
    int tid = threadIdx.x;
    int vb = blockIdx.x * VX;

    __shared__ __align__(16) float shx[VX * CC];
    __shared__ __align__(16) float res[VX * CC];
    __shared__ int sflag[VX];

    for (int o = tid; o < VX * CC; o += 256) {
        int v = o >> 6, c = o & 63;
        int pv = vb + v;
        int xx = pv % WINP; int t = pv / WINP;
        int yy = t % HINP; t /= HINP;
        int zz = t % DINP; int n = t / DINP;
        int xi = xx - 1, yi = yy - 1, zi = zz - 1;
        bool in = (xi >= 0 && xi < WW && yi >= 0 && yi < HH && zi >= 0 && zi < DD);
        if (c == 0) sflag[v] = in ? 1 : 0;
        shx[o] = in ? input[((size_t)((n * DD + zi) * HH + yi) * WW + xi) * CC + c] : 0.0f;
    }
    __syncthreads();

    int lane = tid & 31, warp = tid >> 5;
    int half = lane >> 4, hl = lane & 15;

    float4 xv[VX];
#pragma unroll
    for (int v = 0; v < VX; v++) xv[v] = ((const float4*)(shx + v * CC))[hl];

#pragma unroll
    for (int i = 0; i < 4; i++) {
        int r = i * 16 + warp * 2 + half;
        float4 w = ((const float4*)(in_w + (size_t)r * CC))[hl];
        float p[VX];
#pragma unroll
        for (int v = 0; v < VX; v++)
            p[v] = fmaf(w.x, xv[v].x, fmaf(w.y, xv[v].y, fmaf(w.z, xv[v].z, w.w * xv[v].w)));
        float tot = multi_reduce8(p, hl);
        if (hl < 8)
            res[hl * CC + r] = sflag[hl] ? (tot + in_b[r]) : 0.0f;
    }
    __syncthreads();

    if (tid < 128)
        ((float4*)(g_xp + (size_t)vb * CC))[tid] = ((const float4*)res)[tid];
}

// ---------------------------------------------------------------------------
// Kernel 2: fused dwconv -> LN -> GELU -> heads -> softmax -> sampling ->
//           output projection. 8 consecutive x-voxels per block, 256 threads.
// ---------------------------------------------------------------------------
__global__ void __launch_bounds__(256, 3) dcnv3_fused_kernel(
    const float* __restrict__ input,
    const float* __restrict__ dw_w,
    const float* __restrict__ dw_b,
    const float* __restrict__ ln_g,
    const float* __restrict__ ln_b,
    const float* __restrict__ off_w,
    const float* __restrict__ off_b,
    const float* __restrict__ mask_w,
    const float* __restrict__ mask_b,
    const float* __restrict__ out_w,
    const float* __restrict__ out_b,
    float* __restrict__ out)
{
    int tid = threadIdx.x;
    int vb = blockIdx.x * VX;
    int x0 = vb % WW; int t = vb / WW;
    int y = t % HH; t /= HH;
    int z = t % DD; int n = t / DD;

    int lane = tid & 31, warp = tid >> 5;
    int half = lane >> 4, hl = lane & 15;

    __shared__ __align__(16) float slab[3 * 3 * 10 * CC];  // input slab
    __shared__ __align__(16) float dwws[CC * 27];           // staged dw weights
    __shared__ __align__(16) float x1s[VX * CC];
    __shared__ __align__(16) float outv[VX * CC];
    __shared__ __align__(16) float res[VX * CC];
    __shared__ float offs[VX * GG * PP * 3];                // 8*324
    __shared__ float maskv[VX * GG * PP];                   // 8*108

    // ---- phase 1a: stage dw weights + input slab ----
    for (int e = tid; e < CC * 27 / 4; e += 256)            // 432 float4
        ((float4*)dwws)[e] = ((const float4*)dw_w)[e];
    for (int e = tid; e < 3 * 3 * 10 * 16; e += 256) {      // 1440 float4
        int c4 = e & 15;
        int xx = (e >> 4) % 10;
        int r = e / 160;
        int yy = r % 3, zz = r / 3;
        int gz = z + zz - 1, gy = y + yy - 1, gx = x0 + xx - 1;
        float4 val = make_float4(0.f, 0.f, 0.f, 0.f);
        if (gz >= 0 && gz < DD && gy >= 0 && gy < HH && gx >= 0 && gx < WW)
            val = ((const float4*)(input + ((size_t)((n * DD + gz) * HH + gy) * WW + gx) * CC))[c4];
        ((float4*)slab)[e] = val;
    }
    __syncthreads();

    // ---- phase 1b: depthwise 3x3x3 conv from smem ----
    for (int o = tid; o < VX * CC; o += 256) {
        int v = o >> 6, c = o & 63;
        float acc = dw_b[c];
#pragma unroll
        for (int zz = 0; zz < 3; zz++)
#pragma unroll
            for (int yy = 0; yy < 3; yy++)
#pragma unroll
                for (int e = 0; e < 3; e++)
                    acc = fmaf(slab[((zz * 3 + yy) * 10 + v + e) * CC + c],
                               dwws[c * 27 + zz * 9 + yy * 3 + e], acc);
        x1s[o] = acc;
    }
    __syncthreads();

    // ---- phase 2: LayerNorm + exact GELU (warp = voxel) ----
    {
        int v = warp;
        float a = x1s[v * CC + lane];
        float b = x1s[v * CC + lane + 32];
        float s = a + b, s2 = a * a + b * b;
#pragma unroll
        for (int o = 16; o > 0; o >>= 1) {
            s  += __shfl_xor_sync(0xffffffffu, s,  o);
            s2 += __shfl_xor_sync(0xffffffffu, s2, o);
        }
        float mean = s * (1.0f / CC);
        float var  = s2 * (1.0f / CC) - mean * mean;
        float rstd = rsqrtf(var + 1e-6f);
        a = (a - mean) * rstd * ln_g[lane] + ln_b[lane];
        b = (b - mean) * rstd * ln_g[lane + 32] + ln_b[lane + 32];
        a = 0.5f * a * (1.0f + erff(a * 0.70710678118654752f));
        b = 0.5f * b * (1.0f + erff(b * 0.70710678118654752f));
        x1s[v * CC + lane] = a;
        x1s[v * CC + lane + 32] = b;
    }
    __syncthreads();

    // ---- phase 3: offset head (324 rows) + mask head (108 rows), 8 voxels ----
    {
        float4 xv[VX];
#pragma unroll
        for (int v = 0; v < VX; v++) xv[v] = ((const float4*)(x1s + v * CC))[hl];
        for (int i = 0; i < 27; i++) {
            int r = i * 16 + warp * 2 + half;
            const float* wr = (r < 324) ? (off_w + (size_t)r * CC)
                                        : (mask_w + (size_t)(r - 324) * CC);
            float4 w = ((const float4*)wr)[hl];
            float p[VX];
#pragma unroll
            for (int v = 0; v < VX; v++)
                p[v] = fmaf(w.x, xv[v].x, fmaf(w.y, xv[v].y, fmaf(w.z, xv[v].z, w.w * xv[v].w)));
            float tot = multi_reduce8(p, hl);
            if (hl < 8) {
                if (r < 324) offs[hl * 324 + r] = tot + off_b[r];
                else         maskv[hl * 108 + (r - 324)] = tot + mask_b[r - 324];
            }
        }
    }
    __syncthreads();

    // ---- phase 4: softmax over P per (voxel, group) ----
    if (tid < 32) {
        float* row = maskv + (tid >> 2) * 108 + (tid & 3) * PP;
        float mx = -1e30f;
        for (int p = 0; p < PP; p++) mx = fmaxf(mx, row[p]);
        float s = 0.0f;
        for (int p = 0; p < PP; p++) { float e = __expf(row[p] - mx); row[p] = e; s += e; }
        float inv = 1.0f / s;
        for (int p = 0; p < PP; p++) row[p] *= inv;
    }
    __syncthreads();

    // ---- phase 5: deformable trilinear sampling (float4 per lane) ----
    // warp handles 4 (voxel,group) pairs; lane: q = chunk of 4 channels,
    // p8 = point slot (8 slots over 27 points).
    {
        int q = lane & 3, p8 = lane >> 2;
        for (int sgi = warp; sgi < VX * GG; sgi += 8) {
            int v = sgi >> 2, g = sgi & 3;
            const float* xpg = g_xp + (size_t)n * (DINP * HINP * WINP * CC) + g * GCH + q * 4;
            const float* ofv = offs + v * 324 + g * 81;
            const float* mkv = maskv + v * 108 + g * 27;
            int xg = x0 + v;
            float4 acc = make_float4(0.f, 0.f, 0.f, 0.f);
            for (int p = p8; p < PP; p += 8) {
                int i0 = p / 9, i1 = (p / 3) % 3, i2 = p % 3;   // (kw, kh, kd)
                float px = (float)(xg + i0) + ofv[p * 3 + 0];
                float py = (float)(y  + i1) + ofv[p * 3 + 1];
                float pz = (float)(z  + i2) + ofv[p * 3 + 2];
                float m  = mkv[p];
                float fx0 = floorf(px), fy0 = floorf(py), fz0 = floorf(pz);
                int xi0 = (int)fx0, yi0 = (int)fy0, zi0 = (int)fz0;
                float fx = px - fx0, fy = py - fy0, fz = pz - fz0;
                float4 s4 = make_float4(0.f, 0.f, 0.f, 0.f);
#pragma unroll
                for (int dz = 0; dz < 2; dz++) {
                    int zi = zi0 + dz; if (zi < 0 || zi >= DINP) continue;
                    float wz = dz ? fz : 1.0f - fz;
#pragma unroll
                    for (int dy = 0; dy < 2; dy++) {
                        int yi = yi0 + dy; if (yi < 0 || yi >= HINP) continue;
                        float wy = dy ? fy : 1.0f - fy;
#pragma unroll
                        for (int dx = 0; dx < 2; dx++) {
                            int xi = xi0 + dx; if (xi < 0 || xi >= WINP) continue;
                            float wt = wz * wy * (dx ? fx : 1.0f - fx);
                            float4 val = *(const float4*)(xpg + ((size_t)(zi * HINP + yi) * WINP + xi) * CC);
                            s4.x = fmaf(wt, val.x, s4.x);
                            s4.y = fmaf(wt, val.y, s4.y);
                            s4.z = fmaf(wt, val.z, s4.z);
                            s4.w = fmaf(wt, val.w, s4.w);
                        }
                    }
                }
                acc.x = fmaf(m, s4.x, acc.x);
                acc.y = fmaf(m, s4.y, acc.y);
                acc.z = fmaf(m, s4.z, acc.z);
                acc.w = fmaf(m, s4.w, acc.w);
            }
#pragma unroll
            for (int o = 16; o >= 4; o >>= 1) {
                acc.x += __shfl_xor_sync(0xffffffffu, acc.x, o);
                acc.y += __shfl_xor_sync(0xffffffffu, acc.y, o);
                acc.z += __shfl_xor_sync(0xffffffffu, acc.z, o);
                acc.w += __shfl_xor_sync(0xffffffffu, acc.w, o);
            }
            if (p8 == 0)
                ((float4*)(outv + v * CC + g * GCH))[q] = acc;
        }
    }
    __syncthreads();

    // ---- phase 6: output projection (64 rows, 8 voxels) ----
    {
        float4 ov[VX];
#pragma unroll
        for (int v = 0; v < VX; v++) ov[v] = ((const float4*)(outv + v * CC))[hl];
#pragma unroll
        for (int i = 0; i < 4; i++) {
            int r = i * 16 + warp * 2 + half;
            float4 w = ((const float4*)(out_w + (size_t)r * CC))[hl];
            float p[VX];
#pragma unroll
            for (int v = 0; v < VX; v++)
                p[v] = fmaf(w.x, ov[v].x, fmaf(w.y, ov[v].y, fmaf(w.z, ov[v].z, w.w * ov[v].w)));
            float tot = multi_reduce8(p, hl);
            if (hl < 8)
                res[hl * CC + r] = tot + out_b[r];
        }
    }
    __syncthreads();

    if (tid < 128)
        ((float4*)(out + (size_t)vb * CC))[tid] = ((const float4*)res)[tid];
}

extern "C" void kernel_launch(void* const* d_in, const int* in_sizes, int n_in,
                              void* d_out, int out_size)
{
    const float* input  = (const float*)d_in[0];
    const float* dw_w   = (const float*)d_in[1];
    const float* dw_b   = (const float*)d_in[2];
    const float* ln_g   = (const float*)d_in[3];
    const float* ln_b   = (const float*)d_in[4];
    const float* off_w  = (const float*)d_in[5];
    const float* off_b  = (const float*)d_in[6];
    const float* mask_w = (const float*)d_in[7];
    const float* mask_b = (const float*)d_in[8];
    const float* in_w   = (const float*)d_in[9];
    const float* in_b   = (const float*)d_in[10];
    const float* out_w  = (const float*)d_in[11];
    const float* out_b  = (const float*)d_in[12];
    float* out = (float*)d_out;

    int proj_blocks  = NB * DINP * HINP * WINP / VX;   // 5202
    int fused_blocks = NB * DD * HH * WW / VX;         // 4096

    proj_pad_kernel<<<proj_blocks, 256>>>(input, in_w, in_b);
    dcnv3_fused_kernel<<<fused_blocks, 256>>>(
        input, dw_w, dw_b, ln_g, ln_b,
        off_w, off_b, mask_w, mask_b,
        out_w, out_b, out);
}

// round 4
// speedup vs baseline: 11.7666x; 1.0663x over previous
#include <cuda_runtime.h>
#include <math.h>

#define NB 2
#define DD 16
#define HH 32
#define WW 32
#define CC 64
#define GG 4
#define GCH 16
#define PP 27
#define DINP 18
#define HINP 34
#define WINP 34
#define VX 8          // voxels per block

// padded value-projection scratch: (N, Din, Hin, Win, C), ~10.65 MB
__device__ float g_xp[(size_t)NB * DINP * HINP * WINP * CC];

// ---------------------------------------------------------------------------
// Multi-voxel half-warp reduction: p[v] holds partial dot (over the 16-lane
// k-split "hl") for voxel v. Returns, on lanes hl=0..7, the full sum for
// voxel v = hl. 15 shuffles for 8 reductions.
// ---------------------------------------------------------------------------
__device__ __forceinline__ float multi_reduce8(float p[VX], int hl)
{
#pragma unroll
    for (int v = 0; v < 8; v++) p[v] += __shfl_xor_sync(0xffffffffu, p[v], 8);
    float q[4];
    bool b4 = (hl & 4) != 0;
#pragma unroll
    for (int j = 0; j < 4; j++) {
        float send = b4 ? p[j] : p[j + 4];
        float recv = __shfl_xor_sync(0xffffffffu, send, 4);
        q[j] = (b4 ? p[j + 4] : p[j]) + recv;
    }
    float s[2];
    bool b2 = (hl & 2) != 0;
#pragma unroll
    for (int j = 0; j < 2; j++) {
        float send = b2 ? q[j] : q[j + 2];
        float recv = __shfl_xor_sync(0xffffffffu, send, 2);
        s[j] = (b2 ? q[j + 2] : q[j]) + recv;
    }
    bool b1 = (hl & 1) != 0;
    float send = b1 ? s[0] : s[1];
    float recv = __shfl_xor_sync(0xffffffffu, send, 1);
    return (b1 ? s[1] : s[0]) + recv;
}

// ---------------------------------------------------------------------------
// Kernel 1: value projection into zero-padded buffer, 8 padded voxels/block.
// ---------------------------------------------------------------------------
__global__ void __launch_bounds__(256, 3) proj_pad_kernel(
    const float* __restrict__ input,
    const float* __restrict__ in_w,
    const float* __restrict__ in_b)
{
    int tid = threadIdx.x;
    int vb = blockIdx.x * VX;

    __shared__ __align__(16) float shx[VX * CC];
    __shared__ __align__(16) float res[VX * CC];
    __shared__ int sflag[VX];

    for (int o = tid; o < VX * CC; o += 256) {
        int v = o >> 6, c = o & 63;
        int pv = vb + v;
        int xx = pv % WINP; int t = pv / WINP;
        int yy = t % HINP; t /= HINP;
        int zz = t % DINP; int n = t / DINP;
        int xi = xx - 1, yi = yy - 1, zi = zz - 1;
        bool in = (xi >= 0 && xi < WW && yi >= 0 && yi < HH && zi >= 0 && zi < DD);
        if (c == 0) sflag[v] = in ? 1 : 0;
        shx[o] = in ? input[((size_t)((n * DD + zi) * HH + yi) * WW + xi) * CC + c] : 0.0f;
    }
    __syncthreads();

    int lane = tid & 31, warp = tid >> 5;
    int half = lane >> 4, hl = lane & 15;

    float4 xv[VX];
#pragma unroll
    for (int v = 0; v < VX; v++) xv[v] = ((const float4*)(shx + v * CC))[hl];

#pragma unroll
    for (int i = 0; i < 4; i++) {
        int r = i * 16 + warp * 2 + half;
        float4 w = ((const float4*)(in_w + (size_t)r * CC))[hl];
        float p[VX];
#pragma unroll
        for (int v = 0; v < VX; v++)
            p[v] = fmaf(w.x, xv[v].x, fmaf(w.y, xv[v].y, fmaf(w.z, xv[v].z, w.w * xv[v].w)));
        float tot = multi_reduce8(p, hl);
        if (hl < 8)
            res[hl * CC + r] = sflag[hl] ? (tot + in_b[r]) : 0.0f;
    }
    __syncthreads();

    if (tid < 128)
        ((float4*)(g_xp + (size_t)vb * CC))[tid] = ((const float4*)res)[tid];
}

// ---------------------------------------------------------------------------
// Kernel 2: fused pipeline, 8 consecutive x-voxels per block, 256 threads.
// Shared memory is manually overlaid:
//   [0, 31104)      : phase 1 = slab(23040)+dwws(6912); phase >=4.5 = params (864*9*4)
//   [31104, 41472)  : offs (phase 3-4.5); outv (phase 5-6)
//   [41472, 44928)  : maskv
//   [44928, 46976)  : x1s (phase 1b-3); res (phase 6)
// ---------------------------------------------------------------------------
__global__ void __launch_bounds__(256, 3) dcnv3_fused_kernel(
    const float* __restrict__ input,
    const float* __restrict__ dw_w,
    const float* __restrict__ dw_b,
    const float* __restrict__ ln_g,
    const float* __restrict__ ln_b,
    const float* __restrict__ off_w,
    const float* __restrict__ off_b,
    const float* __restrict__ mask_w,
    const float* __restrict__ mask_b,
    const float* __restrict__ out_w,
    const float* __restrict__ out_b,
    float* __restrict__ out)
{
    __shared__ __align__(16) char smem_raw[46976];
    float* slab   = (float*)smem_raw;              // 5760 floats
    float* dwws   = slab + 5760;                   // 1728 floats
    float* params = (float*)smem_raw;              // 864*9 floats (overlays slab)
    float* offs   = (float*)(smem_raw + 31104);    // 2592 floats
    float* outv   = offs;                          // 512 floats (overlays offs)
    float* maskv  = (float*)(smem_raw + 41472);    // 864 floats
    float* x1s    = (float*)(smem_raw + 44928);    // 512 floats
    float* res    = x1s;                           // 512 floats (overlays x1s)

    int tid = threadIdx.x;
    int vb = blockIdx.x * VX;
    int x0 = vb % WW; int t = vb / WW;
    int y = t % HH; t /= HH;
    int z = t % DD; int n = t / DD;

    int lane = tid & 31, warp = tid >> 5;
    int half = lane >> 4, hl = lane & 15;

    // ---- phase 1a: stage dw weights + input slab (3 x 3 x 10 x 64) ----
    for (int e = tid; e < CC * 27 / 4; e += 256)            // 432 float4
        ((float4*)dwws)[e] = ((const float4*)dw_w)[e];
    for (int e = tid; e < 3 * 3 * 10 * 16; e += 256) {      // 1440 float4
        int c4 = e & 15;
        int xx = (e >> 4) % 10;
        int r = e / 160;
        int yy = r % 3, zz = r / 3;
        int gz = z + zz - 1, gy = y + yy - 1, gx = x0 + xx - 1;
        float4 val = make_float4(0.f, 0.f, 0.f, 0.f);
        if (gz >= 0 && gz < DD && gy >= 0 && gy < HH && gx >= 0 && gx < WW)
            val = ((const float4*)(input + ((size_t)((n * DD + gz) * HH + gy) * WW + gx) * CC))[c4];
        ((float4*)slab)[e] = val;
    }
    __syncthreads();

    // ---- phase 1b: depthwise conv, sliding window in x ----
    // thread = (channel c, voxel pair): computes voxels v0, v0+1
    {
        int c = tid & 63, pair = tid >> 6;     // pair in 0..3
        int v0 = pair * 2;
        float acc0 = dw_b[c], acc1 = acc0;
#pragma unroll
        for (int zz = 0; zz < 3; zz++) {
#pragma unroll
            for (int yy = 0; yy < 3; yy++) {
                const float* srow = slab + ((zz * 3 + yy) * 10 + v0) * CC + c;
                const float* wrow = dwws + c * 27 + zz * 9 + yy * 3;
                float s0 = srow[0];
                float s1 = srow[CC];
                float s2 = srow[2 * CC];
                float s3 = srow[3 * CC];
                float w0 = wrow[0], w1 = wrow[1], w2 = wrow[2];
                acc0 = fmaf(s0, w0, fmaf(s1, w1, fmaf(s2, w2, acc0)));
                acc1 = fmaf(s1, w0, fmaf(s2, w1, fmaf(s3, w2, acc1)));
            }
        }
        x1s[v0 * CC + c] = acc0;
        x1s[(v0 + 1) * CC + c] = acc1;
    }
    __syncthreads();

    // ---- phase 2: LayerNorm + exact GELU (warp = voxel) ----
    {
        int v = warp;
        float a = x1s[v * CC + lane];
        float b = x1s[v * CC + lane + 32];
        float s = a + b, s2 = a * a + b * b;
#pragma unroll
        for (int o = 16; o > 0; o >>= 1) {
            s  += __shfl_xor_sync(0xffffffffu, s,  o);
            s2 += __shfl_xor_sync(0xffffffffu, s2, o);
        }
        float mean = s * (1.0f / CC);
        float var  = s2 * (1.0f / CC) - mean * mean;
        float rstd = rsqrtf(var + 1e-6f);
        a = (a - mean) * rstd * ln_g[lane] + ln_b[lane];
        b = (b - mean) * rstd * ln_g[lane + 32] + ln_b[lane + 32];
        a = 0.5f * a * (1.0f + erff(a * 0.70710678118654752f));
        b = 0.5f * b * (1.0f + erff(b * 0.70710678118654752f));
        x1s[v * CC + lane] = a;
        x1s[v * CC + lane + 32] = b;
    }
    __syncthreads();

    // ---- phase 3: offset head (324 rows) + mask head (108 rows), 8 voxels ----
    {
        float4 xv[VX];
#pragma unroll
        for (int v = 0; v < VX; v++) xv[v] = ((const float4*)(x1s + v * CC))[hl];
        for (int i = 0; i < 27; i++) {
            int r = i * 16 + warp * 2 + half;
            const float* wr = (r < 324) ? (off_w + (size_t)r * CC)
                                        : (mask_w + (size_t)(r - 324) * CC);
            float4 w = ((const float4*)wr)[hl];
            float p[VX];
#pragma unroll
            for (int v = 0; v < VX; v++)
                p[v] = fmaf(w.x, xv[v].x, fmaf(w.y, xv[v].y, fmaf(w.z, xv[v].z, w.w * xv[v].w)));
            float tot = multi_reduce8(p, hl);
            if (hl < 8) {
                if (r < 324) offs[hl * 324 + r] = tot + off_b[r];
                else         maskv[hl * 108 + (r - 324)] = tot + mask_b[r - 324];
            }
        }
    }
    __syncthreads();

    // ---- phase 4: softmax over P per (voxel, group), warp per 4 rows ----
    {
#pragma unroll
        for (int rr = 0; rr < 4; rr++) {
            int row = warp * 4 + rr;
            float val = (lane < PP) ? maskv[row * PP + lane] : -1e30f;
            float mx = val;
#pragma unroll
            for (int o = 16; o > 0; o >>= 1)
                mx = fmaxf(mx, __shfl_xor_sync(0xffffffffu, mx, o));
            float e = (lane < PP) ? __expf(val - mx) : 0.0f;
            float s = e;
#pragma unroll
            for (int o = 16; o > 0; o >>= 1)
                s += __shfl_xor_sync(0xffffffffu, s, o);
            if (lane < PP) maskv[row * PP + lane] = e / s;
        }
    }
    __syncthreads();

    // ---- phase 4.5: precompute sampling params per (v,g,p) into smem ----
    // layout: params[e*9 + {m, fx, fy, fz, x0i, y0i, z0i(bits)}]
    for (int e = tid; e < VX * GG * PP; e += 256) {
        int v = e / 108, rem = e % 108;
        int g = rem / 27, p = rem % 27;
        int i0 = p / 9, i1 = (p / 3) % 3, i2 = p % 3;       // (kw, kh, kd)
        const float* ofv = offs + v * 324 + (g * 27 + p) * 3;
        float px = (float)(x0 + v + i0) + ofv[0];
        float py = (float)(y + i1) + ofv[1];
        float pz = (float)(z + i2) + ofv[2];
        float fx0 = floorf(px), fy0 = floorf(py), fz0 = floorf(pz);
        float* P = params + e * 9;
        P[0] = maskv[v * 108 + g * 27 + p];
        P[1] = px - fx0;
        P[2] = py - fy0;
        P[3] = pz - fz0;
        P[4] = __int_as_float((int)fx0);
        P[5] = __int_as_float((int)fy0);
        P[6] = __int_as_float((int)fz0);
    }
    __syncthreads();

    // ---- phase 5: deformable trilinear sampling ----
    // warp handles 4 (voxel,group) pairs; lane: q = 4-channel chunk,
    // p8 = point slot (8 slots over 27 points).
    {
        int q = lane & 3, p8 = lane >> 2;
        for (int sgi = warp; sgi < VX * GG; sgi += 8) {
            int v = sgi >> 2, g = sgi & 3;
            const float* xpg = g_xp + (size_t)n * (DINP * HINP * WINP * CC) + g * GCH + q * 4;
            float4 acc = make_float4(0.f, 0.f, 0.f, 0.f);
            for (int p = p8; p < PP; p += 8) {
                const float* P = params + (sgi * 27 + p) * 9;
                float m  = P[0];
                float fx = P[1], fy = P[2], fz = P[3];
                int xi0 = __float_as_int(P[4]);
                int yi0 = __float_as_int(P[5]);
                int zi0 = __float_as_int(P[6]);
                bool bx[2] = { (unsigned)xi0 < WINP, (unsigned)(xi0 + 1) < WINP };
                bool by[2] = { (unsigned)yi0 < HINP, (unsigned)(yi0 + 1) < HINP };
                bool bz[2] = { (unsigned)zi0 < DINP, (unsigned)(zi0 + 1) < DINP };
                float wx[2] = { 1.0f - fx, fx };
                float wy[2] = { 1.0f - fy, fy };
                float wz[2] = { 1.0f - fz, fz };
                long base = ((long)(zi0 * HINP + yi0) * WINP + xi0) * CC;
                const float* bp = xpg + base;   // deref only on valid corners
                float4 s4 = make_float4(0.f, 0.f, 0.f, 0.f);
#pragma unroll
                for (int dz = 0; dz < 2; dz++) {
#pragma unroll
                    for (int dy = 0; dy < 2; dy++) {
                        float wzy = wz[dz] * wy[dy];
                        bool bzy = bz[dz] && by[dy];
#pragma unroll
                        for (int dx = 0; dx < 2; dx++) {
                            if (bzy && bx[dx]) {
                                float4 val = *(const float4*)(bp +
                                    (dz * (HINP * WINP) + dy * WINP + dx) * CC);
                                float wt = wzy * wx[dx];
                                s4.x = fmaf(wt, val.x, s4.x);
                                s4.y = fmaf(wt, val.y, s4.y);
                                s4.z = fmaf(wt, val.z, s4.z);
                                s4.w = fmaf(wt, val.w, s4.w);
                            }
                        }
                    }
                }
                acc.x = fmaf(m, s4.x, acc.x);
                acc.y = fmaf(m, s4.y, acc.y);
                acc.z = fmaf(m, s4.z, acc.z);
                acc.w = fmaf(m, s4.w, acc.w);
            }
#pragma unroll
            for (int o = 16; o >= 4; o >>= 1) {
                acc.x += __shfl_xor_sync(0xffffffffu, acc.x, o);
                acc.y += __shfl_xor_sync(0xffffffffu, acc.y, o);
                acc.z += __shfl_xor_sync(0xffffffffu, acc.z, o);
                acc.w += __shfl_xor_sync(0xffffffffu, acc.w, o);
            }
            if (p8 == 0)
                ((float4*)(outv + v * CC + g * GCH))[q] = acc;
        }
    }
    __syncthreads();

    // ---- phase 6: output projection (64 rows, 8 voxels) ----
    {
        float4 ov[VX];
#pragma unroll
        for (int v = 0; v < VX; v++) ov[v] = ((const float4*)(outv + v * CC))[hl];
#pragma unroll
        for (int i = 0; i < 4; i++) {
            int r = i * 16 + warp * 2 + half;
            float4 w = ((const float4*)(out_w + (size_t)r * CC))[hl];
            float p[VX];
#pragma unroll
            for (int v = 0; v < VX; v++)
                p[v] = fmaf(w.x, ov[v].x, fmaf(w.y, ov[v].y, fmaf(w.z, ov[v].z, w.w * ov[v].w)));
            float tot = multi_reduce8(p, hl);
            if (hl < 8)
                res[hl * CC + r] = tot + out_b[r];
        }
    }
    __syncthreads();

    if (tid < 128)
        ((float4*)(out + (size_t)vb * CC))[tid] = ((const float4*)res)[tid];
}

extern "C" void kernel_launch(void* const* d_in, const int* in_sizes, int n_in,
                              void* d_out, int out_size)
{
    const float* input  = (const float*)d_in[0];
    const float* dw_w   = (const float*)d_in[1];
    const float* dw_b   = (const float*)d_in[2];
    const float* ln_g   = (const float*)d_in[3];
    const float* ln_b   = (const float*)d_in[4];
    const float* off_w  = (const float*)d_in[5];
    const float* off_b  = (const float*)d_in[6];
    const float* mask_w = (const float*)d_in[7];
    const float* mask_b = (const float*)d_in[8];
    const float* in_w   = (const float*)d_in[9];
    const float* in_b   = (const float*)d_in[10];
    const float* out_w  = (const float*)d_in[11];
    const float* out_b  = (const float*)d_in[12];
    float* out = (float*)d_out;

    int proj_blocks  = NB * DINP * HINP * WINP / VX;   // 5202
    int fused_blocks = NB * DD * HH * WW / VX;         // 4096

    proj_pad_kernel<<<proj_blocks, 256>>>(input, in_w, in_b);
    dcnv3_fused_kernel<<<fused_blocks, 256>>>(
        input, dw_w, dw_b, ln_g, ln_b,
        off_w, off_b, mask_w, mask_b,
        out_w, out_b, out);
}

// round 5
// speedup vs baseline: 12.9647x; 1.1018x over previous
#include <cuda_runtime.h>
#include <math.h>

#define NB 2
#define DD 16
#define HH 32
#define WW 32
#define CC 64
#define GG 4
#define GCH 16
#define PP 27
#define DINP 18
#define HINP 34
#define WINP 34
#define VX 8          // voxels per block

// padded value-projection scratch: (N, Din, Hin, Win, C), ~10.65 MB
__device__ float g_xp[(size_t)NB * DINP * HINP * WINP * CC];

// ---------------------------------------------------------------------------
// Multi-voxel half-warp reduction: p[v] holds partial dot (over the 16-lane
// k-split "hl") for voxel v. Returns, on lanes hl=0..7, the full sum for
// voxel v = hl. 15 shuffles for 8 reductions.
// ---------------------------------------------------------------------------
__device__ __forceinline__ float multi_reduce8(float p[VX], int hl)
{
#pragma unroll
    for (int v = 0; v < 8; v++) p[v] += __shfl_xor_sync(0xffffffffu, p[v], 8);
    float q[4];
    bool b4 = (hl & 4) != 0;
#pragma unroll
    for (int j = 0; j < 4; j++) {
        float send = b4 ? p[j] : p[j + 4];
        float recv = __shfl_xor_sync(0xffffffffu, send, 4);
        q[j] = (b4 ? p[j + 4] : p[j]) + recv;
    }
    float s[2];
    bool b2 = (hl & 2) != 0;
#pragma unroll
    for (int j = 0; j < 2; j++) {
        float send = b2 ? q[j] : q[j + 2];
        float recv = __shfl_xor_sync(0xffffffffu, send, 2);
        s[j] = (b2 ? q[j + 2] : q[j]) + recv;
    }
    bool b1 = (hl & 1) != 0;
    float send = b1 ? s[0] : s[1];
    float recv = __shfl_xor_sync(0xffffffffu, send, 1);
    return (b1 ? s[1] : s[0]) + recv;
}

// ---------------------------------------------------------------------------
// Kernel 1: value projection into zero-padded buffer, 8 padded voxels/block.
// ---------------------------------------------------------------------------
__global__ void __launch_bounds__(256, 4) proj_pad_kernel(
    const float* __restrict__ input,
    const float* __restrict__ in_w,
    const float* __restrict__ in_b)
{
    int tid = threadIdx.x;
    int vb = blockIdx.x * VX;

    __shared__ __align__(16) float shx[VX * CC];
    __shared__ __align__(16) float res[VX * CC];
    __shared__ int sflag[VX];

    for (int o = tid; o < VX * CC; o += 256) {
        int v = o >> 6, c = o & 63;
        int pv = vb + v;
        int xx = pv % WINP; int t = pv / WINP;
        int yy = t % HINP; t /= HINP;
        int zz = t % DINP; int n = t / DINP;
        int xi = xx - 1, yi = yy - 1, zi = zz - 1;
        bool in = (xi >= 0 && xi < WW && yi >= 0 && yi < HH && zi >= 0 && zi < DD);
        if (c == 0) sflag[v] = in ? 1 : 0;
        shx[o] = in ? input[((size_t)((n * DD + zi) * HH + yi) * WW + xi) * CC + c] : 0.0f;
    }
    __syncthreads();

    int lane = tid & 31, warp = tid >> 5;
    int half = lane >> 4, hl = lane & 15;

    float4 xv[VX];
#pragma unroll
    for (int v = 0; v < VX; v++) xv[v] = ((const float4*)(shx + v * CC))[hl];

#pragma unroll
    for (int i = 0; i < 4; i++) {
        int r = i * 16 + warp * 2 + half;
        float4 w = ((const float4*)(in_w + (size_t)r * CC))[hl];
        float p[VX];
#pragma unroll
        for (int v = 0; v < VX; v++)
            p[v] = fmaf(w.x, xv[v].x, fmaf(w.y, xv[v].y, fmaf(w.z, xv[v].z, w.w * xv[v].w)));
        float tot = multi_reduce8(p, hl);
        if (hl < 8)
            res[hl * CC + r] = sflag[hl] ? (tot + in_b[r]) : 0.0f;
    }
    __syncthreads();

    if (tid < 128)
        ((float4*)(g_xp + (size_t)vb * CC))[tid] = ((const float4*)res)[tid];
}

// ---------------------------------------------------------------------------
// Kernel 2: fused pipeline, 8 consecutive x-voxels per block, 256 threads,
// register-capped at 64 for 4 blocks/SM (50% occupancy).
// Shared memory overlays:
//   [0, 31104)      : phase 1 = slab(23040B)+dwws; phase >=4.5 = params
//   [31104, 41472)  : offs (phase 3-4.5); outv (phase 5-6)
//   [41472, 44928)  : maskv
//   [44928, 46976)  : x1s (phase 1b-3); res (phase 6)
// ---------------------------------------------------------------------------
__global__ void __launch_bounds__(256, 4) dcnv3_fused_kernel(
    const float* __restrict__ input,
    const float* __restrict__ dw_w,
    const float* __restrict__ dw_b,
    const float* __restrict__ ln_g,
    const float* __restrict__ ln_b,
    const float* __restrict__ off_w,
    const float* __restrict__ off_b,
    const float* __restrict__ mask_w,
    const float* __restrict__ mask_b,
    const float* __restrict__ out_w,
    const float* __restrict__ out_b,
    float* __restrict__ out)
{
    __shared__ __align__(16) char smem_raw[46976];
    float* slab   = (float*)smem_raw;              // 5760 floats
    float* dwws   = slab + 5760;                   // 1728 floats
    float* params = (float*)smem_raw;              // 864*9 floats (overlays slab)
    float* offs   = (float*)(smem_raw + 31104);    // 2592 floats
    float* outv   = offs;                          // 512 floats (overlays offs)
    float* maskv  = (float*)(smem_raw + 41472);    // 864 floats
    float* x1s    = (float*)(smem_raw + 44928);    // 512 floats
    float* res    = x1s;                           // 512 floats (overlays x1s)

    int tid = threadIdx.x;
    int vb = blockIdx.x * VX;
    int x0 = vb % WW; int t = vb / WW;
    int y = t % HH; t /= HH;
    int z = t % DD; int n = t / DD;

    int lane = tid & 31, warp = tid >> 5;
    int half = lane >> 4, hl = lane & 15;

    // ---- phase 1a: stage dw weights + input slab (3 x 3 x 10 x 64) ----
    for (int e = tid; e < CC * 27 / 4; e += 256)            // 432 float4
        ((float4*)dwws)[e] = ((const float4*)dw_w)[e];
    for (int e = tid; e < 3 * 3 * 10 * 16; e += 256) {      // 1440 float4
        int c4 = e & 15;
        int xx = (e >> 4) % 10;
        int r = e / 160;
        int yy = r % 3, zz = r / 3;
        int gz = z + zz - 1, gy = y + yy - 1, gx = x0 + xx - 1;
        float4 val = make_float4(0.f, 0.f, 0.f, 0.f);
        if (gz >= 0 && gz < DD && gy >= 0 && gy < HH && gx >= 0 && gx < WW)
            val = ((const float4*)(input + ((size_t)((n * DD + gz) * HH + gy) * WW + gx) * CC))[c4];
        ((float4*)slab)[e] = val;
    }
    __syncthreads();

    // ---- phase 1b: depthwise conv, sliding window in x ----
    {
        int c = tid & 63, pair = tid >> 6;     // pair in 0..3
        int v0 = pair * 2;
        float acc0 = dw_b[c], acc1 = acc0;
#pragma unroll
        for (int zz = 0; zz < 3; zz++) {
#pragma unroll
            for (int yy = 0; yy < 3; yy++) {
                const float* srow = slab + ((zz * 3 + yy) * 10 + v0) * CC + c;
                const float* wrow = dwws + c * 27 + zz * 9 + yy * 3;
                float s0 = srow[0];
                float s1 = srow[CC];
                float s2 = srow[2 * CC];
                float s3 = srow[3 * CC];
                float w0 = wrow[0], w1 = wrow[1], w2 = wrow[2];
                acc0 = fmaf(s0, w0, fmaf(s1, w1, fmaf(s2, w2, acc0)));
                acc1 = fmaf(s1, w0, fmaf(s2, w1, fmaf(s3, w2, acc1)));
            }
        }
        x1s[v0 * CC + c] = acc0;
        x1s[(v0 + 1) * CC + c] = acc1;
    }
    __syncthreads();

    // ---- phase 2: LayerNorm + exact GELU (warp = voxel) ----
    {
        int v = warp;
        float a = x1s[v * CC + lane];
        float b = x1s[v * CC + lane + 32];
        float s = a + b, s2 = a * a + b * b;
#pragma unroll
        for (int o = 16; o > 0; o >>= 1) {
            s  += __shfl_xor_sync(0xffffffffu, s,  o);
            s2 += __shfl_xor_sync(0xffffffffu, s2, o);
        }
        float mean = s * (1.0f / CC);
        float var  = s2 * (1.0f / CC) - mean * mean;
        float rstd = rsqrtf(var + 1e-6f);
        a = (a - mean) * rstd * ln_g[lane] + ln_b[lane];
        b = (b - mean) * rstd * ln_g[lane + 32] + ln_b[lane + 32];
        a = 0.5f * a * (1.0f + erff(a * 0.70710678118654752f));
        b = 0.5f * b * (1.0f + erff(b * 0.70710678118654752f));
        x1s[v * CC + lane] = a;
        x1s[v * CC + lane + 32] = b;
    }
    __syncthreads();

    // ---- phase 3: offset head (324 rows) + mask head (108 rows), 8 voxels ----
    {
        float4 xv[VX];
#pragma unroll
        for (int v = 0; v < VX; v++) xv[v] = ((const float4*)(x1s + v * CC))[hl];
        for (int i = 0; i < 27; i++) {
            int r = i * 16 + warp * 2 + half;
            const float* wr = (r < 324) ? (off_w + (size_t)r * CC)
                                        : (mask_w + (size_t)(r - 324) * CC);
            float4 w = ((const float4*)wr)[hl];
            float p[VX];
#pragma unroll
            for (int v = 0; v < VX; v++)
                p[v] = fmaf(w.x, xv[v].x, fmaf(w.y, xv[v].y, fmaf(w.z, xv[v].z, w.w * xv[v].w)));
            float tot = multi_reduce8(p, hl);
            if (hl < 8) {
                if (r < 324) offs[hl * 324 + r] = tot + off_b[r];
                else         maskv[hl * 108 + (r - 324)] = tot + mask_b[r - 324];
            }
        }
    }
    __syncthreads();

    // ---- phase 4: softmax over P per (voxel, group), warp per 4 rows ----
    {
#pragma unroll
        for (int rr = 0; rr < 4; rr++) {
            int row = warp * 4 + rr;
            float val = (lane < PP) ? maskv[row * PP + lane] : -1e30f;
            float mx = val;
#pragma unroll
            for (int o = 16; o > 0; o >>= 1)
                mx = fmaxf(mx, __shfl_xor_sync(0xffffffffu, mx, o));
            float e = (lane < PP) ? __expf(val - mx) : 0.0f;
            float s = e;
#pragma unroll
            for (int o = 16; o > 0; o >>= 1)
                s += __shfl_xor_sync(0xffffffffu, s, o);
            if (lane < PP) maskv[row * PP + lane] = e / s;
        }
    }
    __syncthreads();

    // ---- phase 4.5: precompute sampling params per (v,g,p) into smem ----
    // layout: params[e*9 + {m, fx, fy, fz, x0i, y0i, z0i}]
    for (int e = tid; e < VX * GG * PP; e += 256) {
        int v = e / 108, rem = e % 108;
        int g = rem / 27, p = rem % 27;
        int i0 = p / 9, i1 = (p / 3) % 3, i2 = p % 3;       // (kw, kh, kd)
        const float* ofv = offs + v * 324 + (g * 27 + p) * 3;
        float px = (float)(x0 + v + i0) + ofv[0];
        float py = (float)(y + i1) + ofv[1];
        float pz = (float)(z + i2) + ofv[2];
        float fx0 = floorf(px), fy0 = floorf(py), fz0 = floorf(pz);
        float* P = params + e * 9;
        P[0] = maskv[v * 108 + g * 27 + p];
        P[1] = px - fx0;
        P[2] = py - fy0;
        P[3] = pz - fz0;
        P[4] = __int_as_float((int)fx0);
        P[5] = __int_as_float((int)fy0);
        P[6] = __int_as_float((int)fz0);
    }
    __syncthreads();

    // ---- phase 5: deformable trilinear sampling ----
    // warp handles 4 (voxel,group) pairs; lane: q = 4-channel chunk,
    // p8 = point slot (8 slots over 27 points). 32-bit addressing.
    {
        int q = lane & 3, p8 = lane >> 2;
        const float* xpn = g_xp + (size_t)n * (DINP * HINP * WINP * CC);
        for (int sgi = warp; sgi < VX * GG; sgi += 8) {
            int v = sgi >> 2, g = sgi & 3;
            const float* xpg = xpn + g * GCH + q * 4;
            float4 acc = make_float4(0.f, 0.f, 0.f, 0.f);
            for (int p = p8; p < PP; p += 8) {
                const float* P = params + (sgi * 27 + p) * 9;
                float m  = P[0];
                float fx = P[1], fy = P[2], fz = P[3];
                int xi0 = __float_as_int(P[4]);
                int yi0 = __float_as_int(P[5]);
                int zi0 = __float_as_int(P[6]);
                bool bx0 = (unsigned)xi0 < WINP, bx1 = (unsigned)(xi0 + 1) < WINP;
                bool by0 = (unsigned)yi0 < HINP, by1 = (unsigned)(yi0 + 1) < HINP;
                bool bz0 = (unsigned)zi0 < DINP, bz1 = (unsigned)(zi0 + 1) < DINP;
                float gx1 = fx, gx0 = 1.0f - fx;
                float wz0 = 1.0f - fz, wz1 = fz;
                float wy0 = 1.0f - fy, wy1 = fy;
                int base = ((zi0 * HINP + yi0) * WINP + xi0) * CC;
                const float* bp = xpg + base;
                float4 s4 = make_float4(0.f, 0.f, 0.f, 0.f);
#pragma unroll
                for (int dz = 0; dz < 2; dz++) {
                    bool bz = dz ? bz1 : bz0;
                    float wz = dz ? wz1 : wz0;
#pragma unroll
                    for (int dy = 0; dy < 2; dy++) {
                        float wzy = wz * (dy ? wy1 : wy0);
                        bool bzy = bz && (dy ? by1 : by0);
#pragma unroll
                        for (int dx = 0; dx < 2; dx++) {
                            if (bzy && (dx ? bx1 : bx0)) {
                                float4 val = *(const float4*)(bp +
                                    (dz * (HINP * WINP) + dy * WINP + dx) * CC);
                                float wt = wzy * (dx ? gx1 : gx0);
                                s4.x = fmaf(wt, val.x, s4.x);
                                s4.y = fmaf(wt, val.y, s4.y);
                                s4.z = fmaf(wt, val.z, s4.z);
                                s4.w = fmaf(wt, val.w, s4.w);
                            }
                        }
                    }
                }
                acc.x = fmaf(m, s4.x, acc.x);
                acc.y = fmaf(m, s4.y, acc.y);
                acc.z = fmaf(m, s4.z, acc.z);
                acc.w = fmaf(m, s4.w, acc.w);
            }
#pragma unroll
            for (int o = 16; o >= 4; o >>= 1) {
                acc.x += __shfl_xor_sync(0xffffffffu, acc.x, o);
                acc.y += __shfl_xor_sync(0xffffffffu, acc.y, o);
                acc.z += __shfl_xor_sync(0xffffffffu, acc.z, o);
                acc.w += __shfl_xor_sync(0xffffffffu, acc.w, o);
            }
            if (p8 == 0)
                ((float4*)(outv + v * CC + g * GCH))[q] = acc;
        }
    }
    __syncthreads();

    // ---- phase 6: output projection (64 rows, 8 voxels) ----
    {
        float4 ov[VX];
#pragma unroll
        for (int v = 0; v < VX; v++) ov[v] = ((const float4*)(outv + v * CC))[hl];
#pragma unroll
        for (int i = 0; i < 4; i++) {
            int r = i * 16 + warp * 2 + half;
            float4 w = ((const float4*)(out_w + (size_t)r * CC))[hl];
            float p[VX];
#pragma unroll
            for (int v = 0; v < VX; v++)
                p[v] = fmaf(w.x, ov[v].x, fmaf(w.y, ov[v].y, fmaf(w.z, ov[v].z, w.w * ov[v].w)));
            float tot = multi_reduce8(p, hl);
            if (hl < 8)
                res[hl * CC + r] = tot + out_b[r];
        }
    }
    __syncthreads();

    if (tid < 128)
        ((float4*)(out + (size_t)vb * CC))[tid] = ((const float4*)res)[tid];
}

extern "C" void kernel_launch(void* const* d_in, const int* in_sizes, int n_in,
                              void* d_out, int out_size)
{
    const float* input  = (const float*)d_in[0];
    const float* dw_w   = (const float*)d_in[1];
    const float* dw_b   = (const float*)d_in[2];
    const float* ln_g   = (const float*)d_in[3];
    const float* ln_b   = (const float*)d_in[4];
    const float* off_w  = (const float*)d_in[5];
    const float* off_b  = (const float*)d_in[6];
    const float* mask_w = (const float*)d_in[7];
    const float* mask_b = (const float*)d_in[8];
    const float* in_w   = (const float*)d_in[9];
    const float* in_b   = (const float*)d_in[10];
    const float* out_w  = (const float*)d_in[11];
    const float* out_b  = (const float*)d_in[12];
    float* out = (float*)d_out;

    int proj_blocks  = NB * DINP * HINP * WINP / VX;   // 5202
    int fused_blocks = NB * DD * HH * WW / VX;         // 4096

    proj_pad_kernel<<<proj_blocks, 256>>>(input, in_w, in_b);
    dcnv3_fused_kernel<<<fused_blocks, 256>>>(
        input, dw_w, dw_b, ln_g, ln_b,
        off_w, off_b, mask_w, mask_b,
        out_w, out_b, out);
}

// round 6
// speedup vs baseline: 16.4840x; 1.2714x over previous
#include <cuda_runtime.h>
#include <math.h>

#define NB 2
#define DD 16
#define HH 32
#define WW 32
#define CC 64
#define GG 4
#define GCH 16
#define PP 27
#define DINP 18
#define HINP 34
#define WINP 34
#define VX 8          // voxels per block

// padded value-projection scratch: (N, Din, Hin, Win, C), ~10.65 MB
__device__ float g_xp[(size_t)NB * DINP * HINP * WINP * CC];
// k-major transposed head weights: [kc][r], r padded 432->512 with zeros
__device__ float4 g_wT[16 * 512];
// k-major transposed input-projection weights: [kc][r], r in [0,64)
__device__ float4 g_inT[16 * 64];

// ---------------------------------------------------------------------------
// Setup: transpose weights into k-major float4 layouts (runs every launch;
// tiny, deterministic, graph-capturable).
// ---------------------------------------------------------------------------
__global__ void transpose_weights_kernel(
    const float* __restrict__ off_w,
    const float* __restrict__ mask_w,
    const float* __restrict__ in_w)
{
    int i = blockIdx.x * blockDim.x + threadIdx.x;
    if (i < 16 * 512) {
        int kc = i >> 9, r = i & 511;
        float4 v = make_float4(0.f, 0.f, 0.f, 0.f);
        if (r < 324) {
            const float* s = off_w + (size_t)r * CC + kc * 4;
            v = make_float4(s[0], s[1], s[2], s[3]);
        } else if (r < 432) {
            const float* s = mask_w + (size_t)(r - 324) * CC + kc * 4;
            v = make_float4(s[0], s[1], s[2], s[3]);
        }
        g_wT[i] = v;
    } else {
        int j = i - 16 * 512;
        if (j < 16 * 64) {
            int kc = j >> 6, r = j & 63;
            const float* s = in_w + (size_t)r * CC + kc * 4;
            g_inT[j] = make_float4(s[0], s[1], s[2], s[3]);
        }
    }
}

// ---------------------------------------------------------------------------
// Kernel 1: value projection into zero-padded buffer, 8 padded voxels/block.
// Thread owns one output row for a 2-voxel slice; coalesced k-major weights.
// ---------------------------------------------------------------------------
__global__ void __launch_bounds__(256, 4) proj_pad_kernel(
    const float* __restrict__ input,
    const float* __restrict__ in_b)
{
    int tid = threadIdx.x;
    int vb = blockIdx.x * VX;

    __shared__ __align__(16) float shx[VX * CC];
    __shared__ __align__(16) float res[VX * CC];
    __shared__ int sflag[VX];

    for (int o = tid; o < VX * CC; o += 256) {
        int v = o >> 6, c = o & 63;
        int pv = vb + v;
        int xx = pv % WINP; int t = pv / WINP;
        int yy = t % HINP; t /= HINP;
        int zz = t % DINP; int n = t / DINP;
        int xi = xx - 1, yi = yy - 1, zi = zz - 1;
        bool in = (xi >= 0 && xi < WW && yi >= 0 && yi < HH && zi >= 0 && zi < DD);
        if (c == 0) sflag[v] = in ? 1 : 0;
        shx[o] = in ? input[((size_t)((n * DD + zi) * HH + yi) * WW + xi) * CC + c] : 0.0f;
    }
    __syncthreads();

    {
        int r = tid & 63, vh = tid >> 6;       // vh: 0..3 -> voxels 2vh, 2vh+1
        int v0 = vh * 2, v1 = v0 + 1;
        float a0 = 0.f, a1 = 0.f;
#pragma unroll
        for (int kc = 0; kc < 16; kc++) {
            float4 w  = g_inT[kc * 64 + r];
            float4 xa = ((const float4*)shx)[v0 * 16 + kc];
            float4 xb = ((const float4*)shx)[v1 * 16 + kc];
            a0 = fmaf(w.x, xa.x, fmaf(w.y, xa.y, fmaf(w.z, xa.z, fmaf(w.w, xa.w, a0))));
            a1 = fmaf(w.x, xb.x, fmaf(w.y, xb.y, fmaf(w.z, xb.z, fmaf(w.w, xb.w, a1))));
        }
        float b = in_b[r];
        res[v0 * CC + r] = sflag[v0] ? (a0 + b) : 0.0f;
        res[v1 * CC + r] = sflag[v1] ? (a1 + b) : 0.0f;
    }
    __syncthreads();

    if (tid < 128)
        ((float4*)(g_xp + (size_t)vb * CC))[tid] = ((const float4*)res)[tid];
}

// ---------------------------------------------------------------------------
// Kernel 2: fused pipeline, 8 consecutive x-voxels per block, 256 threads.
// Shared memory overlays:
//   [0, 31104)      : phase 1 = slab+dwws; phase >=4.5 = SoA sampling params
//   [31104, 41472)  : offs (phase 3-4.5); outv (phase 5-6)
//   [41472, 44928)  : maskv
//   [44928, 46976)  : x1s (phase 1b-3); res (phase 6)
// ---------------------------------------------------------------------------
__global__ void __launch_bounds__(256, 4) dcnv3_fused_kernel(
    const float* __restrict__ input,
    const float* __restrict__ dw_w,
    const float* __restrict__ dw_b,
    const float* __restrict__ ln_g,
    const float* __restrict__ ln_b,
    const float* __restrict__ off_b,
    const float* __restrict__ mask_b,
    const float* __restrict__ out_w,
    const float* __restrict__ out_b,
    float* __restrict__ out)
{
    __shared__ __align__(16) char smem_raw[46976];
    float* slab   = (float*)smem_raw;              // 5760 floats
    float* dwws   = slab + 5760;                   // 1728 floats
    // SoA sampling params (overlay slab region): 7 arrays of 864
    float* pwz0 = (float*)smem_raw;                // m*(1-fz)
    float* pwz1 = pwz0 + 864;                      // m*fz
    float* pfx  = pwz0 + 2 * 864;
    float* pfy  = pwz0 + 3 * 864;
    float* pxi  = pwz0 + 4 * 864;                  // int bits
    float* pyi  = pwz0 + 5 * 864;
    float* pzi  = pwz0 + 6 * 864;
    float* offs   = (float*)(smem_raw + 31104);    // 2592 floats
    float* outv   = offs;                          // 512 floats (overlays offs)
    float* maskv  = (float*)(smem_raw + 41472);    // 864 floats
    float* x1s    = (float*)(smem_raw + 44928);    // 512 floats
    float* res    = x1s;                           // 512 floats (overlays x1s)

    int tid = threadIdx.x;
    int vb = blockIdx.x * VX;
    int x0 = vb % WW; int t = vb / WW;
    int y = t % HH; t /= HH;
    int z = t % DD; int n = t / DD;

    int lane = tid & 31, warp = tid >> 5;
    int half = lane >> 4, hl = lane & 15;

    // ---- phase 1a: stage dw weights + input slab (3 x 3 x 10 x 64) ----
    for (int e = tid; e < CC * 27 / 4; e += 256)            // 432 float4
        ((float4*)dwws)[e] = ((const float4*)dw_w)[e];
    for (int e = tid; e < 3 * 3 * 10 * 16; e += 256) {      // 1440 float4
        int c4 = e & 15;
        int xx = (e >> 4) % 10;
        int r = e / 160;
        int yy = r % 3, zz = r / 3;
        int gz = z + zz - 1, gy = y + yy - 1, gx = x0 + xx - 1;
        float4 val = make_float4(0.f, 0.f, 0.f, 0.f);
        if (gz >= 0 && gz < DD && gy >= 0 && gy < HH && gx >= 0 && gx < WW)
            val = ((const float4*)(input + ((size_t)((n * DD + gz) * HH + gy) * WW + gx) * CC))[c4];
        ((float4*)slab)[e] = val;
    }
    __syncthreads();

    // ---- phase 1b: depthwise conv, sliding window in x ----
    {
        int c = tid & 63, pair = tid >> 6;     // pair in 0..3
        int v0 = pair * 2;
        float acc0 = dw_b[c], acc1 = acc0;
#pragma unroll
        for (int zz = 0; zz < 3; zz++) {
#pragma unroll
            for (int yy = 0; yy < 3; yy++) {
                const float* srow = slab + ((zz * 3 + yy) * 10 + v0) * CC + c;
                const float* wrow = dwws + c * 27 + zz * 9 + yy * 3;
                float s0 = srow[0];
                float s1 = srow[CC];
                float s2 = srow[2 * CC];
                float s3 = srow[3 * CC];
                float w0 = wrow[0], w1 = wrow[1], w2 = wrow[2];
                acc0 = fmaf(s0, w0, fmaf(s1, w1, fmaf(s2, w2, acc0)));
                acc1 = fmaf(s1, w0, fmaf(s2, w1, fmaf(s3, w2, acc1)));
            }
        }
        x1s[v0 * CC + c] = acc0;
        x1s[(v0 + 1) * CC + c] = acc1;
    }
    __syncthreads();

    // ---- phase 2: LayerNorm + exact GELU (warp = voxel) ----
    {
        int v = warp;
        float a = x1s[v * CC + lane];
        float b = x1s[v * CC + lane + 32];
        float s = a + b, s2 = a * a + b * b;
#pragma unroll
        for (int o = 16; o > 0; o >>= 1) {
            s  += __shfl_xor_sync(0xffffffffu, s,  o);
            s2 += __shfl_xor_sync(0xffffffffu, s2, o);
        }
        float mean = s * (1.0f / CC);
        float var  = s2 * (1.0f / CC) - mean * mean;
        float rstd = rsqrtf(var + 1e-6f);
        a = (a - mean) * rstd * ln_g[lane] + ln_b[lane];
        b = (b - mean) * rstd * ln_g[lane + 32] + ln_b[lane + 32];
        a = 0.5f * a * (1.0f + erff(a * 0.70710678118654752f));
        b = 0.5f * b * (1.0f + erff(b * 0.70710678118654752f));
        x1s[v * CC + lane] = a;
        x1s[v * CC + lane + 32] = b;
    }
    __syncthreads();

    // ---- phase 3: heads GEMM, shuffle-free. Thread owns rows tid, tid+256.
    // Rows 0..323 = offset head, 324..431 = mask head, 432..511 = zero pad.
    {
        int r0 = tid, r1 = tid + 256;
        float a0[VX], a1[VX];
#pragma unroll
        for (int v = 0; v < VX; v++) { a0[v] = 0.f; a1[v] = 0.f; }
#pragma unroll 4
        for (int kc = 0; kc < 16; kc++) {
            float4 w0 = g_wT[kc * 512 + r0];
            float4 w1 = g_wT[kc * 512 + r1];
#pragma unroll
            for (int v = 0; v < VX; v++) {
                float4 xv = ((const float4*)x1s)[v * 16 + kc];
                a0[v] = fmaf(w0.x, xv.x, fmaf(w0.y, xv.y, fmaf(w0.z, xv.z, fmaf(w0.w, xv.w, a0[v]))));
                a1[v] = fmaf(w1.x, xv.x, fmaf(w1.y, xv.y, fmaf(w1.z, xv.z, fmaf(w1.w, xv.w, a1[v]))));
            }
        }
        // r0 in [0,256) -> always offset rows
        float b0 = off_b[r0];
#pragma unroll
        for (int v = 0; v < VX; v++) offs[v * 324 + r0] = a0[v] + b0;
        if (r1 < 324) {
            float b1 = off_b[r1];
#pragma unroll
            for (int v = 0; v < VX; v++) offs[v * 324 + r1] = a1[v] + b1;
        } else if (r1 < 432) {
            float b1 = mask_b[r1 - 324];
#pragma unroll
            for (int v = 0; v < VX; v++) maskv[v * 108 + (r1 - 324)] = a1[v] + b1;
        }
    }
    __syncthreads();

    // ---- phase 4: softmax over P per (voxel, group), warp per 4 rows ----
    {
#pragma unroll
        for (int rr = 0; rr < 4; rr++) {
            int row = warp * 4 + rr;
            float val = (lane < PP) ? maskv[row * PP + lane] : -1e30f;
            float mx = val;
#pragma unroll
            for (int o = 16; o > 0; o >>= 1)
                mx = fmaxf(mx, __shfl_xor_sync(0xffffffffu, mx, o));
            float e = (lane < PP) ? __expf(val - mx) : 0.0f;
            float s = e;
#pragma unroll
            for (int o = 16; o > 0; o >>= 1)
                s += __shfl_xor_sync(0xffffffffu, s, o);
            if (lane < PP) maskv[row * PP + lane] = e / s;
        }
    }
    __syncthreads();

    // ---- phase 4.5: precompute SoA sampling params (mask folded into wz) ----
    for (int e = tid; e < VX * GG * PP; e += 256) {
        int sgi = e / 27, p = e % 27;
        int v = sgi >> 2, g = sgi & 3;
        int i0 = p / 9, i1 = (p / 3) % 3, i2 = p % 3;       // (kw, kh, kd)
        const float* ofv = offs + v * 324 + (g * 27 + p) * 3;
        float px = (float)(x0 + v + i0) + ofv[0];
        float py = (float)(y + i1) + ofv[1];
        float pz = (float)(z + i2) + ofv[2];
        float fx0 = floorf(px), fy0 = floorf(py), fz0 = floorf(pz);
        float fz = pz - fz0;
        float m  = maskv[v * 108 + g * 27 + p];
        pwz0[e] = m * (1.0f - fz);
        pwz1[e] = m * fz;
        pfx[e] = px - fx0;
        pfy[e] = py - fy0;
        pxi[e] = __int_as_float((int)fx0);
        pyi[e] = __int_as_float((int)fy0);
        pzi[e] = __int_as_float((int)fz0);
    }
    __syncthreads();

    // ---- phase 5: deformable trilinear sampling ----
    // warp handles 4 (voxel,group) pairs; lane: q = 4-channel chunk,
    // p8 = point slot (8 slots over 27 points). 32-bit addressing.
    {
        int q = lane & 3, p8 = lane >> 2;
        const float* xpn = g_xp + (size_t)n * (DINP * HINP * WINP * CC);
        for (int sgi = warp; sgi < VX * GG; sgi += 8) {
            int v = sgi >> 2, g = sgi & 3;
            const float* xpg = xpn + g * GCH + q * 4;
            float4 acc = make_float4(0.f, 0.f, 0.f, 0.f);
            for (int p = p8; p < PP; p += 8) {
                int idx = sgi * 27 + p;
                float wz0 = pwz0[idx], wz1 = pwz1[idx];   // mask pre-folded
                float fx = pfx[idx], fy = pfy[idx];
                int xi0 = __float_as_int(pxi[idx]);
                int yi0 = __float_as_int(pyi[idx]);
                int zi0 = __float_as_int(pzi[idx]);
                bool bx0 = (unsigned)xi0 < WINP, bx1 = (unsigned)(xi0 + 1) < WINP;
                bool by0 = (unsigned)yi0 < HINP, by1 = (unsigned)(yi0 + 1) < HINP;
                bool bz0 = (unsigned)zi0 < DINP, bz1 = (unsigned)(zi0 + 1) < DINP;
                float gx1 = fx, gx0 = 1.0f - fx;
                float wy0 = 1.0f - fy, wy1 = fy;
                int base = ((zi0 * HINP + yi0) * WINP + xi0) * CC;
                const float* bp = xpg + base;
#pragma unroll
                for (int dz = 0; dz < 2; dz++) {
                    bool bz = dz ? bz1 : bz0;
                    float wz = dz ? wz1 : wz0;
#pragma unroll
                    for (int dy = 0; dy < 2; dy++) {
                        float wzy = wz * (dy ? wy1 : wy0);
                        bool bzy = bz && (dy ? by1 : by0);
#pragma unroll
                        for (int dx = 0; dx < 2; dx++) {
                            if (bzy && (dx ? bx1 : bx0)) {
                                float4 val = *(const float4*)(bp +
                                    (dz * (HINP * WINP) + dy * WINP + dx) * CC);
                                float wt = wzy * (dx ? gx1 : gx0);
                                acc.x = fmaf(wt, val.x, acc.x);
                                acc.y = fmaf(wt, val.y, acc.y);
                                acc.z = fmaf(wt, val.z, acc.z);
                                acc.w = fmaf(wt, val.w, acc.w);
                            }
                        }
                    }
                }
            }
#pragma unroll
            for (int o = 16; o >= 4; o >>= 1) {
                acc.x += __shfl_xor_sync(0xffffffffu, acc.x, o);
                acc.y += __shfl_xor_sync(0xffffffffu, acc.y, o);
                acc.z += __shfl_xor_sync(0xffffffffu, acc.z, o);
                acc.w += __shfl_xor_sync(0xffffffffu, acc.w, o);
            }
            if (p8 == 0)
                ((float4*)(outv + v * CC + g * GCH))[q] = acc;
        }
    }
    __syncthreads();

    // ---- phase 6: output projection (64 rows, 8 voxels) ----
    {
        int hl2 = hl;
        float4 ov[VX];
#pragma unroll
        for (int v = 0; v < VX; v++) ov[v] = ((const float4*)(outv + v * CC))[hl2];
#pragma unroll
        for (int i = 0; i < 4; i++) {
            int r = i * 16 + warp * 2 + half;
            float4 w = ((const float4*)(out_w + (size_t)r * CC))[hl2];
            float p[VX];
#pragma unroll
            for (int v = 0; v < VX; v++)
                p[v] = fmaf(w.x, ov[v].x, fmaf(w.y, ov[v].y, fmaf(w.z, ov[v].z, w.w * ov[v].w)));
            // multi-voxel half-warp reduce (15 shfl for 8 dots)
#pragma unroll
            for (int v = 0; v < 8; v++) p[v] += __shfl_xor_sync(0xffffffffu, p[v], 8);
            float qq[4];
            bool b4 = (hl2 & 4) != 0;
#pragma unroll
            for (int j = 0; j < 4; j++) {
                float send = b4 ? p[j] : p[j + 4];
                float recv = __shfl_xor_sync(0xffffffffu, send, 4);
                qq[j] = (b4 ? p[j + 4] : p[j]) + recv;
            }
            float ss[2];
            bool b2 = (hl2 & 2) != 0;
#pragma unroll
            for (int j = 0; j < 2; j++) {
                float send = b2 ? qq[j] : qq[j + 2];
                float recv = __shfl_xor_sync(0xffffffffu, send, 2);
                ss[j] = (b2 ? qq[j + 2] : qq[j]) + recv;
            }
            bool b1 = (hl2 & 1) != 0;
            float send = b1 ? ss[0] : ss[1];
            float recv = __shfl_xor_sync(0xffffffffu, send, 1);
            float tot = (b1 ? ss[1] : ss[0]) + recv;
            if (hl2 < 8)
                res[hl2 * CC + r] = tot + out_b[r];
        }
    }
    __syncthreads();

    if (tid < 128)
        ((float4*)(out + (size_t)vb * CC))[tid] = ((const float4*)res)[tid];
}

extern "C" void kernel_launch(void* const* d_in, const int* in_sizes, int n_in,
                              void* d_out, int out_size)
{
    const float* input  = (const float*)d_in[0];
    const float* dw_w   = (const float*)d_in[1];
    const float* dw_b   = (const float*)d_in[2];
    const float* ln_g   = (const float*)d_in[3];
    const float* ln_b   = (const float*)d_in[4];
    const float* off_w  = (const float*)d_in[5];
    const float* off_b  = (const float*)d_in[6];
    const float* mask_w = (const float*)d_in[7];
    const float* mask_b = (const float*)d_in[8];
    const float* in_b   = (const float*)d_in[10];
    const float* out_w  = (const float*)d_in[11];
    const float* out_b  = (const float*)d_in[12];
    const float* in_w   = (const float*)d_in[9];
    float* out = (float*)d_out;

    int proj_blocks  = NB * DINP * HINP * WINP / VX;   // 5202
    int fused_blocks = NB * DD * HH * WW / VX;         // 4096

    transpose_weights_kernel<<<36, 256>>>(off_w, mask_w, in_w);
    proj_pad_kernel<<<proj_blocks, 256>>>(input, in_b);
    dcnv3_fused_kernel<<<fused_blocks, 256>>>(
        input, dw_w, dw_b, ln_g, ln_b,
        off_b, mask_b, out_w, out_b, out);
}

// round 7
// speedup vs baseline: 18.9496x; 1.1496x over previous
#include <cuda_runtime.h>
#include <cuda_fp16.h>
#include <math.h>

#define NB 2
#define DD 16
#define HH 32
#define WW 32
#define CC 64
#define GG 4
#define GCH 16
#define PP 27
#define DINP 18
#define HINP 34
#define WINP 34
#define VX 8          // voxels per block

// padded value buffer, fp16, group-major: [n][g][z][y][x][16ch], ~5.3 MB
__device__ __half g_xph[(size_t)NB * GG * DINP * HINP * WINP * GCH];
// k-major transposed head weights: [kc][r], r padded 432->512 with zeros
__device__ float4 g_wT[16 * 512];
// k-major transposed input-projection weights: [kc][r], r in [0,64)
__device__ float4 g_inT[16 * 64];

// ---------------------------------------------------------------------------
// Setup: transpose weights into k-major float4 layouts.
// ---------------------------------------------------------------------------
__global__ void transpose_weights_kernel(
    const float* __restrict__ off_w,
    const float* __restrict__ mask_w,
    const float* __restrict__ in_w)
{
    int i = blockIdx.x * blockDim.x + threadIdx.x;
    if (i < 16 * 512) {
        int kc = i >> 9, r = i & 511;
        float4 v = make_float4(0.f, 0.f, 0.f, 0.f);
        if (r < 324) {
            const float* s = off_w + (size_t)r * CC + kc * 4;
            v = make_float4(s[0], s[1], s[2], s[3]);
        } else if (r < 432) {
            const float* s = mask_w + (size_t)(r - 324) * CC + kc * 4;
            v = make_float4(s[0], s[1], s[2], s[3]);
        }
        g_wT[i] = v;
    } else {
        int j = i - 16 * 512;
        if (j < 16 * 64) {
            int kc = j >> 6, r = j & 63;
            const float* s = in_w + (size_t)r * CC + kc * 4;
            g_inT[j] = make_float4(s[0], s[1], s[2], s[3]);
        }
    }
}

// ---------------------------------------------------------------------------
// Kernel 1: value projection -> fp16 group-major padded buffer.
// 8 padded voxels/block; coalesced k-major weights; shuffle-free GEMV.
// ---------------------------------------------------------------------------
__global__ void __launch_bounds__(256, 4) proj_pad_kernel(
    const float* __restrict__ input,
    const float* __restrict__ in_b)
{
    int tid = threadIdx.x;
    int vb = blockIdx.x * VX;

    __shared__ __align__(16) float shx[VX * CC];
    __shared__ __align__(16) float res[VX * CC];
    __shared__ int sflag[VX];

    for (int o = tid; o < VX * CC; o += 256) {
        int v = o >> 6, c = o & 63;
        int pv = vb + v;
        int xx = pv % WINP; int t = pv / WINP;
        int yy = t % HINP; t /= HINP;
        int zz = t % DINP; int n = t / DINP;
        int xi = xx - 1, yi = yy - 1, zi = zz - 1;
        bool in = (xi >= 0 && xi < WW && yi >= 0 && yi < HH && zi >= 0 && zi < DD);
        if (c == 0) sflag[v] = in ? 1 : 0;
        shx[o] = in ? input[((size_t)((n * DD + zi) * HH + yi) * WW + xi) * CC + c] : 0.0f;
    }
    __syncthreads();

    {
        int r = tid & 63, vh = tid >> 6;       // vh: 0..3 -> voxels 2vh, 2vh+1
        int v0 = vh * 2, v1 = v0 + 1;
        float a0 = 0.f, a1 = 0.f;
#pragma unroll
        for (int kc = 0; kc < 16; kc++) {
            float4 w  = g_inT[kc * 64 + r];
            float4 xa = ((const float4*)shx)[v0 * 16 + kc];
            float4 xb = ((const float4*)shx)[v1 * 16 + kc];
            a0 = fmaf(w.x, xa.x, fmaf(w.y, xa.y, fmaf(w.z, xa.z, fmaf(w.w, xa.w, a0))));
            a1 = fmaf(w.x, xb.x, fmaf(w.y, xb.y, fmaf(w.z, xb.z, fmaf(w.w, xb.w, a1))));
        }
        float b = in_b[r];
        res[v0 * CC + r] = sflag[v0] ? (a0 + b) : 0.0f;
        res[v1 * CC + r] = sflag[v1] ? (a1 + b) : 0.0f;
    }
    __syncthreads();

    // write fp16 group-major: chunk = 4 channels
    for (int o = tid; o < VX * CC / 4; o += 256) {   // 128 chunks
        int v = o >> 4, g = (o >> 2) & 3, c4 = o & 3;
        int pv = vb + v;
        int xx = pv % WINP; int t = pv / WINP;
        int yy = t % HINP; t /= HINP;
        int zz = t % DINP; int n = t / DINP;
        const float* s = res + v * CC + g * GCH + c4 * 4;
        __half2 h01 = __floats2half2_rn(s[0], s[1]);
        __half2 h23 = __floats2half2_rn(s[2], s[3]);
        uint2 u;
        ((__half2*)&u)[0] = h01;
        ((__half2*)&u)[1] = h23;
        size_t base = ((size_t)(((n * GG + g) * DINP + zz) * HINP + yy) * WINP + xx) * GCH;
        *(uint2*)(g_xph + base + c4 * 4) = u;
    }
}

// ---------------------------------------------------------------------------
// Kernel 2: fused pipeline, 8 consecutive x-voxels per block, 256 threads.
// Shared memory overlays:
//   [0, 31104)      : phase 1 = slab+dwws; phase >=4.5 = SoA sampling params
//   [31104, 41472)  : offs (phase 3-4.5); outv (phase 5-6)
//   [41472, 44928)  : maskv
//   [44928, 46976)  : x1s (phase 1b-3); res (phase 6)
// ---------------------------------------------------------------------------
__global__ void __launch_bounds__(256, 4) dcnv3_fused_kernel(
    const float* __restrict__ input,
    const float* __restrict__ dw_w,
    const float* __restrict__ dw_b,
    const float* __restrict__ ln_g,
    const float* __restrict__ ln_b,
    const float* __restrict__ off_b,
    const float* __restrict__ mask_b,
    const float* __restrict__ out_w,
    const float* __restrict__ out_b,
    float* __restrict__ out)
{
    __shared__ __align__(16) char smem_raw[46976];
    float* slab   = (float*)smem_raw;              // 5760 floats
    float* dwws   = slab + 5760;                   // 1728 floats
    // SoA sampling params (overlay slab region): 7 arrays of 864
    float* pwz0 = (float*)smem_raw;                // m*(1-fz)
    float* pwz1 = pwz0 + 864;                      // m*fz
    float* pfx  = pwz0 + 2 * 864;
    float* pfy  = pwz0 + 3 * 864;
    float* pxi  = pwz0 + 4 * 864;                  // int bits
    float* pyi  = pwz0 + 5 * 864;
    float* pzi  = pwz0 + 6 * 864;
    float* offs   = (float*)(smem_raw + 31104);    // 2592 floats
    float* outv   = offs;                          // 512 floats (overlays offs)
    float* maskv  = (float*)(smem_raw + 41472);    // 864 floats
    float* x1s    = (float*)(smem_raw + 44928);    // 512 floats
    float* res    = x1s;                           // 512 floats (overlays x1s)

    int tid = threadIdx.x;
    int vb = blockIdx.x * VX;
    int x0 = vb % WW; int t = vb / WW;
    int y = t % HH; t /= HH;
    int z = t % DD; int n = t / DD;

    int lane = tid & 31, warp = tid >> 5;
    int half = lane >> 4, hl = lane & 15;

    // ---- phase 1a: stage dw weights + input slab (3 x 3 x 10 x 64) ----
    for (int e = tid; e < CC * 27 / 4; e += 256)            // 432 float4
        ((float4*)dwws)[e] = ((const float4*)dw_w)[e];
    for (int e = tid; e < 3 * 3 * 10 * 16; e += 256) {      // 1440 float4
        int c4 = e & 15;
        int xx = (e >> 4) % 10;
        int r = e / 160;
        int yy = r % 3, zz = r / 3;
        int gz = z + zz - 1, gy = y + yy - 1, gx = x0 + xx - 1;
        float4 val = make_float4(0.f, 0.f, 0.f, 0.f);
        if (gz >= 0 && gz < DD && gy >= 0 && gy < HH && gx >= 0 && gx < WW)
            val = ((const float4*)(input + ((size_t)((n * DD + gz) * HH + gy) * WW + gx) * CC))[c4];
        ((float4*)slab)[e] = val;
    }
    __syncthreads();

    // ---- phase 1b: depthwise conv, sliding window in x ----
    {
        int c = tid & 63, pair = tid >> 6;     // pair in 0..3
        int v0 = pair * 2;
        float acc0 = dw_b[c], acc1 = acc0;
#pragma unroll
        for (int zz = 0; zz < 3; zz++) {
#pragma unroll
            for (int yy = 0; yy < 3; yy++) {
                const float* srow = slab + ((zz * 3 + yy) * 10 + v0) * CC + c;
                const float* wrow = dwws + c * 27 + zz * 9 + yy * 3;
                float s0 = srow[0];
                float s1 = srow[CC];
                float s2 = srow[2 * CC];
                float s3 = srow[3 * CC];
                float w0 = wrow[0], w1 = wrow[1], w2 = wrow[2];
                acc0 = fmaf(s0, w0, fmaf(s1, w1, fmaf(s2, w2, acc0)));
                acc1 = fmaf(s1, w0, fmaf(s2, w1, fmaf(s3, w2, acc1)));
            }
        }
        x1s[v0 * CC + c] = acc0;
        x1s[(v0 + 1) * CC + c] = acc1;
    }
    __syncthreads();

    // ---- phase 2: LayerNorm + exact GELU (warp = voxel) ----
    {
        int v = warp;
        float a = x1s[v * CC + lane];
        float b = x1s[v * CC + lane + 32];
        float s = a + b, s2 = a * a + b * b;
#pragma unroll
        for (int o = 16; o > 0; o >>= 1) {
            s  += __shfl_xor_sync(0xffffffffu, s,  o);
            s2 += __shfl_xor_sync(0xffffffffu, s2, o);
        }
        float mean = s * (1.0f / CC);
        float var  = s2 * (1.0f / CC) - mean * mean;
        float rstd = rsqrtf(var + 1e-6f);
        a = (a - mean) * rstd * ln_g[lane] + ln_b[lane];
        b = (b - mean) * rstd * ln_g[lane + 32] + ln_b[lane + 32];
        a = 0.5f * a * (1.0f + erff(a * 0.70710678118654752f));
        b = 0.5f * b * (1.0f + erff(b * 0.70710678118654752f));
        x1s[v * CC + lane] = a;
        x1s[v * CC + lane + 32] = b;
    }
    __syncthreads();

    // ---- phase 3: heads GEMM, shuffle-free. Thread owns rows tid, tid+256 ----
    {
        int r0 = tid, r1 = tid + 256;
        float a0[VX], a1[VX];
#pragma unroll
        for (int v = 0; v < VX; v++) { a0[v] = 0.f; a1[v] = 0.f; }
#pragma unroll 4
        for (int kc = 0; kc < 16; kc++) {
            float4 w0 = g_wT[kc * 512 + r0];
            float4 w1 = g_wT[kc * 512 + r1];
#pragma unroll
            for (int v = 0; v < VX; v++) {
                float4 xv = ((const float4*)x1s)[v * 16 + kc];
                a0[v] = fmaf(w0.x, xv.x, fmaf(w0.y, xv.y, fmaf(w0.z, xv.z, fmaf(w0.w, xv.w, a0[v]))));
                a1[v] = fmaf(w1.x, xv.x, fmaf(w1.y, xv.y, fmaf(w1.z, xv.z, fmaf(w1.w, xv.w, a1[v]))));
            }
        }
        float b0 = off_b[r0];
#pragma unroll
        for (int v = 0; v < VX; v++) offs[v * 324 + r0] = a0[v] + b0;
        if (r1 < 324) {
            float b1 = off_b[r1];
#pragma unroll
            for (int v = 0; v < VX; v++) offs[v * 324 + r1] = a1[v] + b1;
        } else if (r1 < 432) {
            float b1 = mask_b[r1 - 324];
#pragma unroll
            for (int v = 0; v < VX; v++) maskv[v * 108 + (r1 - 324)] = a1[v] + b1;
        }
    }
    __syncthreads();

    // ---- phase 4: softmax over P per (voxel, group), warp per 4 rows ----
    {
#pragma unroll
        for (int rr = 0; rr < 4; rr++) {
            int row = warp * 4 + rr;
            float val = (lane < PP) ? maskv[row * PP + lane] : -1e30f;
            float mx = val;
#pragma unroll
            for (int o = 16; o > 0; o >>= 1)
                mx = fmaxf(mx, __shfl_xor_sync(0xffffffffu, mx, o));
            float e = (lane < PP) ? __expf(val - mx) : 0.0f;
            float s = e;
#pragma unroll
            for (int o = 16; o > 0; o >>= 1)
                s += __shfl_xor_sync(0xffffffffu, s, o);
            if (lane < PP) maskv[row * PP + lane] = e / s;
        }
    }
    __syncthreads();

    // ---- phase 4.5: precompute SoA sampling params (mask folded into wz) ----
    for (int e = tid; e < VX * GG * PP; e += 256) {
        int sgi = e / 27, p = e % 27;
        int v = sgi >> 2, g = sgi & 3;
        int i0 = p / 9, i1 = (p / 3) % 3, i2 = p % 3;       // (kw, kh, kd)
        const float* ofv = offs + v * 324 + (g * 27 + p) * 3;
        float px = (float)(x0 + v + i0) + ofv[0];
        float py = (float)(y + i1) + ofv[1];
        float pz = (float)(z + i2) + ofv[2];
        float fx0 = floorf(px), fy0 = floorf(py), fz0 = floorf(pz);
        float fz = pz - fz0;
        float m  = maskv[v * 108 + g * 27 + p];
        pwz0[e] = m * (1.0f - fz);
        pwz1[e] = m * fz;
        pfx[e] = px - fx0;
        pfy[e] = py - fy0;
        pxi[e] = __int_as_float((int)fx0);
        pyi[e] = __int_as_float((int)fy0);
        pzi[e] = __int_as_float((int)fz0);
    }
    __syncthreads();

    // ---- phase 5: deformable trilinear sampling from fp16 group-major ----
    // lane = (p8, q2, dx): dx = lane&1, q2 = (lane>>1)&1, p8 = lane>>2.
    // One LDG.128 per (dz,dy) fetches the full dx-pair (64 halves / 4 lanes)
    // for 8 points. Accumulate 8 channels (q2 half) in fp32.
    {
        int dx = lane & 1, q2 = (lane >> 1) & 1, p8 = lane >> 2;
        for (int sgi = warp; sgi < VX * GG; sgi += 8) {
            int v = sgi >> 2, g = sgi & 3;
            const __half* xg = g_xph +
                (size_t)(n * GG + g) * (DINP * HINP * WINP) * GCH;
            float4 aA = make_float4(0.f, 0.f, 0.f, 0.f);
            float4 aB = make_float4(0.f, 0.f, 0.f, 0.f);
            for (int p = p8; p < PP; p += 8) {
                int idx = sgi * 27 + p;
                float wz0 = pwz0[idx], wz1 = pwz1[idx];   // mask pre-folded
                float fx = pfx[idx], fy = pfy[idx];
                int xi0 = __float_as_int(pxi[idx]);
                int yi0 = __float_as_int(pyi[idx]);
                int zi0 = __float_as_int(pzi[idx]);
                bool bxl = (unsigned)(xi0 + dx) < WINP;    // this lane's x corner
                bool by0 = (unsigned)yi0 < HINP, by1 = (unsigned)(yi0 + 1) < HINP;
                bool bz0 = (unsigned)zi0 < DINP, bz1 = (unsigned)(zi0 + 1) < DINP;
                float wxl = dx ? fx : 1.0f - fx;
                float wy0 = 1.0f - fy, wy1 = fy;
                int base = ((zi0 * HINP + yi0) * WINP + xi0) * GCH
                         + dx * GCH + q2 * 8;
                const __half* bp = xg + base;
#pragma unroll
                for (int dz = 0; dz < 2; dz++) {
                    bool bz = dz ? bz1 : bz0;
                    float wz = dz ? wz1 : wz0;
#pragma unroll
                    for (int dy = 0; dy < 2; dy++) {
                        bool ok = bxl && bz && (dy ? by1 : by0);
                        if (ok) {
                            float wt = wz * (dy ? wy1 : wy0) * wxl;
                            uint4 raw = *(const uint4*)(bp +
                                (dz * (HINP * WINP) + dy * WINP) * GCH);
                            const __half2* hp = (const __half2*)&raw;
                            float2 f0 = __half22float2(hp[0]);
                            float2 f1 = __half22float2(hp[1]);
                            float2 f2 = __half22float2(hp[2]);
                            float2 f3 = __half22float2(hp[3]);
                            aA.x = fmaf(wt, f0.x, aA.x);
                            aA.y = fmaf(wt, f0.y, aA.y);
                            aA.z = fmaf(wt, f1.x, aA.z);
                            aA.w = fmaf(wt, f1.y, aA.w);
                            aB.x = fmaf(wt, f2.x, aB.x);
                            aB.y = fmaf(wt, f2.y, aB.y);
                            aB.z = fmaf(wt, f3.x, aB.z);
                            aB.w = fmaf(wt, f3.y, aB.w);
                        }
                    }
                }
            }
            // reduce over dx (xor 1) then p8 (xor 4, 8, 16)
#pragma unroll
            for (int o = 0; o < 4; o++) {
                int st = (o == 0) ? 1 : (2 << o);          // 1, 4, 8, 16
                aA.x += __shfl_xor_sync(0xffffffffu, aA.x, st);
                aA.y += __shfl_xor_sync(0xffffffffu, aA.y, st);
                aA.z += __shfl_xor_sync(0xffffffffu, aA.z, st);
                aA.w += __shfl_xor_sync(0xffffffffu, aA.w, st);
                aB.x += __shfl_xor_sync(0xffffffffu, aB.x, st);
                aB.y += __shfl_xor_sync(0xffffffffu, aB.y, st);
                aB.z += __shfl_xor_sync(0xffffffffu, aB.z, st);
                aB.w += __shfl_xor_sync(0xffffffffu, aB.w, st);
            }
            if (dx == 0 && p8 == 0) {
                float* dst = outv + v * CC + g * GCH + q2 * 8;
                ((float4*)dst)[0] = aA;
                ((float4*)dst)[1] = aB;
            }
        }
    }
    __syncthreads();

    // ---- phase 6: output projection (64 rows, 8 voxels) ----
    {
        float4 ov[VX];
#pragma unroll
        for (int v = 0; v < VX; v++) ov[v] = ((const float4*)(outv + v * CC))[hl];
#pragma unroll
        for (int i = 0; i < 4; i++) {
            int r = i * 16 + warp * 2 + half;
            float4 w = ((const float4*)(out_w + (size_t)r * CC))[hl];
            float p[VX];
#pragma unroll
            for (int v = 0; v < VX; v++)
                p[v] = fmaf(w.x, ov[v].x, fmaf(w.y, ov[v].y, fmaf(w.z, ov[v].z, w.w * ov[v].w)));
            // multi-voxel half-warp reduce (15 shfl for 8 dots)
#pragma unroll
            for (int v = 0; v < 8; v++) p[v] += __shfl_xor_sync(0xffffffffu, p[v], 8);
            float qq[4];
            bool b4 = (hl & 4) != 0;
#pragma unroll
            for (int j = 0; j < 4; j++) {
                float send = b4 ? p[j] : p[j + 4];
                float recv = __shfl_xor_sync(0xffffffffu, send, 4);
                qq[j] = (b4 ? p[j + 4] : p[j]) + recv;
            }
            float ss[2];
            bool b2 = (hl & 2) != 0;
#pragma unroll
            for (int j = 0; j < 2; j++) {
                float send = b2 ? qq[j] : qq[j + 2];
                float recv = __shfl_xor_sync(0xffffffffu, send, 2);
                ss[j] = (b2 ? qq[j + 2] : qq[j]) + recv;
            }
            bool b1 = (hl & 1) != 0;
            float send = b1 ? ss[0] : ss[1];
            float recv = __shfl_xor_sync(0xffffffffu, send, 1);
            float tot = (b1 ? ss[1] : ss[0]) + recv;
            if (hl < 8)
                res[hl * CC + r] = tot + out_b[r];
        }
    }
    __syncthreads();

    if (tid < 128)
        ((float4*)(out + (size_t)vb * CC))[tid] = ((const float4*)res)[tid];
}

extern "C" void kernel_launch(void* const* d_in, const int* in_sizes, int n_in,
                              void* d_out, int out_size)
{
    const float* input  = (const float*)d_in[0];
    const float* dw_w   = (const float*)d_in[1];
    const float* dw_b   = (const float*)d_in[2];
    const float* ln_g   = (const float*)d_in[3];
    const float* ln_b   = (const float*)d_in[4];
    const float* off_w  = (const float*)d_in[5];
    const float* off_b  = (const float*)d_in[6];
    const float* mask_w = (const float*)d_in[7];
    const float* mask_b = (const float*)d_in[8];
    const float* in_w   = (const float*)d_in[9];
    const float* in_b   = (const float*)d_in[10];
    const float* out_w  = (const float*)d_in[11];
    const float* out_b  = (const float*)d_in[12];
    float* out = (float*)d_out;

    int proj_blocks  = NB * DINP * HINP * WINP / VX;   // 5202
    int fused_blocks = NB * DD * HH * WW / VX;         // 4096

    transpose_weights_kernel<<<36, 256>>>(off_w, mask_w, in_w);
    proj_pad_kernel<<<proj_blocks, 256>>>(input, in_b);
    dcnv3_fused_kernel<<<fused_blocks, 256>>>(
        input, dw_w, dw_b, ln_g, ln_b,
        off_b, mask_b, out_w, out_b, out);
}

// round 8
// speedup vs baseline: 19.1361x; 1.0098x over previous
#include <cuda_runtime.h>
#include <cuda_fp16.h>
#include <math.h>

#define NB 2
#define DD 16
#define HH 32
#define WW 32
#define CC 64
#define GG 4
#define GCH 16
#define PP 27
#define DINP 18
#define HINP 34
#define WINP 34
#define VX 8          // voxels per block

typedef unsigned long long u64;

// ---- packed f32x2 helpers (sm_103a dual-FMA) ----
__device__ __forceinline__ u64 pk2(float lo, float hi) {
    u64 r; asm("mov.b64 %0, {%1, %2};" : "=l"(r) : "f"(lo), "f"(hi)); return r;
}
__device__ __forceinline__ float2 upk2(u64 v) {
    float2 r; asm("mov.b64 {%0, %1}, %2;" : "=f"(r.x), "=f"(r.y) : "l"(v)); return r;
}
__device__ __forceinline__ void fma2(u64& acc, u64 a, u64 b) {
    asm("fma.rn.f32x2 %0, %1, %2, %0;" : "+l"(acc) : "l"(a), "l"(b));
}

// padded value buffer, fp16, group-major: [n][g][z][y][x][16ch], ~5.3 MB
__device__ __half g_xph[(size_t)NB * GG * DINP * HINP * WINP * GCH];
// k-major transposed head weights: [kc][r], r padded 432->512 with zeros
__device__ float4 g_wT[16 * 512];
// k-major transposed input-projection weights: [kc][r], r in [0,64)
__device__ float4 g_inT[16 * 64];

// ---------------------------------------------------------------------------
// Setup: transpose weights into k-major float4 layouts.
// ---------------------------------------------------------------------------
__global__ void transpose_weights_kernel(
    const float* __restrict__ off_w,
    const float* __restrict__ mask_w,
    const float* __restrict__ in_w)
{
    int i = blockIdx.x * blockDim.x + threadIdx.x;
    if (i < 16 * 512) {
        int kc = i >> 9, r = i & 511;
        float4 v = make_float4(0.f, 0.f, 0.f, 0.f);
        if (r < 324) {
            const float* s = off_w + (size_t)r * CC + kc * 4;
            v = make_float4(s[0], s[1], s[2], s[3]);
        } else if (r < 432) {
            const float* s = mask_w + (size_t)(r - 324) * CC + kc * 4;
            v = make_float4(s[0], s[1], s[2], s[3]);
        }
        g_wT[i] = v;
    } else {
        int j = i - 16 * 512;
        if (j < 16 * 64) {
            int kc = j >> 6, r = j & 63;
            const float* s = in_w + (size_t)r * CC + kc * 4;
            g_inT[j] = make_float4(s[0], s[1], s[2], s[3]);
        }
    }
}

// ---------------------------------------------------------------------------
// Kernel 1: value projection -> fp16 group-major padded buffer.
// 8 padded voxels/block; k-major weights; packed f32x2 dot products.
// ---------------------------------------------------------------------------
__global__ void __launch_bounds__(256, 4) proj_pad_kernel(
    const float* __restrict__ input,
    const float* __restrict__ in_b)
{
    int tid = threadIdx.x;
    int vb = blockIdx.x * VX;

    __shared__ __align__(16) float shx[VX * CC];
    __shared__ __align__(16) float res[VX * CC];
    __shared__ int sflag[VX];

    for (int o = tid; o < VX * CC; o += 256) {
        int v = o >> 6, c = o & 63;
        int pv = vb + v;
        int xx = pv % WINP; int t = pv / WINP;
        int yy = t % HINP; t /= HINP;
        int zz = t % DINP; int n = t / DINP;
        int xi = xx - 1, yi = yy - 1, zi = zz - 1;
        bool in = (xi >= 0 && xi < WW && yi >= 0 && yi < HH && zi >= 0 && zi < DD);
        if (c == 0) sflag[v] = in ? 1 : 0;
        shx[o] = in ? input[((size_t)((n * DD + zi) * HH + yi) * WW + xi) * CC + c] : 0.0f;
    }
    __syncthreads();

    {
        int r = tid & 63, vh = tid >> 6;       // vh: 0..3 -> voxels 2vh, 2vh+1
        int v0 = vh * 2, v1 = v0 + 1;
        u64 a0 = 0ull, a1 = 0ull;
#pragma unroll
        for (int kc = 0; kc < 16; kc++) {
            float4 w  = g_inT[kc * 64 + r];
            float4 xa = ((const float4*)shx)[v0 * 16 + kc];
            float4 xb = ((const float4*)shx)[v1 * 16 + kc];
            u64 wxy = pk2(w.x, w.y), wzw = pk2(w.z, w.w);
            fma2(a0, wxy, pk2(xa.x, xa.y));
            fma2(a0, wzw, pk2(xa.z, xa.w));
            fma2(a1, wxy, pk2(xb.x, xb.y));
            fma2(a1, wzw, pk2(xb.z, xb.w));
        }
        float b = in_b[r];
        float2 t0 = upk2(a0), t1 = upk2(a1);
        res[v0 * CC + r] = sflag[v0] ? (t0.x + t0.y + b) : 0.0f;
        res[v1 * CC + r] = sflag[v1] ? (t1.x + t1.y + b) : 0.0f;
    }
    __syncthreads();

    // write fp16 group-major: chunk = 4 channels
    for (int o = tid; o < VX * CC / 4; o += 256) {   // 128 chunks
        int v = o >> 4, g = (o >> 2) & 3, c4 = o & 3;
        int pv = vb + v;
        int xx = pv % WINP; int t = pv / WINP;
        int yy = t % HINP; t /= HINP;
        int zz = t % DINP; int n = t / DINP;
        const float* s = res + v * CC + g * GCH + c4 * 4;
        __half2 h01 = __floats2half2_rn(s[0], s[1]);
        __half2 h23 = __floats2half2_rn(s[2], s[3]);
        uint2 u;
        ((__half2*)&u)[0] = h01;
        ((__half2*)&u)[1] = h23;
        size_t base = ((size_t)(((n * GG + g) * DINP + zz) * HINP + yy) * WINP + xx) * GCH;
        *(uint2*)(g_xph + base + c4 * 4) = u;
    }
}

// ---------------------------------------------------------------------------
// Kernel 2: fused pipeline, 8 consecutive x-voxels per block, 256 threads.
// Shared memory overlays:
//   [0, 31104)      : phase 1 = slab+dwws; phase >=4.5 = SoA sampling params
//   [31104, 41472)  : offs (phase 3-4.5); outv (phase 5-6)
//   [41472, 44928)  : maskv
//   [44928, 46976)  : x1s (phase 1b-3); res (phase 6)
// ---------------------------------------------------------------------------
__global__ void __launch_bounds__(256, 4) dcnv3_fused_kernel(
    const float* __restrict__ input,
    const float* __restrict__ dw_w,
    const float* __restrict__ dw_b,
    const float* __restrict__ ln_g,
    const float* __restrict__ ln_b,
    const float* __restrict__ off_b,
    const float* __restrict__ mask_b,
    const float* __restrict__ out_w,
    const float* __restrict__ out_b,
    float* __restrict__ out)
{
    __shared__ __align__(16) char smem_raw[46976];
    float* slab   = (float*)smem_raw;              // 5760 floats
    float* dwws   = slab + 5760;                   // 1728 floats
    // SoA sampling params (overlay slab region): 7 arrays of 864
    float* pwz0 = (float*)smem_raw;                // m*(1-fz)
    float* pwz1 = pwz0 + 864;                      // m*fz
    float* pfx  = pwz0 + 2 * 864;
    float* pfy  = pwz0 + 3 * 864;
    float* pxi  = pwz0 + 4 * 864;                  // int bits
    float* pyi  = pwz0 + 5 * 864;
    float* pzi  = pwz0 + 6 * 864;
    float* offs   = (float*)(smem_raw + 31104);    // 2592 floats
    float* outv   = offs;                          // 512 floats (overlays offs)
    float* maskv  = (float*)(smem_raw + 41472);    // 864 floats
    float* x1s    = (float*)(smem_raw + 44928);    // 512 floats
    float* res    = x1s;                           // 512 floats (overlays x1s)

    int tid = threadIdx.x;
    int vb = blockIdx.x * VX;
    int x0 = vb % WW; int t = vb / WW;
    int y = t % HH; t /= HH;
    int z = t % DD; int n = t / DD;

    int lane = tid & 31, warp = tid >> 5;
    int half = lane >> 4, hl = lane & 15;

    // ---- phase 1a: stage dw weights + input slab (3 x 3 x 10 x 64) ----
    for (int e = tid; e < CC * 27 / 4; e += 256)            // 432 float4
        ((float4*)dwws)[e] = ((const float4*)dw_w)[e];
    for (int e = tid; e < 3 * 3 * 10 * 16; e += 256) {      // 1440 float4
        int c4 = e & 15;
        int xx = (e >> 4) % 10;
        int r = e / 160;
        int yy = r % 3, zz = r / 3;
        int gz = z + zz - 1, gy = y + yy - 1, gx = x0 + xx - 1;
        float4 val = make_float4(0.f, 0.f, 0.f, 0.f);
        if (gz >= 0 && gz < DD && gy >= 0 && gy < HH && gx >= 0 && gx < WW)
            val = ((const float4*)(input + ((size_t)((n * DD + gz) * HH + gy) * WW + gx) * CC))[c4];
        ((float4*)slab)[e] = val;
    }
    __syncthreads();

    // ---- phase 1b: depthwise conv, sliding window in x ----
    {
        int c = tid & 63, pair = tid >> 6;     // pair in 0..3
        int v0 = pair * 2;
        float acc0 = dw_b[c], acc1 = acc0;
#pragma unroll
        for (int zz = 0; zz < 3; zz++) {
#pragma unroll
            for (int yy = 0; yy < 3; yy++) {
                const float* srow = slab + ((zz * 3 + yy) * 10 + v0) * CC + c;
                const float* wrow = dwws + c * 27 + zz * 9 + yy * 3;
                float s0 = srow[0];
                float s1 = srow[CC];
                float s2 = srow[2 * CC];
                float s3 = srow[3 * CC];
                float w0 = wrow[0], w1 = wrow[1], w2 = wrow[2];
                acc0 = fmaf(s0, w0, fmaf(s1, w1, fmaf(s2, w2, acc0)));
                acc1 = fmaf(s1, w0, fmaf(s2, w1, fmaf(s3, w2, acc1)));
            }
        }
        x1s[v0 * CC + c] = acc0;
        x1s[(v0 + 1) * CC + c] = acc1;
    }
    __syncthreads();

    // ---- phase 2: LayerNorm + exact GELU (warp = voxel) ----
    {
        int v = warp;
        float a = x1s[v * CC + lane];
        float b = x1s[v * CC + lane + 32];
        float s = a + b, s2 = a * a + b * b;
#pragma unroll
        for (int o = 16; o > 0; o >>= 1) {
            s  += __shfl_xor_sync(0xffffffffu, s,  o);
            s2 += __shfl_xor_sync(0xffffffffu, s2, o);
        }
        float mean = s * (1.0f / CC);
        float var  = s2 * (1.0f / CC) - mean * mean;
        float rstd = rsqrtf(var + 1e-6f);
        a = (a - mean) * rstd * ln_g[lane] + ln_b[lane];
        b = (b - mean) * rstd * ln_g[lane + 32] + ln_b[lane + 32];
        a = 0.5f * a * (1.0f + erff(a * 0.70710678118654752f));
        b = 0.5f * b * (1.0f + erff(b * 0.70710678118654752f));
        x1s[v * CC + lane] = a;
        x1s[v * CC + lane + 32] = b;
    }
    __syncthreads();

    // ---- phase 3: heads GEMM, shuffle-free, packed f32x2 FMAs.
    // Thread owns rows tid, tid+256. Rows 0..323 offset, 324..431 mask.
    {
        int r0 = tid, r1 = tid + 256;
        u64 a0[VX], a1[VX];
#pragma unroll
        for (int v = 0; v < VX; v++) { a0[v] = 0ull; a1[v] = 0ull; }
#pragma unroll 4
        for (int kc = 0; kc < 16; kc++) {
            float4 w0 = g_wT[kc * 512 + r0];
            float4 w1 = g_wT[kc * 512 + r1];
            u64 w0a = pk2(w0.x, w0.y), w0b = pk2(w0.z, w0.w);
            u64 w1a = pk2(w1.x, w1.y), w1b = pk2(w1.z, w1.w);
#pragma unroll
            for (int v = 0; v < VX; v++) {
                float4 xv = ((const float4*)x1s)[v * 16 + kc];
                u64 xa = pk2(xv.x, xv.y), xb = pk2(xv.z, xv.w);
                fma2(a0[v], w0a, xa);
                fma2(a0[v], w0b, xb);
                fma2(a1[v], w1a, xa);
                fma2(a1[v], w1b, xb);
            }
        }
        float b0 = off_b[r0];
#pragma unroll
        for (int v = 0; v < VX; v++) {
            float2 tv = upk2(a0[v]);
            offs[v * 324 + r0] = tv.x + tv.y + b0;
        }
        if (r1 < 324) {
            float b1 = off_b[r1];
#pragma unroll
            for (int v = 0; v < VX; v++) {
                float2 tv = upk2(a1[v]);
                offs[v * 324 + r1] = tv.x + tv.y + b1;
            }
        } else if (r1 < 432) {
            float b1 = mask_b[r1 - 324];
#pragma unroll
            for (int v = 0; v < VX; v++) {
                float2 tv = upk2(a1[v]);
                maskv[v * 108 + (r1 - 324)] = tv.x + tv.y + b1;
            }
        }
    }
    __syncthreads();

    // ---- phase 4: softmax over P per (voxel, group), warp per 4 rows ----
    {
#pragma unroll
        for (int rr = 0; rr < 4; rr++) {
            int row = warp * 4 + rr;
            float val = (lane < PP) ? maskv[row * PP + lane] : -1e30f;
            float mx = val;
#pragma unroll
            for (int o = 16; o > 0; o >>= 1)
                mx = fmaxf(mx, __shfl_xor_sync(0xffffffffu, mx, o));
            float e = (lane < PP) ? __expf(val - mx) : 0.0f;
            float s = e;
#pragma unroll
            for (int o = 16; o > 0; o >>= 1)
                s += __shfl_xor_sync(0xffffffffu, s, o);
            if (lane < PP) maskv[row * PP + lane] = e / s;
        }
    }
    __syncthreads();

    // ---- phase 4.5: precompute SoA sampling params (mask folded into wz) ----
    for (int e = tid; e < VX * GG * PP; e += 256) {
        int sgi = e / 27, p = e % 27;
        int v = sgi >> 2, g = sgi & 3;
        int i0 = p / 9, i1 = (p / 3) % 3, i2 = p % 3;       // (kw, kh, kd)
        const float* ofv = offs + v * 324 + (g * 27 + p) * 3;
        float px = (float)(x0 + v + i0) + ofv[0];
        float py = (float)(y + i1) + ofv[1];
        float pz = (float)(z + i2) + ofv[2];
        float fx0 = floorf(px), fy0 = floorf(py), fz0 = floorf(pz);
        float fz = pz - fz0;
        float m  = maskv[v * 108 + g * 27 + p];
        pwz0[e] = m * (1.0f - fz);
        pwz1[e] = m * fz;
        pfx[e] = px - fx0;
        pfy[e] = py - fy0;
        pxi[e] = __int_as_float((int)fx0);
        pyi[e] = __int_as_float((int)fy0);
        pzi[e] = __int_as_float((int)fz0);
    }
    __syncthreads();

    // ---- phase 5: deformable trilinear sampling from fp16 group-major ----
    // lane = (p8, q2, dx): dx = lane&1, q2 = (lane>>1)&1, p8 = lane>>2.
    {
        int dx = lane & 1, q2 = (lane >> 1) & 1, p8 = lane >> 2;
        for (int sgi = warp; sgi < VX * GG; sgi += 8) {
            int v = sgi >> 2, g = sgi & 3;
            const __half* xg = g_xph +
                (size_t)(n * GG + g) * (DINP * HINP * WINP) * GCH;
            float4 aA = make_float4(0.f, 0.f, 0.f, 0.f);
            float4 aB = make_float4(0.f, 0.f, 0.f, 0.f);
            for (int p = p8; p < PP; p += 8) {
                int idx = sgi * 27 + p;
                float wz0 = pwz0[idx], wz1 = pwz1[idx];   // mask pre-folded
                float fx = pfx[idx], fy = pfy[idx];
                int xi0 = __float_as_int(pxi[idx]);
                int yi0 = __float_as_int(pyi[idx]);
                int zi0 = __float_as_int(pzi[idx]);
                bool bxl = (unsigned)(xi0 + dx) < WINP;    // this lane's x corner
                bool by0 = (unsigned)yi0 < HINP, by1 = (unsigned)(yi0 + 1) < HINP;
                bool bz0 = (unsigned)zi0 < DINP, bz1 = (unsigned)(zi0 + 1) < DINP;
                float wxl = dx ? fx : 1.0f - fx;
                float wy0 = 1.0f - fy, wy1 = fy;
                int base = ((zi0 * HINP + yi0) * WINP + xi0) * GCH
                         + dx * GCH + q2 * 8;
                const __half* bp = xg + base;
#pragma unroll
                for (int dz = 0; dz < 2; dz++) {
                    bool bz = dz ? bz1 : bz0;
                    float wz = dz ? wz1 : wz0;
#pragma unroll
                    for (int dy = 0; dy < 2; dy++) {
                        bool ok = bxl && bz && (dy ? by1 : by0);
                        if (ok) {
                            float wt = wz * (dy ? wy1 : wy0) * wxl;
                            uint4 raw = *(const uint4*)(bp +
                                (dz * (HINP * WINP) + dy * WINP) * GCH);
                            const __half2* hp = (const __half2*)&raw;
                            float2 f0 = __half22float2(hp[0]);
                            float2 f1 = __half22float2(hp[1]);
                            float2 f2 = __half22float2(hp[2]);
                            float2 f3 = __half22float2(hp[3]);
                            aA.x = fmaf(wt, f0.x, aA.x);
                            aA.y = fmaf(wt, f0.y, aA.y);
                            aA.z = fmaf(wt, f1.x, aA.z);
                            aA.w = fmaf(wt, f1.y, aA.w);
                            aB.x = fmaf(wt, f2.x, aB.x);
                            aB.y = fmaf(wt, f2.y, aB.y);
                            aB.z = fmaf(wt, f3.x, aB.z);
                            aB.w = fmaf(wt, f3.y, aB.w);
                        }
                    }
                }
            }
            // reduce over dx (xor 1) then p8 (xor 4, 8, 16)
#pragma unroll
            for (int o = 0; o < 4; o++) {
                int st = (o == 0) ? 1 : (2 << o);          // 1, 4, 8, 16
                aA.x += __shfl_xor_sync(0xffffffffu, aA.x, st);
                aA.y += __shfl_xor_sync(0xffffffffu, aA.y, st);
                aA.z += __shfl_xor_sync(0xffffffffu, aA.z, st);
                aA.w += __shfl_xor_sync(0xffffffffu, aA.w, st);
                aB.x += __shfl_xor_sync(0xffffffffu, aB.x, st);
                aB.y += __shfl_xor_sync(0xffffffffu, aB.y, st);
                aB.z += __shfl_xor_sync(0xffffffffu, aB.z, st);
                aB.w += __shfl_xor_sync(0xffffffffu, aB.w, st);
            }
            if (dx == 0 && p8 == 0) {
                float* dst = outv + v * CC + g * GCH + q2 * 8;
                ((float4*)dst)[0] = aA;
                ((float4*)dst)[1] = aB;
            }
        }
    }
    __syncthreads();

    // ---- phase 6: output projection (64 rows, 8 voxels), packed f32x2 ----
    {
        float4 ov[VX];
#pragma unroll
        for (int v = 0; v < VX; v++) ov[v] = ((const float4*)(outv + v * CC))[hl];
#pragma unroll
        for (int i = 0; i < 4; i++) {
            int r = i * 16 + warp * 2 + half;
            float4 w = ((const float4*)(out_w + (size_t)r * CC))[hl];
            u64 wa = pk2(w.x, w.y), wb = pk2(w.z, w.w);
            float p[VX];
#pragma unroll
            for (int v = 0; v < VX; v++) {
                u64 acc = 0ull;
                fma2(acc, wa, pk2(ov[v].x, ov[v].y));
                fma2(acc, wb, pk2(ov[v].z, ov[v].w));
                float2 tv = upk2(acc);
                p[v] = tv.x + tv.y;
            }
            // multi-voxel half-warp reduce (15 shfl for 8 dots)
#pragma unroll
            for (int v = 0; v < 8; v++) p[v] += __shfl_xor_sync(0xffffffffu, p[v], 8);
            float qq[4];
            bool b4 = (hl & 4) != 0;
#pragma unroll
            for (int j = 0; j < 4; j++) {
                float send = b4 ? p[j] : p[j + 4];
                float recv = __shfl_xor_sync(0xffffffffu, send, 4);
                qq[j] = (b4 ? p[j + 4] : p[j]) + recv;
            }
            float ss[2];
            bool b2 = (hl & 2) != 0;
#pragma unroll
            for (int j = 0; j < 2; j++) {
                float send = b2 ? qq[j] : qq[j + 2];
                float recv = __shfl_xor_sync(0xffffffffu, send, 2);
                ss[j] = (b2 ? qq[j + 2] : qq[j]) + recv;
            }
            bool b1 = (hl & 1) != 0;
            float send = b1 ? ss[0] : ss[1];
            float recv = __shfl_xor_sync(0xffffffffu, send, 1);
            float tot = (b1 ? ss[1] : ss[0]) + recv;
            if (hl < 8)
                res[hl * CC + r] = tot + out_b[r];
        }
    }
    __syncthreads();

    if (tid < 128)
        ((float4*)(out + (size_t)vb * CC))[tid] = ((const float4*)res)[tid];
}

extern "C" void kernel_launch(void* const* d_in, const int* in_sizes, int n_in,
                              void* d_out, int out_size)
{
    const float* input  = (const float*)d_in[0];
    const float* dw_w   = (const float*)d_in[1];
    const float* dw_b   = (const float*)d_in[2];
    const float* ln_g   = (const float*)d_in[3];
    const float* ln_b   = (const float*)d_in[4];
    const float* off_w  = (const float*)d_in[5];
    const float* off_b  = (const float*)d_in[6];
    const float* mask_w = (const float*)d_in[7];
    const float* mask_b = (const float*)d_in[8];
    const float* in_w   = (const float*)d_in[9];
    const float* in_b   = (const float*)d_in[10];
    const float* out_w  = (const float*)d_in[11];
    const float* out_b  = (const float*)d_in[12];
    float* out = (float*)d_out;

    int proj_blocks  = NB * DINP * HINP * WINP / VX;   // 5202
    int fused_blocks = NB * DD * HH * WW / VX;         // 4096

    transpose_weights_kernel<<<36, 256>>>(off_w, mask_w, in_w);
    proj_pad_kernel<<<proj_blocks, 256>>>(input, in_b);
    dcnv3_fused_kernel<<<fused_blocks, 256>>>(
        input, dw_w, dw_b, ln_g, ln_b,
        off_b, mask_b, out_w, out_b, out);
}

// round 9
// speedup vs baseline: 20.5681x; 1.0748x over previous
#include <cuda_runtime.h>
#include <cuda_fp16.h>
#include <math.h>

#define NB 2
#define DD 16
#define HH 32
#define WW 32
#define CC 64
#define GG 4
#define GCH 16
#define PP 27
#define DINP 18
#define HINP 34
#define WINP 34
#define VX 8          // voxels per block

typedef unsigned long long u64;

// ---- packed f32x2 helpers (sm_103a dual-FMA) ----
__device__ __forceinline__ u64 pk2(float lo, float hi) {
    u64 r; asm("mov.b64 %0, {%1, %2};" : "=l"(r) : "f"(lo), "f"(hi)); return r;
}
__device__ __forceinline__ float2 upk2(u64 v) {
    float2 r; asm("mov.b64 {%0, %1}, %2;" : "=f"(r.x), "=f"(r.y) : "l"(v)); return r;
}
__device__ __forceinline__ void fma2(u64& acc, u64 a, u64 b) {
    asm("fma.rn.f32x2 %0, %1, %2, %0;" : "+l"(acc) : "l"(a), "l"(b));
}

// padded value buffer, fp16, group-major: [n][g][z][y][x][16ch], ~5.3 MB
__device__ __half g_xph[(size_t)NB * GG * DINP * HINP * WINP * GCH];
// k-major transposed head weights: [kc][r], r padded 432->512 with zeros
__device__ float4 g_wT[16 * 512];
// k-major transposed input-projection weights: [kc][r], r in [0,64)
__device__ float4 g_inT[16 * 64];

// ---------------------------------------------------------------------------
// Setup: transpose weights into k-major float4 layouts.
// ---------------------------------------------------------------------------
__global__ void transpose_weights_kernel(
    const float* __restrict__ off_w,
    const float* __restrict__ mask_w,
    const float* __restrict__ in_w)
{
    int i = blockIdx.x * blockDim.x + threadIdx.x;
    if (i < 16 * 512) {
        int kc = i >> 9, r = i & 511;
        float4 v = make_float4(0.f, 0.f, 0.f, 0.f);
        if (r < 324) {
            const float* s = off_w + (size_t)r * CC + kc * 4;
            v = make_float4(s[0], s[1], s[2], s[3]);
        } else if (r < 432) {
            const float* s = mask_w + (size_t)(r - 324) * CC + kc * 4;
            v = make_float4(s[0], s[1], s[2], s[3]);
        }
        g_wT[i] = v;
    } else {
        int j = i - 16 * 512;
        if (j < 16 * 64) {
            int kc = j >> 6, r = j & 63;
            const float* s = in_w + (size_t)r * CC + kc * 4;
            g_inT[j] = make_float4(s[0], s[1], s[2], s[3]);
        }
    }
}

// ---------------------------------------------------------------------------
// Kernel 1: value projection -> fp16 group-major padded buffer.
// ---------------------------------------------------------------------------
__global__ void __launch_bounds__(256, 4) proj_pad_kernel(
    const float* __restrict__ input,
    const float* __restrict__ in_b)
{
    int tid = threadIdx.x;
    int vb = blockIdx.x * VX;

    __shared__ __align__(16) float shx[VX * CC];
    __shared__ __align__(16) float res[VX * CC];
    __shared__ int sflag[VX];

    for (int o = tid; o < VX * CC; o += 256) {
        int v = o >> 6, c = o & 63;
        int pv = vb + v;
        int xx = pv % WINP; int t = pv / WINP;
        int yy = t % HINP; t /= HINP;
        int zz = t % DINP; int n = t / DINP;
        int xi = xx - 1, yi = yy - 1, zi = zz - 1;
        bool in = (xi >= 0 && xi < WW && yi >= 0 && yi < HH && zi >= 0 && zi < DD);
        if (c == 0) sflag[v] = in ? 1 : 0;
        shx[o] = in ? input[((size_t)((n * DD + zi) * HH + yi) * WW + xi) * CC + c] : 0.0f;
    }
    __syncthreads();

    {
        int r = tid & 63, vh = tid >> 6;       // vh: 0..3 -> voxels 2vh, 2vh+1
        int v0 = vh * 2, v1 = v0 + 1;
        u64 a0 = 0ull, a1 = 0ull;
#pragma unroll
        for (int kc = 0; kc < 16; kc++) {
            float4 w  = g_inT[kc * 64 + r];
            float4 xa = ((const float4*)shx)[v0 * 16 + kc];
            float4 xb = ((const float4*)shx)[v1 * 16 + kc];
            u64 wxy = pk2(w.x, w.y), wzw = pk2(w.z, w.w);
            fma2(a0, wxy, pk2(xa.x, xa.y));
            fma2(a0, wzw, pk2(xa.z, xa.w));
            fma2(a1, wxy, pk2(xb.x, xb.y));
            fma2(a1, wzw, pk2(xb.z, xb.w));
        }
        float b = in_b[r];
        float2 t0 = upk2(a0), t1 = upk2(a1);
        res[v0 * CC + r] = sflag[v0] ? (t0.x + t0.y + b) : 0.0f;
        res[v1 * CC + r] = sflag[v1] ? (t1.x + t1.y + b) : 0.0f;
    }
    __syncthreads();

    // write fp16 group-major: chunk = 4 channels
    for (int o = tid; o < VX * CC / 4; o += 256) {   // 128 chunks
        int v = o >> 4, g = (o >> 2) & 3, c4 = o & 3;
        int pv = vb + v;
        int xx = pv % WINP; int t = pv / WINP;
        int yy = t % HINP; t /= HINP;
        int zz = t % DINP; int n = t / DINP;
        const float* s = res + v * CC + g * GCH + c4 * 4;
        __half2 h01 = __floats2half2_rn(s[0], s[1]);
        __half2 h23 = __floats2half2_rn(s[2], s[3]);
        uint2 u;
        ((__half2*)&u)[0] = h01;
        ((__half2*)&u)[1] = h23;
        size_t base = ((size_t)(((n * GG + g) * DINP + zz) * HINP + yy) * WINP + xx) * GCH;
        *(uint2*)(g_xph + base + c4 * 4) = u;
    }
}

// ---------------------------------------------------------------------------
// Kernel 2: fused pipeline, 8 consecutive x-voxels per block, 256 threads.
// Shared memory overlays:
//   [0, 31104)      : phase 1 = slab+dwws; phase >=4.5 = SoA sampling params
//   [31104, 41472)  : offs (phase 3-4.5); outvA/outvB (phase 5-6)
//   [41472, 44928)  : maskv
//   [44928, 46976)  : x1s (phase 1b-3); res (phase 6)
// ---------------------------------------------------------------------------
__global__ void __launch_bounds__(256, 4) dcnv3_fused_kernel(
    const float* __restrict__ input,
    const float* __restrict__ dw_w,
    const float* __restrict__ dw_b,
    const float* __restrict__ ln_g,
    const float* __restrict__ ln_b,
    const float* __restrict__ off_b,
    const float* __restrict__ mask_b,
    const float* __restrict__ out_w,
    const float* __restrict__ out_b,
    float* __restrict__ out)
{
    __shared__ __align__(16) char smem_raw[46976];
    float* slab   = (float*)smem_raw;              // 5760 floats
    float* dwws   = slab + 5760;                   // 1728 floats
    // SoA sampling params (overlay slab region), index e = (g*27+p)*8 + v
    float* pwz0 = (float*)smem_raw;                // m*(1-fz)
    float* pwz1 = pwz0 + 864;                      // m*fz
    float* pfx  = pwz0 + 2 * 864;
    float* pfy  = pwz0 + 3 * 864;
    float* pxi  = pwz0 + 4 * 864;                  // int bits
    float* pyi  = pwz0 + 5 * 864;
    float* pzi  = pwz0 + 6 * 864;
    float* offs   = (float*)(smem_raw + 31104);    // 2592 floats
    float* outvA  = offs;                          // 512 floats (overlays offs)
    float* outvB  = offs + 512;                    // 512 floats
    float* maskv  = (float*)(smem_raw + 41472);    // 864 floats
    float* x1s    = (float*)(smem_raw + 44928);    // 512 floats
    float* res    = x1s;                           // 512 floats (overlays x1s)

    int tid = threadIdx.x;
    int vb = blockIdx.x * VX;
    int x0 = vb % WW; int t = vb / WW;
    int y = t % HH; t /= HH;
    int z = t % DD; int n = t / DD;

    int lane = tid & 31, warp = tid >> 5;
    int half = lane >> 4, hl = lane & 15;

    // ---- phase 1a: stage dw weights + input slab (3 x 3 x 10 x 64) ----
    for (int e = tid; e < CC * 27 / 4; e += 256)            // 432 float4
        ((float4*)dwws)[e] = ((const float4*)dw_w)[e];
    for (int e = tid; e < 3 * 3 * 10 * 16; e += 256) {      // 1440 float4
        int c4 = e & 15;
        int xx = (e >> 4) % 10;
        int r = e / 160;
        int yy = r % 3, zz = r / 3;
        int gz = z + zz - 1, gy = y + yy - 1, gx = x0 + xx - 1;
        float4 val = make_float4(0.f, 0.f, 0.f, 0.f);
        if (gz >= 0 && gz < DD && gy >= 0 && gy < HH && gx >= 0 && gx < WW)
            val = ((const float4*)(input + ((size_t)((n * DD + gz) * HH + gy) * WW + gx) * CC))[c4];
        ((float4*)slab)[e] = val;
    }
    __syncthreads();

    // ---- phase 1b: depthwise conv, sliding window in x ----
    {
        int c = tid & 63, pair = tid >> 6;     // pair in 0..3
        int v0 = pair * 2;
        float acc0 = dw_b[c], acc1 = acc0;
#pragma unroll
        for (int zz = 0; zz < 3; zz++) {
#pragma unroll
            for (int yy = 0; yy < 3; yy++) {
                const float* srow = slab + ((zz * 3 + yy) * 10 + v0) * CC + c;
                const float* wrow = dwws + c * 27 + zz * 9 + yy * 3;
                float s0 = srow[0];
                float s1 = srow[CC];
                float s2 = srow[2 * CC];
                float s3 = srow[3 * CC];
                float w0 = wrow[0], w1 = wrow[1], w2 = wrow[2];
                acc0 = fmaf(s0, w0, fmaf(s1, w1, fmaf(s2, w2, acc0)));
                acc1 = fmaf(s1, w0, fmaf(s2, w1, fmaf(s3, w2, acc1)));
            }
        }
        x1s[v0 * CC + c] = acc0;
        x1s[(v0 + 1) * CC + c] = acc1;
    }
    __syncthreads();

    // ---- phase 2: LayerNorm + exact GELU (warp = voxel) ----
    {
        int v = warp;
        float a = x1s[v * CC + lane];
        float b = x1s[v * CC + lane + 32];
        float s = a + b, s2 = a * a + b * b;
#pragma unroll
        for (int o = 16; o > 0; o >>= 1) {
            s  += __shfl_xor_sync(0xffffffffu, s,  o);
            s2 += __shfl_xor_sync(0xffffffffu, s2, o);
        }
        float mean = s * (1.0f / CC);
        float var  = s2 * (1.0f / CC) - mean * mean;
        float rstd = rsqrtf(var + 1e-6f);
        a = (a - mean) * rstd * ln_g[lane] + ln_b[lane];
        b = (b - mean) * rstd * ln_g[lane + 32] + ln_b[lane + 32];
        a = 0.5f * a * (1.0f + erff(a * 0.70710678118654752f));
        b = 0.5f * b * (1.0f + erff(b * 0.70710678118654752f));
        x1s[v * CC + lane] = a;
        x1s[v * CC + lane + 32] = b;
    }
    __syncthreads();

    // ---- phase 3: heads GEMM, shuffle-free, packed f32x2 FMAs ----
    {
        int r0 = tid, r1 = tid + 256;
        u64 a0[VX], a1[VX];
#pragma unroll
        for (int v = 0; v < VX; v++) { a0[v] = 0ull; a1[v] = 0ull; }
#pragma unroll 4
        for (int kc = 0; kc < 16; kc++) {
            float4 w0 = g_wT[kc * 512 + r0];
            float4 w1 = g_wT[kc * 512 + r1];
            u64 w0a = pk2(w0.x, w0.y), w0b = pk2(w0.z, w0.w);
            u64 w1a = pk2(w1.x, w1.y), w1b = pk2(w1.z, w1.w);
#pragma unroll
            for (int v = 0; v < VX; v++) {
                float4 xv = ((const float4*)x1s)[v * 16 + kc];
                u64 xa = pk2(xv.x, xv.y), xb = pk2(xv.z, xv.w);
                fma2(a0[v], w0a, xa);
                fma2(a0[v], w0b, xb);
                fma2(a1[v], w1a, xa);
                fma2(a1[v], w1b, xb);
            }
        }
        float b0 = off_b[r0];
#pragma unroll
        for (int v = 0; v < VX; v++) {
            float2 tv = upk2(a0[v]);
            offs[v * 324 + r0] = tv.x + tv.y + b0;
        }
        if (r1 < 324) {
            float b1 = off_b[r1];
#pragma unroll
            for (int v = 0; v < VX; v++) {
                float2 tv = upk2(a1[v]);
                offs[v * 324 + r1] = tv.x + tv.y + b1;
            }
        } else if (r1 < 432) {
            float b1 = mask_b[r1 - 324];
#pragma unroll
            for (int v = 0; v < VX; v++) {
                float2 tv = upk2(a1[v]);
                maskv[v * 108 + (r1 - 324)] = tv.x + tv.y + b1;
            }
        }
    }
    __syncthreads();

    // ---- phase 4: softmax over P per (voxel, group), warp per 4 rows ----
    {
#pragma unroll
        for (int rr = 0; rr < 4; rr++) {
            int row = warp * 4 + rr;
            float val = (lane < PP) ? maskv[row * PP + lane] : -1e30f;
            float mx = val;
#pragma unroll
            for (int o = 16; o > 0; o >>= 1)
                mx = fmaxf(mx, __shfl_xor_sync(0xffffffffu, mx, o));
            float e = (lane < PP) ? __expf(val - mx) : 0.0f;
            float s = e;
#pragma unroll
            for (int o = 16; o > 0; o >>= 1)
                s += __shfl_xor_sync(0xffffffffu, s, o);
            if (lane < PP) maskv[row * PP + lane] = e / s;
        }
    }
    __syncthreads();

    // ---- phase 4.5: precompute SoA sampling params, index (g*27+p)*8+v ----
    for (int e = tid; e < VX * GG * PP; e += 256) {
        int v = e & 7, gp = e >> 3;
        int g = gp / 27, p = gp % 27;
        int i0 = p / 9, i1 = (p / 3) % 3, i2 = p % 3;       // (kw, kh, kd)
        const float* ofv = offs + v * 324 + (g * 27 + p) * 3;
        float px = (float)(x0 + v + i0) + ofv[0];
        float py = (float)(y + i1) + ofv[1];
        float pz = (float)(z + i2) + ofv[2];
        float fx0 = floorf(px), fy0 = floorf(py), fz0 = floorf(pz);
        float fz = pz - fz0;
        float m  = maskv[v * 108 + g * 27 + p];
        pwz0[e] = m * (1.0f - fz);
        pwz1[e] = m * fz;
        pfx[e] = px - fx0;
        pfy[e] = py - fy0;
        pxi[e] = __int_as_float((int)fx0);
        pyi[e] = __int_as_float((int)fy0);
        pzi[e] = __int_as_float((int)fz0);
    }
    __syncthreads();

    // ---- phase 5: deformable trilinear sampling, cross-voxel coalesced ----
    // warp = (g, p-half); lane = (v, q2, dx). For a fixed (g,p) one warp-LDG
    // fetches all 8 voxels' dx-pairs -> near-contiguous addresses.
    {
        int dx = lane & 1, q2 = (lane >> 1) & 1, v = lane >> 2;
        int g = warp & 3, phalf = warp >> 2;
        int pstart = phalf ? 14 : 0;
        int pend   = phalf ? 27 : 14;
        float* outp = phalf ? outvB : outvA;
        const __half* xg = g_xph +
            (size_t)(n * GG + g) * (DINP * HINP * WINP) * GCH;
        float4 aA = make_float4(0.f, 0.f, 0.f, 0.f);
        float4 aB = make_float4(0.f, 0.f, 0.f, 0.f);
        for (int p = pstart; p < pend; p++) {
            int idx = (g * 27 + p) * 8 + v;
            float wz0 = pwz0[idx], wz1 = pwz1[idx];   // mask pre-folded
            float fx = pfx[idx], fy = pfy[idx];
            int xi0 = __float_as_int(pxi[idx]);
            int yi0 = __float_as_int(pyi[idx]);
            int zi0 = __float_as_int(pzi[idx]);
            bool bxl = (unsigned)(xi0 + dx) < WINP;    // this lane's x corner
            bool by0 = (unsigned)yi0 < HINP, by1 = (unsigned)(yi0 + 1) < HINP;
            bool bz0 = (unsigned)zi0 < DINP, bz1 = (unsigned)(zi0 + 1) < DINP;
            float wxl = dx ? fx : 1.0f - fx;
            float wy0 = 1.0f - fy, wy1 = fy;
            int base = ((zi0 * HINP + yi0) * WINP + xi0) * GCH
                     + dx * GCH + q2 * 8;
            const __half* bp = xg + base;
#pragma unroll
            for (int dz = 0; dz < 2; dz++) {
                bool bz = dz ? bz1 : bz0;
                float wz = dz ? wz1 : wz0;
#pragma unroll
                for (int dy = 0; dy < 2; dy++) {
                    bool ok = bxl && bz && (dy ? by1 : by0);
                    if (ok) {
                        float wt = wz * (dy ? wy1 : wy0) * wxl;
                        uint4 raw = *(const uint4*)(bp +
                            (dz * (HINP * WINP) + dy * WINP) * GCH);
                        const __half2* hp = (const __half2*)&raw;
                        float2 f0 = __half22float2(hp[0]);
                        float2 f1 = __half22float2(hp[1]);
                        float2 f2 = __half22float2(hp[2]);
                        float2 f3 = __half22float2(hp[3]);
                        aA.x = fmaf(wt, f0.x, aA.x);
                        aA.y = fmaf(wt, f0.y, aA.y);
                        aA.z = fmaf(wt, f1.x, aA.z);
                        aA.w = fmaf(wt, f1.y, aA.w);
                        aB.x = fmaf(wt, f2.x, aB.x);
                        aB.y = fmaf(wt, f2.y, aB.y);
                        aB.z = fmaf(wt, f3.x, aB.z);
                        aB.w = fmaf(wt, f3.y, aB.w);
                    }
                }
            }
        }
        // reduce over dx (xor 1)
        aA.x += __shfl_xor_sync(0xffffffffu, aA.x, 1);
        aA.y += __shfl_xor_sync(0xffffffffu, aA.y, 1);
        aA.z += __shfl_xor_sync(0xffffffffu, aA.z, 1);
        aA.w += __shfl_xor_sync(0xffffffffu, aA.w, 1);
        aB.x += __shfl_xor_sync(0xffffffffu, aB.x, 1);
        aB.y += __shfl_xor_sync(0xffffffffu, aB.y, 1);
        aB.z += __shfl_xor_sync(0xffffffffu, aB.z, 1);
        aB.w += __shfl_xor_sync(0xffffffffu, aB.w, 1);
        if (dx == 0) {
            float* dst = outp + v * CC + g * GCH + q2 * 8;
            ((float4*)dst)[0] = aA;
            ((float4*)dst)[1] = aB;
        }
    }
    __syncthreads();

    // ---- phase 6: output projection (64 rows, 8 voxels), packed f32x2 ----
    {
        float4 ov[VX];
#pragma unroll
        for (int v = 0; v < VX; v++) {
            float4 a = ((const float4*)(outvA + v * CC))[hl];
            float4 b = ((const float4*)(outvB + v * CC))[hl];
            ov[v] = make_float4(a.x + b.x, a.y + b.y, a.z + b.z, a.w + b.w);
        }
#pragma unroll
        for (int i = 0; i < 4; i++) {
            int r = i * 16 + warp * 2 + half;
            float4 w = ((const float4*)(out_w + (size_t)r * CC))[hl];
            u64 wa = pk2(w.x, w.y), wb = pk2(w.z, w.w);
            float p[VX];
#pragma unroll
            for (int v = 0; v < VX; v++) {
                u64 acc = 0ull;
                fma2(acc, wa, pk2(ov[v].x, ov[v].y));
                fma2(acc, wb, pk2(ov[v].z, ov[v].w));
                float2 tv = upk2(acc);
                p[v] = tv.x + tv.y;
            }
            // multi-voxel half-warp reduce (15 shfl for 8 dots)
#pragma unroll
            for (int v = 0; v < 8; v++) p[v] += __shfl_xor_sync(0xffffffffu, p[v], 8);
            float qq[4];
            bool b4 = (hl & 4) != 0;
#pragma unroll
            for (int j = 0; j < 4; j++) {
                float send = b4 ? p[j] : p[j + 4];
                float recv = __shfl_xor_sync(0xffffffffu, send, 4);
                qq[j] = (b4 ? p[j + 4] : p[j]) + recv;
            }
            float ss[2];
            bool b2 = (hl & 2) != 0;
#pragma unroll
            for (int j = 0; j < 2; j++) {
                float send = b2 ? qq[j] : qq[j + 2];
                float recv = __shfl_xor_sync(0xffffffffu, send, 2);
                ss[j] = (b2 ? qq[j + 2] : qq[j]) + recv;
            }
            bool b1 = (hl & 1) != 0;
            float send = b1 ? ss[0] : ss[1];
            float recv = __shfl_xor_sync(0xffffffffu, send, 1);
            float tot = (b1 ? ss[1] : ss[0]) + recv;
            if (hl < 8)
                res[hl * CC + r] = tot + out_b[r];
        }
    }
    __syncthreads();

    if (tid < 128)
        ((float4*)(out + (size_t)vb * CC))[tid] = ((const float4*)res)[tid];
}

extern "C" void kernel_launch(void* const* d_in, const int* in_sizes, int n_in,
                              void* d_out, int out_size)
{
    const float* input  = (const float*)d_in[0];
    const float* dw_w   = (const float*)d_in[1];
    const float* dw_b   = (const float*)d_in[2];
    const float* ln_g   = (const float*)d_in[3];
    const float* ln_b   = (const float*)d_in[4];
    const float* off_w  = (const float*)d_in[5];
    const float* off_b  = (const float*)d_in[6];
    const float* mask_w = (const float*)d_in[7];
    const float* mask_b = (const float*)d_in[8];
    const float* in_w   = (const float*)d_in[9];
    const float* in_b   = (const float*)d_in[10];
    const float* out_w  = (const float*)d_in[11];
    const float* out_b  = (const float*)d_in[12];
    float* out = (float*)d_out;

    int proj_blocks  = NB * DINP * HINP * WINP / VX;   // 5202
    int fused_blocks = NB * DD * HH * WW / VX;         // 4096

    transpose_weights_kernel<<<36, 256>>>(off_w, mask_w, in_w);
    proj_pad_kernel<<<proj_blocks, 256>>>(input, in_b);
    dcnv3_fused_kernel<<<fused_blocks, 256>>>(
        input, dw_w, dw_b, ln_g, ln_b,
        off_b, mask_b, out_w, out_b, out);
}

// round 10
// speedup vs baseline: 21.9844x; 1.0689x over previous
#include <cuda_runtime.h>
#include <cuda_fp16.h>
#include <math.h>

#define NB 2
#define DD 16
#define HH 32
#define WW 32
#define CC 64
#define GG 4
#define GCH 16
#define PP 27
#define DINP 18
#define HINP 34
#define WINP 34
#define VX 8          // voxels per block

typedef unsigned long long u64;

// ---- packed f32x2 helpers (sm_103a dual-FMA) ----
__device__ __forceinline__ u64 pk2(float lo, float hi) {
    u64 r; asm("mov.b64 %0, {%1, %2};" : "=l"(r) : "f"(lo), "f"(hi)); return r;
}
__device__ __forceinline__ float2 upk2(u64 v) {
    float2 r; asm("mov.b64 {%0, %1}, %2;" : "=f"(r.x), "=f"(r.y) : "l"(v)); return r;
}
__device__ __forceinline__ void fma2(u64& acc, u64 a, u64 b) {
    asm("fma.rn.f32x2 %0, %1, %2, %0;" : "+l"(acc) : "l"(a), "l"(b));
}

// padded value buffer, fp16, group-major: [n][g][z][y][x][16ch], ~5.3 MB.
// Border cells are NEVER written; they rely on static zero-initialization
// of __device__ globals (zeros == padding), valid across all graph replays.
__device__ __half g_xph[(size_t)NB * GG * DINP * HINP * WINP * GCH];
// k-major transposed head weights: [kc][r], r padded 432->512 with zeros
__device__ float4 g_wT[16 * 512];

// ---------------------------------------------------------------------------
// Multi-voxel half-warp reduction: p[v] holds partial dot (over the 16-lane
// k-split "hl") for voxel v. Returns, on lanes hl=0..7, the full sum for
// voxel v = hl. 15 shuffles for 8 reductions.
// ---------------------------------------------------------------------------
__device__ __forceinline__ float multi_reduce8(float p[VX], int hl)
{
#pragma unroll
    for (int v = 0; v < 8; v++) p[v] += __shfl_xor_sync(0xffffffffu, p[v], 8);
    float q[4];
    bool b4 = (hl & 4) != 0;
#pragma unroll
    for (int j = 0; j < 4; j++) {
        float send = b4 ? p[j] : p[j + 4];
        float recv = __shfl_xor_sync(0xffffffffu, send, 4);
        q[j] = (b4 ? p[j + 4] : p[j]) + recv;
    }
    float s[2];
    bool b2 = (hl & 2) != 0;
#pragma unroll
    for (int j = 0; j < 2; j++) {
        float send = b2 ? q[j] : q[j + 2];
        float recv = __shfl_xor_sync(0xffffffffu, send, 2);
        s[j] = (b2 ? q[j + 2] : q[j]) + recv;
    }
    bool b1 = (hl & 1) != 0;
    float send = b1 ? s[0] : s[1];
    float recv = __shfl_xor_sync(0xffffffffu, send, 1);
    return (b1 ? s[1] : s[0]) + recv;
}

// ---------------------------------------------------------------------------
// Kernel 1: value projection -> fp16 group-major padded buffer (interior
// voxels only; borders stay zero). Blocks 0..31 also build g_wT, which is
// only consumed by the fused kernel launched after this one completes.
// ---------------------------------------------------------------------------
__global__ void __launch_bounds__(256, 4) proj_pad_kernel(
    const float* __restrict__ input,
    const float* __restrict__ in_w,
    const float* __restrict__ in_b,
    const float* __restrict__ off_w,
    const float* __restrict__ mask_w)
{
    int tid = threadIdx.x;
    int vb = blockIdx.x * VX;              // OUTPUT voxel index (interior)
    int x0 = vb % WW; int t = vb / WW;
    int y = t % HH; t /= HH;
    int z = t % DD; int n = t / DD;

    // side duty: transpose head weights (first 32 blocks, 1 float4/thread)
    if (blockIdx.x < 32) {
        int i = blockIdx.x * 256 + tid;    // 0..8191
        int kc = i >> 9, r = i & 511;
        float4 v = make_float4(0.f, 0.f, 0.f, 0.f);
        if (r < 324) {
            const float* s = off_w + (size_t)r * CC + kc * 4;
            v = make_float4(s[0], s[1], s[2], s[3]);
        } else if (r < 432) {
            const float* s = mask_w + (size_t)(r - 324) * CC + kc * 4;
            v = make_float4(s[0], s[1], s[2], s[3]);
        }
        g_wT[i] = v;
    }

    __shared__ __align__(16) float shx[VX * CC];
    __shared__ __align__(16) float res[VX * CC];

    // stage 8 input voxels (always in-bounds)
    {
        const float* ip = input + ((size_t)((n * DD + z) * HH + y) * WW + x0) * CC;
        for (int o = tid; o < VX * CC / 4; o += 256)
            ((float4*)shx)[o] = ((const float4*)ip)[o];
    }
    __syncthreads();

    // GEMV: 2 rows per warp, float4 per half-warp lane, direct in_w (coalesced)
    {
        int lane = tid & 31, warp = tid >> 5;
        int half = lane >> 4, hl = lane & 15;
        float4 xv[VX];
#pragma unroll
        for (int v = 0; v < VX; v++) xv[v] = ((const float4*)shx)[v * 16 + hl];
#pragma unroll
        for (int i = 0; i < 4; i++) {
            int r = i * 16 + warp * 2 + half;
            float4 w = ((const float4*)(in_w + (size_t)r * CC))[hl];
            u64 wa = pk2(w.x, w.y), wb = pk2(w.z, w.w);
            float p[VX];
#pragma unroll
            for (int v = 0; v < VX; v++) {
                u64 acc = 0ull;
                fma2(acc, wa, pk2(xv[v].x, xv[v].y));
                fma2(acc, wb, pk2(xv[v].z, xv[v].w));
                float2 tv = upk2(acc);
                p[v] = tv.x + tv.y;
            }
            float tot = multi_reduce8(p, hl);
            if (hl < 8)
                res[hl * CC + r] = tot + in_b[r];
        }
    }
    __syncthreads();

    // write fp16 group-major at padded coords (z+1, y+1, x0+v+1)
    if (tid < VX * CC / 4) {               // 128 chunks
        int o = tid;
        int v = o >> 4, g = (o >> 2) & 3, c4 = o & 3;
        const float* s = res + v * CC + g * GCH + c4 * 4;
        __half2 h01 = __floats2half2_rn(s[0], s[1]);
        __half2 h23 = __floats2half2_rn(s[2], s[3]);
        uint2 u;
        ((__half2*)&u)[0] = h01;
        ((__half2*)&u)[1] = h23;
        size_t base = ((size_t)(((n * GG + g) * DINP + (z + 1)) * HINP + (y + 1)) * WINP
                       + (x0 + v + 1)) * GCH;
        *(uint2*)(g_xph + base + c4 * 4) = u;
    }
}

// ---------------------------------------------------------------------------
// Kernel 2: fused pipeline, 8 consecutive x-voxels per block, 256 threads.
// Shared memory overlays:
//   [0, 31104)      : phase 1 = slab+dwws; phase >=4.5 = SoA sampling params
//   [31104, 41472)  : offs (phase 3-4.5); outvA/outvB (phase 5-6)
//   [41472, 44928)  : maskv
//   [44928, 46976)  : x1s (phase 1b-3); res (phase 6)
// ---------------------------------------------------------------------------
__global__ void __launch_bounds__(256, 4) dcnv3_fused_kernel(
    const float* __restrict__ input,
    const float* __restrict__ dw_w,
    const float* __restrict__ dw_b,
    const float* __restrict__ ln_g,
    const float* __restrict__ ln_b,
    const float* __restrict__ off_b,
    const float* __restrict__ mask_b,
    const float* __restrict__ out_w,
    const float* __restrict__ out_b,
    float* __restrict__ out)
{
    __shared__ __align__(16) char smem_raw[46976];
    float* slab   = (float*)smem_raw;              // 5760 floats
    float* dwws   = slab + 5760;                   // 1728 floats
    // SoA sampling params (overlay slab region), index e = (g*27+p)*8 + v
    float* pwz0 = (float*)smem_raw;                // m*(1-fz)
    float* pwz1 = pwz0 + 864;                      // m*fz
    float* pfx  = pwz0 + 2 * 864;
    float* pfy  = pwz0 + 3 * 864;
    float* pxi  = pwz0 + 4 * 864;                  // int bits
    float* pyi  = pwz0 + 5 * 864;
    float* pzi  = pwz0 + 6 * 864;
    float* offs   = (float*)(smem_raw + 31104);    // 2592 floats
    float* outvA  = offs;                          // 512 floats (overlays offs)
    float* outvB  = offs + 512;                    // 512 floats
    float* maskv  = (float*)(smem_raw + 41472);    // 864 floats
    float* x1s    = (float*)(smem_raw + 44928);    // 512 floats
    float* res    = x1s;                           // 512 floats (overlays x1s)

    int tid = threadIdx.x;
    int vb = blockIdx.x * VX;
    int x0 = vb % WW; int t = vb / WW;
    int y = t % HH; t /= HH;
    int z = t % DD; int n = t / DD;

    int lane = tid & 31, warp = tid >> 5;
    int half = lane >> 4, hl = lane & 15;

    // ---- phase 1a: stage dw weights + input slab (3 x 3 x 10 x 64) ----
    for (int e = tid; e < CC * 27 / 4; e += 256)            // 432 float4
        ((float4*)dwws)[e] = ((const float4*)dw_w)[e];
    bool interior = (z >= 1) && (z <= DD - 2) && (y >= 1) && (y <= HH - 2)
                 && (x0 >= 1) && (x0 + VX <= WW - 1);
    if (interior) {
        const float* ib = input + ((size_t)((n * DD + z - 1) * HH + y - 1) * WW
                                   + x0 - 1) * CC;
        for (int e = tid; e < 3 * 3 * 10 * 16; e += 256) {  // 1440 float4
            int c4 = e & 15;
            int xx = (e >> 4) % 10;
            int r = e / 160;
            int yy = r % 3, zz = r / 3;
            ((float4*)slab)[e] =
                ((const float4*)(ib + ((size_t)(zz * HH + yy) * WW + xx) * CC))[c4];
        }
    } else {
        for (int e = tid; e < 3 * 3 * 10 * 16; e += 256) {
            int c4 = e & 15;
            int xx = (e >> 4) % 10;
            int r = e / 160;
            int yy = r % 3, zz = r / 3;
            int gz = z + zz - 1, gy = y + yy - 1, gx = x0 + xx - 1;
            float4 val = make_float4(0.f, 0.f, 0.f, 0.f);
            if (gz >= 0 && gz < DD && gy >= 0 && gy < HH && gx >= 0 && gx < WW)
                val = ((const float4*)(input + ((size_t)((n * DD + gz) * HH + gy) * WW + gx) * CC))[c4];
            ((float4*)slab)[e] = val;
        }
    }
    __syncthreads();

    // ---- phase 1b: depthwise conv, sliding window in x ----
    {
        int c = tid & 63, pair = tid >> 6;     // pair in 0..3
        int v0 = pair * 2;
        float acc0 = dw_b[c], acc1 = acc0;
#pragma unroll
        for (int zz = 0; zz < 3; zz++) {
#pragma unroll
            for (int yy = 0; yy < 3; yy++) {
                const float* srow = slab + ((zz * 3 + yy) * 10 + v0) * CC + c;
                const float* wrow = dwws + c * 27 + zz * 9 + yy * 3;
                float s0 = srow[0];
                float s1 = srow[CC];
                float s2 = srow[2 * CC];
                float s3 = srow[3 * CC];
                float w0 = wrow[0], w1 = wrow[1], w2 = wrow[2];
                acc0 = fmaf(s0, w0, fmaf(s1, w1, fmaf(s2, w2, acc0)));
                acc1 = fmaf(s1, w0, fmaf(s2, w1, fmaf(s3, w2, acc1)));
            }
        }
        x1s[v0 * CC + c] = acc0;
        x1s[(v0 + 1) * CC + c] = acc1;
    }
    __syncthreads();

    // ---- phase 2: LayerNorm + exact GELU (warp = voxel) ----
    {
        int v = warp;
        float a = x1s[v * CC + lane];
        float b = x1s[v * CC + lane + 32];
        float s = a + b, s2 = a * a + b * b;
#pragma unroll
        for (int o = 16; o > 0; o >>= 1) {
            s  += __shfl_xor_sync(0xffffffffu, s,  o);
            s2 += __shfl_xor_sync(0xffffffffu, s2, o);
        }
        float mean = s * (1.0f / CC);
        float var  = s2 * (1.0f / CC) - mean * mean;
        float rstd = rsqrtf(var + 1e-6f);
        a = (a - mean) * rstd * ln_g[lane] + ln_b[lane];
        b = (b - mean) * rstd * ln_g[lane + 32] + ln_b[lane + 32];
        a = 0.5f * a * (1.0f + erff(a * 0.70710678118654752f));
        b = 0.5f * b * (1.0f + erff(b * 0.70710678118654752f));
        x1s[v * CC + lane] = a;
        x1s[v * CC + lane + 32] = b;
    }
    __syncthreads();

    // ---- phase 3: heads GEMM, shuffle-free, packed f32x2 FMAs ----
    {
        int r0 = tid, r1 = tid + 256;
        u64 a0[VX], a1[VX];
#pragma unroll
        for (int v = 0; v < VX; v++) { a0[v] = 0ull; a1[v] = 0ull; }
#pragma unroll 4
        for (int kc = 0; kc < 16; kc++) {
            float4 w0 = g_wT[kc * 512 + r0];
            float4 w1 = g_wT[kc * 512 + r1];
            u64 w0a = pk2(w0.x, w0.y), w0b = pk2(w0.z, w0.w);
            u64 w1a = pk2(w1.x, w1.y), w1b = pk2(w1.z, w1.w);
#pragma unroll
            for (int v = 0; v < VX; v++) {
                float4 xv = ((const float4*)x1s)[v * 16 + kc];
                u64 xa = pk2(xv.x, xv.y), xb = pk2(xv.z, xv.w);
                fma2(a0[v], w0a, xa);
                fma2(a0[v], w0b, xb);
                fma2(a1[v], w1a, xa);
                fma2(a1[v], w1b, xb);
            }
        }
        float b0 = off_b[r0];
#pragma unroll
        for (int v = 0; v < VX; v++) {
            float2 tv = upk2(a0[v]);
            offs[v * 324 + r0] = tv.x + tv.y + b0;
        }
        if (r1 < 324) {
            float b1 = off_b[r1];
#pragma unroll
            for (int v = 0; v < VX; v++) {
                float2 tv = upk2(a1[v]);
                offs[v * 324 + r1] = tv.x + tv.y + b1;
            }
        } else if (r1 < 432) {
            float b1 = mask_b[r1 - 324];
#pragma unroll
            for (int v = 0; v < VX; v++) {
                float2 tv = upk2(a1[v]);
                maskv[v * 108 + (r1 - 324)] = tv.x + tv.y + b1;
            }
        }
    }
    __syncthreads();

    // ---- phase 4: softmax over P per (voxel, group), warp per 4 rows ----
    {
#pragma unroll
        for (int rr = 0; rr < 4; rr++) {
            int row = warp * 4 + rr;
            float val = (lane < PP) ? maskv[row * PP + lane] : -1e30f;
            float mx = val;
#pragma unroll
            for (int o = 16; o > 0; o >>= 1)
                mx = fmaxf(mx, __shfl_xor_sync(0xffffffffu, mx, o));
            float e = (lane < PP) ? __expf(val - mx) : 0.0f;
            float s = e;
#pragma unroll
            for (int o = 16; o > 0; o >>= 1)
                s += __shfl_xor_sync(0xffffffffu, s, o);
            if (lane < PP) maskv[row * PP + lane] = __fdividef(e, s);
        }
    }
    __syncthreads();

    // ---- phase 4.5: precompute SoA sampling params, index (g*27+p)*8+v ----
    for (int e = tid; e < VX * GG * PP; e += 256) {
        int v = e & 7, gp = e >> 3;
        int g = gp / 27, p = gp % 27;
        int i0 = p / 9, i1 = (p / 3) % 3, i2 = p % 3;       // (kw, kh, kd)
        const float* ofv = offs + v * 324 + (g * 27 + p) * 3;
        float px = (float)(x0 + v + i0) + ofv[0];
        float py = (float)(y + i1) + ofv[1];
        float pz = (float)(z + i2) + ofv[2];
        float fx0 = floorf(px), fy0 = floorf(py), fz0 = floorf(pz);
        float fz = pz - fz0;
        float m  = maskv[v * 108 + g * 27 + p];
        pwz0[e] = m * (1.0f - fz);
        pwz1[e] = m * fz;
        pfx[e] = px - fx0;
        pfy[e] = py - fy0;
        pxi[e] = __int_as_float((int)fx0);
        pyi[e] = __int_as_float((int)fy0);
        pzi[e] = __int_as_float((int)fz0);
    }
    __syncthreads();

    // ---- phase 5: deformable trilinear sampling, cross-voxel coalesced ----
    // warp = (g, p-half); lane = (v, q2, dx). For a fixed (g,p) one warp-LDG
    // fetches all 8 voxels' dx-pairs -> near-contiguous addresses.
    {
        int dx = lane & 1, q2 = (lane >> 1) & 1, v = lane >> 2;
        int g = warp & 3, phalf = warp >> 2;
        int pstart = phalf ? 14 : 0;
        int pend   = phalf ? 27 : 14;
        float* outp = phalf ? outvB : outvA;
        const __half* xg = g_xph +
            (size_t)(n * GG + g) * (DINP * HINP * WINP) * GCH;
        float4 aA = make_float4(0.f, 0.f, 0.f, 0.f);
        float4 aB = make_float4(0.f, 0.f, 0.f, 0.f);
        for (int p = pstart; p < pend; p++) {
            int idx = (g * 27 + p) * 8 + v;
            float wz0 = pwz0[idx], wz1 = pwz1[idx];   // mask pre-folded
            float fx = pfx[idx], fy = pfy[idx];
            int xi0 = __float_as_int(pxi[idx]);
            int yi0 = __float_as_int(pyi[idx]);
            int zi0 = __float_as_int(pzi[idx]);
            bool bxl = (unsigned)(xi0 + dx) < WINP;    // this lane's x corner
            bool by0 = (unsigned)yi0 < HINP, by1 = (unsigned)(yi0 + 1) < HINP;
            bool bz0 = (unsigned)zi0 < DINP, bz1 = (unsigned)(zi0 + 1) < DINP;
            float wxl = dx ? fx : 1.0f - fx;
            float wy0 = 1.0f - fy, wy1 = fy;
            int base = ((zi0 * HINP + yi0) * WINP + xi0) * GCH
                     + dx * GCH + q2 * 8;
            const __half* bp = xg + base;
#pragma unroll
            for (int dz = 0; dz < 2; dz++) {
                bool bz = dz ? bz1 : bz0;
                float wz = dz ? wz1 : wz0;
#pragma unroll
                for (int dy = 0; dy < 2; dy++) {
                    bool ok = bxl && bz && (dy ? by1 : by0);
                    if (ok) {
                        float wt = wz * (dy ? wy1 : wy0) * wxl;
                        uint4 raw = *(const uint4*)(bp +
                            (dz * (HINP * WINP) + dy * WINP) * GCH);
                        const __half2* hp = (const __half2*)&raw;
                        float2 f0 = __half22float2(hp[0]);
                        float2 f1 = __half22float2(hp[1]);
                        float2 f2 = __half22float2(hp[2]);
                        float2 f3 = __half22float2(hp[3]);
                        aA.x = fmaf(wt, f0.x, aA.x);
                        aA.y = fmaf(wt, f0.y, aA.y);
                        aA.z = fmaf(wt, f1.x, aA.z);
                        aA.w = fmaf(wt, f1.y, aA.w);
                        aB.x = fmaf(wt, f2.x, aB.x);
                        aB.y = fmaf(wt, f2.y, aB.y);
                        aB.z = fmaf(wt, f3.x, aB.z);
                        aB.w = fmaf(wt, f3.y, aB.w);
                    }
                }
            }
        }
        // reduce over dx (xor 1)
        aA.x += __shfl_xor_sync(0xffffffffu, aA.x, 1);
        aA.y += __shfl_xor_sync(0xffffffffu, aA.y, 1);
        aA.z += __shfl_xor_sync(0xffffffffu, aA.z, 1);
        aA.w += __shfl_xor_sync(0xffffffffu, aA.w, 1);
        aB.x += __shfl_xor_sync(0xffffffffu, aB.x, 1);
        aB.y += __shfl_xor_sync(0xffffffffu, aB.y, 1);
        aB.z += __shfl_xor_sync(0xffffffffu, aB.z, 1);
        aB.w += __shfl_xor_sync(0xffffffffu, aB.w, 1);
        if (dx == 0) {
            float* dst = outp + v * CC + g * GCH + q2 * 8;
            ((float4*)dst)[0] = aA;
            ((float4*)dst)[1] = aB;
        }
    }
    __syncthreads();

    // ---- phase 6: output projection (64 rows, 8 voxels), packed f32x2 ----
    {
        float4 ov[VX];
#pragma unroll
        for (int v = 0; v < VX; v++) {
            float4 a = ((const float4*)(outvA + v * CC))[hl];
            float4 b = ((const float4*)(outvB + v * CC))[hl];
            ov[v] = make_float4(a.x + b.x, a.y + b.y, a.z + b.z, a.w + b.w);
        }
#pragma unroll
        for (int i = 0; i < 4; i++) {
            int r = i * 16 + warp * 2 + half;
            float4 w = ((const float4*)(out_w + (size_t)r * CC))[hl];
            u64 wa = pk2(w.x, w.y), wb = pk2(w.z, w.w);
            float p[VX];
#pragma unroll
            for (int v = 0; v < VX; v++) {
                u64 acc = 0ull;
                fma2(acc, wa, pk2(ov[v].x, ov[v].y));
                fma2(acc, wb, pk2(ov[v].z, ov[v].w));
                float2 tv = upk2(acc);
                p[v] = tv.x + tv.y;
            }
            float tot = multi_reduce8(p, hl);
            if (hl < 8)
                res[hl * CC + r] = tot + out_b[r];
        }
    }
    __syncthreads();

    if (tid < 128)
        ((float4*)(out + (size_t)vb * CC))[tid] = ((const float4*)res)[tid];
}

extern "C" void kernel_launch(void* const* d_in, const int* in_sizes, int n_in,
                              void* d_out, int out_size)
{
    const float* input  = (const float*)d_in[0];
    const float* dw_w   = (const float*)d_in[1];
    const float* dw_b   = (const float*)d_in[2];
    const float* ln_g   = (const float*)d_in[3];
    const float* ln_b   = (const float*)d_in[4];
    const float* off_w  = (const float*)d_in[5];
    const float* off_b  = (const float*)d_in[6];
    const float* mask_w = (const float*)d_in[7];
    const float* mask_b = (const float*)d_in[8];
    const float* in_w   = (const float*)d_in[9];
    const float* in_b   = (const float*)d_in[10];
    const float* out_w  = (const float*)d_in[11];
    const float* out_b  = (const float*)d_in[12];
    float* out = (float*)d_out;

    int blocks = NB * DD * HH * WW / VX;               // 4096

    proj_pad_kernel<<<blocks, 256>>>(input, in_w, in_b, off_w, mask_w);
    dcnv3_fused_kernel<<<blocks, 256>>>(
        input, dw_w, dw_b, ln_g, ln_b,
        off_b, mask_b, out_w, out_b, out);
}

// round 11
// speedup vs baseline: 22.3773x; 1.0179x over previous
#include <cuda_runtime.h>
#include <cuda_fp16.h>
#include <math.h>

#define NB 2
#define DD 16
#define HH 32
#define WW 32
#define CC 64
#define GG 4
#define GCH 16
#define PP 27
#define DINP 18
#define HINP 34
#define WINP 34
#define VX 8          // voxels per block

typedef unsigned long long u64;

// ---- packed f32x2 helpers (sm_103a dual-FMA) ----
__device__ __forceinline__ u64 pk2(float lo, float hi) {
    u64 r; asm("mov.b64 %0, {%1, %2};" : "=l"(r) : "f"(lo), "f"(hi)); return r;
}
__device__ __forceinline__ float2 upk2(u64 v) {
    float2 r; asm("mov.b64 {%0, %1}, %2;" : "=f"(r.x), "=f"(r.y) : "l"(v)); return r;
}
__device__ __forceinline__ void fma2(u64& acc, u64 a, u64 b) {
    asm("fma.rn.f32x2 %0, %1, %2, %0;" : "+l"(acc) : "l"(a), "l"(b));
}

// padded value buffer, fp16, group-major: [n][g][z][y][x][16ch], ~5.3 MB.
// Border cells are NEVER written; they rely on static zero-initialization
// of __device__ globals (zeros == padding), valid across all graph replays.
__device__ __half g_xph[(size_t)NB * GG * DINP * HINP * WINP * GCH];
// k-major transposed head weights: [kc][r], r padded 432->512 with zeros
__device__ float4 g_wT[16 * 512];

// ---------------------------------------------------------------------------
// Multi-voxel half-warp reduction: p[v] holds partial dot (over the 16-lane
// k-split "hl") for voxel v. Returns, on lanes hl=0..7, the full sum for
// voxel v = hl. 15 shuffles for 8 reductions.
// ---------------------------------------------------------------------------
__device__ __forceinline__ float multi_reduce8(float p[VX], int hl)
{
#pragma unroll
    for (int v = 0; v < 8; v++) p[v] += __shfl_xor_sync(0xffffffffu, p[v], 8);
    float q[4];
    bool b4 = (hl & 4) != 0;
#pragma unroll
    for (int j = 0; j < 4; j++) {
        float send = b4 ? p[j] : p[j + 4];
        float recv = __shfl_xor_sync(0xffffffffu, send, 4);
        q[j] = (b4 ? p[j + 4] : p[j]) + recv;
    }
    float s[2];
    bool b2 = (hl & 2) != 0;
#pragma unroll
    for (int j = 0; j < 2; j++) {
        float send = b2 ? q[j] : q[j + 2];
        float recv = __shfl_xor_sync(0xffffffffu, send, 2);
        s[j] = (b2 ? q[j + 2] : q[j]) + recv;
    }
    bool b1 = (hl & 1) != 0;
    float send = b1 ? s[0] : s[1];
    float recv = __shfl_xor_sync(0xffffffffu, send, 1);
    return (b1 ? s[1] : s[0]) + recv;
}

// ---------------------------------------------------------------------------
// Kernel 1: value projection -> fp16 group-major padded buffer (interior
// voxels only; borders stay zero). Blocks 0..31 also build g_wT, which is
// only consumed by the fused kernel launched after this one completes.
// ---------------------------------------------------------------------------
__global__ void __launch_bounds__(256, 4) proj_pad_kernel(
    const float* __restrict__ input,
    const float* __restrict__ in_w,
    const float* __restrict__ in_b,
    const float* __restrict__ off_w,
    const float* __restrict__ mask_w)
{
    int tid = threadIdx.x;
    int vb = blockIdx.x * VX;              // OUTPUT voxel index (interior)
    int x0 = vb % WW; int t = vb / WW;
    int y = t % HH; t /= HH;
    int z = t % DD; int n = t / DD;

    // side duty: transpose head weights (first 32 blocks, 1 float4/thread)
    if (blockIdx.x < 32) {
        int i = blockIdx.x * 256 + tid;    // 0..8191
        int kc = i >> 9, r = i & 511;
        float4 v = make_float4(0.f, 0.f, 0.f, 0.f);
        if (r < 324) {
            const float* s = off_w + (size_t)r * CC + kc * 4;
            v = make_float4(s[0], s[1], s[2], s[3]);
        } else if (r < 432) {
            const float* s = mask_w + (size_t)(r - 324) * CC + kc * 4;
            v = make_float4(s[0], s[1], s[2], s[3]);
        }
        g_wT[i] = v;
    }

    __shared__ __align__(16) float shx[VX * CC];
    __shared__ __align__(16) float res[VX * CC];

    // stage 8 input voxels (always in-bounds)
    {
        const float* ip = input + ((size_t)((n * DD + z) * HH + y) * WW + x0) * CC;
        for (int o = tid; o < VX * CC / 4; o += 256)
            ((float4*)shx)[o] = ((const float4*)ip)[o];
    }
    __syncthreads();

    // GEMV: 2 rows per warp, float4 per half-warp lane, direct in_w (coalesced)
    {
        int lane = tid & 31, warp = tid >> 5;
        int half = lane >> 4, hl = lane & 15;
        float4 xv[VX];
#pragma unroll
        for (int v = 0; v < VX; v++) xv[v] = ((const float4*)shx)[v * 16 + hl];
#pragma unroll
        for (int i = 0; i < 4; i++) {
            int r = i * 16 + warp * 2 + half;
            float4 w = ((const float4*)(in_w + (size_t)r * CC))[hl];
            u64 wa = pk2(w.x, w.y), wb = pk2(w.z, w.w);
            float p[VX];
#pragma unroll
            for (int v = 0; v < VX; v++) {
                u64 acc = 0ull;
                fma2(acc, wa, pk2(xv[v].x, xv[v].y));
                fma2(acc, wb, pk2(xv[v].z, xv[v].w));
                float2 tv = upk2(acc);
                p[v] = tv.x + tv.y;
            }
            float tot = multi_reduce8(p, hl);
            if (hl < 8)
                res[hl * CC + r] = tot + in_b[r];
        }
    }
    __syncthreads();

    // write fp16 group-major at padded coords (z+1, y+1, x0+v+1)
    if (tid < VX * CC / 4) {               // 128 chunks
        int o = tid;
        int v = o >> 4, g = (o >> 2) & 3, c4 = o & 3;
        const float* s = res + v * CC + g * GCH + c4 * 4;
        __half2 h01 = __floats2half2_rn(s[0], s[1]);
        __half2 h23 = __floats2half2_rn(s[2], s[3]);
        uint2 u;
        ((__half2*)&u)[0] = h01;
        ((__half2*)&u)[1] = h23;
        size_t base = ((size_t)(((n * GG + g) * DINP + (z + 1)) * HINP + (y + 1)) * WINP
                       + (x0 + v + 1)) * GCH;
        *(uint2*)(g_xph + base + c4 * 4) = u;
    }
}

// ---------------------------------------------------------------------------
// Kernel 2: fused pipeline, 8 consecutive x-voxels per block, 256 threads.
// Shared memory overlays:
//   [0, 31104)      : phase 1 = slab+dwws; phase >=4.5 = packed sampling params
//   [31104, 41472)  : offs (phase 3-4.5); outvA/outvB (phase 5-6)
//   [41472, 44928)  : maskv
//   [44928, 46976)  : x1s (phase 1b-3); res (phase 6)
// ---------------------------------------------------------------------------
__global__ void __launch_bounds__(256, 4) dcnv3_fused_kernel(
    const float* __restrict__ input,
    const float* __restrict__ dw_w,
    const float* __restrict__ dw_b,
    const float* __restrict__ ln_g,
    const float* __restrict__ ln_b,
    const float* __restrict__ off_b,
    const float* __restrict__ mask_b,
    const float* __restrict__ out_w,
    const float* __restrict__ out_b,
    float* __restrict__ out)
{
    __shared__ __align__(16) char smem_raw[46976];
    float* slab   = (float*)smem_raw;              // 5760 floats
    float* dwws   = slab + 5760;                   // 1728 floats
    // packed sampling params (overlay slab region), index e = (g*27+p)*8 + v
    float2* pA = (float2*)smem_raw;                // [m*(1-fz), m*fz]   6912B
    float2* pB = pA + 864;                         // [fx, fy]           6912B
    int2*   pC = (int2*)(pB + 864);                // [base, boundbits]  6912B
    float* offs   = (float*)(smem_raw + 31104);    // 2592 floats
    float* outvA  = offs;                          // 512 floats (overlays offs)
    float* outvB  = offs + 512;                    // 512 floats
    float* maskv  = (float*)(smem_raw + 41472);    // 864 floats
    float* x1s    = (float*)(smem_raw + 44928);    // 512 floats
    float* res    = x1s;                           // 512 floats (overlays x1s)

    int tid = threadIdx.x;
    int vb = blockIdx.x * VX;
    int x0 = vb % WW; int t = vb / WW;
    int y = t % HH; t /= HH;
    int z = t % DD; int n = t / DD;

    int lane = tid & 31, warp = tid >> 5;
    int half = lane >> 4, hl = lane & 15;

    // ---- phase 1a: stage dw weights + input slab (3 x 3 x 10 x 64) ----
    for (int e = tid; e < CC * 27 / 4; e += 256)            // 432 float4
        ((float4*)dwws)[e] = ((const float4*)dw_w)[e];
    bool interior = (z >= 1) && (z <= DD - 2) && (y >= 1) && (y <= HH - 2)
                 && (x0 >= 1) && (x0 + VX <= WW - 1);
    if (interior) {
        const float* ib = input + ((size_t)((n * DD + z - 1) * HH + y - 1) * WW
                                   + x0 - 1) * CC;
        for (int e = tid; e < 3 * 3 * 10 * 16; e += 256) {  // 1440 float4
            int c4 = e & 15;
            int xx = (e >> 4) % 10;
            int r = e / 160;
            int yy = r % 3, zz = r / 3;
            ((float4*)slab)[e] =
                ((const float4*)(ib + ((size_t)(zz * HH + yy) * WW + xx) * CC))[c4];
        }
    } else {
        for (int e = tid; e < 3 * 3 * 10 * 16; e += 256) {
            int c4 = e & 15;
            int xx = (e >> 4) % 10;
            int r = e / 160;
            int yy = r % 3, zz = r / 3;
            int gz = z + zz - 1, gy = y + yy - 1, gx = x0 + xx - 1;
            float4 val = make_float4(0.f, 0.f, 0.f, 0.f);
            if (gz >= 0 && gz < DD && gy >= 0 && gy < HH && gx >= 0 && gx < WW)
                val = ((const float4*)(input + ((size_t)((n * DD + gz) * HH + gy) * WW + gx) * CC))[c4];
            ((float4*)slab)[e] = val;
        }
    }
    __syncthreads();

    // ---- phase 1b: depthwise conv, sliding window in x ----
    {
        int c = tid & 63, pair = tid >> 6;     // pair in 0..3
        int v0 = pair * 2;
        float acc0 = dw_b[c], acc1 = acc0;
#pragma unroll
        for (int zz = 0; zz < 3; zz++) {
#pragma unroll
            for (int yy = 0; yy < 3; yy++) {
                const float* srow = slab + ((zz * 3 + yy) * 10 + v0) * CC + c;
                const float* wrow = dwws + c * 27 + zz * 9 + yy * 3;
                float s0 = srow[0];
                float s1 = srow[CC];
                float s2 = srow[2 * CC];
                float s3 = srow[3 * CC];
                float w0 = wrow[0], w1 = wrow[1], w2 = wrow[2];
                acc0 = fmaf(s0, w0, fmaf(s1, w1, fmaf(s2, w2, acc0)));
                acc1 = fmaf(s1, w0, fmaf(s2, w1, fmaf(s3, w2, acc1)));
            }
        }
        x1s[v0 * CC + c] = acc0;
        x1s[(v0 + 1) * CC + c] = acc1;
    }
    __syncthreads();

    // ---- phase 2: LayerNorm + exact GELU (warp = voxel) ----
    {
        int v = warp;
        float a = x1s[v * CC + lane];
        float b = x1s[v * CC + lane + 32];
        float s = a + b, s2 = a * a + b * b;
#pragma unroll
        for (int o = 16; o > 0; o >>= 1) {
            s  += __shfl_xor_sync(0xffffffffu, s,  o);
            s2 += __shfl_xor_sync(0xffffffffu, s2, o);
        }
        float mean = s * (1.0f / CC);
        float var  = s2 * (1.0f / CC) - mean * mean;
        float rstd = rsqrtf(var + 1e-6f);
        a = (a - mean) * rstd * ln_g[lane] + ln_b[lane];
        b = (b - mean) * rstd * ln_g[lane + 32] + ln_b[lane + 32];
        a = 0.5f * a * (1.0f + erff(a * 0.70710678118654752f));
        b = 0.5f * b * (1.0f + erff(b * 0.70710678118654752f));
        x1s[v * CC + lane] = a;
        x1s[v * CC + lane + 32] = b;
    }
    __syncthreads();

    // ---- phase 3: heads GEMM, shuffle-free, packed f32x2 FMAs ----
    {
        int r0 = tid, r1 = tid + 256;
        u64 a0[VX], a1[VX];
#pragma unroll
        for (int v = 0; v < VX; v++) { a0[v] = 0ull; a1[v] = 0ull; }
#pragma unroll 4
        for (int kc = 0; kc < 16; kc++) {
            float4 w0 = g_wT[kc * 512 + r0];
            float4 w1 = g_wT[kc * 512 + r1];
            u64 w0a = pk2(w0.x, w0.y), w0b = pk2(w0.z, w0.w);
            u64 w1a = pk2(w1.x, w1.y), w1b = pk2(w1.z, w1.w);
#pragma unroll
            for (int v = 0; v < VX; v++) {
                float4 xv = ((const float4*)x1s)[v * 16 + kc];
                u64 xa = pk2(xv.x, xv.y), xb = pk2(xv.z, xv.w);
                fma2(a0[v], w0a, xa);
                fma2(a0[v], w0b, xb);
                fma2(a1[v], w1a, xa);
                fma2(a1[v], w1b, xb);
            }
        }
        float b0 = off_b[r0];
#pragma unroll
        for (int v = 0; v < VX; v++) {
            float2 tv = upk2(a0[v]);
            offs[v * 324 + r0] = tv.x + tv.y + b0;
        }
        if (r1 < 324) {
            float b1 = off_b[r1];
#pragma unroll
            for (int v = 0; v < VX; v++) {
                float2 tv = upk2(a1[v]);
                offs[v * 324 + r1] = tv.x + tv.y + b1;
            }
        } else if (r1 < 432) {
            float b1 = mask_b[r1 - 324];
#pragma unroll
            for (int v = 0; v < VX; v++) {
                float2 tv = upk2(a1[v]);
                maskv[v * 108 + (r1 - 324)] = tv.x + tv.y + b1;
            }
        }
    }
    __syncthreads();

    // ---- phase 4: softmax over P per (voxel, group), warp per 4 rows ----
    {
#pragma unroll
        for (int rr = 0; rr < 4; rr++) {
            int row = warp * 4 + rr;
            float val = (lane < PP) ? maskv[row * PP + lane] : -1e30f;
            float mx = val;
#pragma unroll
            for (int o = 16; o > 0; o >>= 1)
                mx = fmaxf(mx, __shfl_xor_sync(0xffffffffu, mx, o));
            float e = (lane < PP) ? __expf(val - mx) : 0.0f;
            float s = e;
#pragma unroll
            for (int o = 16; o > 0; o >>= 1)
                s += __shfl_xor_sync(0xffffffffu, s, o);
            if (lane < PP) maskv[row * PP + lane] = __fdividef(e, s);
        }
    }
    __syncthreads();

    // ---- phase 4.5: precompute packed sampling params, e = (g*27+p)*8+v ----
    // pA = [m*(1-fz), m*fz]; pB = [fx, fy];
    // pC = [flat base index, 6 bound bits: bx0|bx1<<1|by0<<2|by1<<3|bz0<<4|bz1<<5]
    for (int e = tid; e < VX * GG * PP; e += 256) {
        int v = e & 7, gp = e >> 3;
        int g = gp / 27, p = gp % 27;
        int i0 = p / 9, i1 = (p / 3) % 3, i2 = p % 3;       // (kw, kh, kd)
        const float* ofv = offs + v * 324 + (g * 27 + p) * 3;
        float px = (float)(x0 + v + i0) + ofv[0];
        float py = (float)(y + i1) + ofv[1];
        float pz = (float)(z + i2) + ofv[2];
        float fx0 = floorf(px), fy0 = floorf(py), fz0 = floorf(pz);
        int xi = (int)fx0, yi = (int)fy0, zi = (int)fz0;
        float fz = pz - fz0;
        float m  = maskv[v * 108 + g * 27 + p];
        pA[e] = make_float2(m * (1.0f - fz), m * fz);
        pB[e] = make_float2(px - fx0, py - fy0);
        int mbits = ((unsigned)xi       < WINP ?  1 : 0)
                  | ((unsigned)(xi + 1) < WINP ?  2 : 0)
                  | ((unsigned)yi       < HINP ?  4 : 0)
                  | ((unsigned)(yi + 1) < HINP ?  8 : 0)
                  | ((unsigned)zi       < DINP ? 16 : 0)
                  | ((unsigned)(zi + 1) < DINP ? 32 : 0);
        int base = ((zi * HINP + yi) * WINP + xi) * GCH;
        pC[e] = make_int2(base, mbits);
    }
    __syncthreads();

    // ---- phase 5: deformable trilinear sampling, cross-voxel coalesced ----
    // warp = (g, p-half); lane = (v, q2, dx). For a fixed (g,p) one warp-LDG
    // fetches all 8 voxels' dx-pairs -> near-contiguous addresses.
    {
        int dx = lane & 1, q2 = (lane >> 1) & 1, v = lane >> 2;
        int g = warp & 3, phalf = warp >> 2;
        int pstart = phalf ? 14 : 0;
        int pend   = phalf ? 27 : 14;
        float* outp = phalf ? outvB : outvA;
        const __half* xgl = g_xph +
            (size_t)(n * GG + g) * (DINP * HINP * WINP) * GCH
            + dx * GCH + q2 * 8;                   // lane-fixed part of address
        float4 aA = make_float4(0.f, 0.f, 0.f, 0.f);
        float4 aB = make_float4(0.f, 0.f, 0.f, 0.f);
        for (int p = pstart; p < pend; p++) {
            int idx = (g * 27 + p) * 8 + v;
            float2 wzp = pA[idx];                  // mask pre-folded z weights
            float2 fxy = pB[idx];
            int2   bm  = pC[idx];
            int mb = bm.y;
            bool bxl = (mb >> dx) & 1;             // this lane's x corner
            float wxl = dx ? fxy.x : 1.0f - fxy.x;
            float wy0 = 1.0f - fxy.y, wy1 = fxy.y;
            const __half* bp = xgl + bm.x;
#pragma unroll
            for (int dz = 0; dz < 2; dz++) {
                bool bz = (mb & (16 << dz)) != 0;
                float wz = dz ? wzp.y : wzp.x;
#pragma unroll
                for (int dy = 0; dy < 2; dy++) {
                    bool ok = bxl && bz && ((mb & (4 << dy)) != 0);
                    if (ok) {
                        float wt = wz * (dy ? wy1 : wy0) * wxl;
                        uint4 raw = *(const uint4*)(bp +
                            (dz * (HINP * WINP) + dy * WINP) * GCH);
                        const __half2* hp = (const __half2*)&raw;
                        float2 f0 = __half22float2(hp[0]);
                        float2 f1 = __half22float2(hp[1]);
                        float2 f2 = __half22float2(hp[2]);
                        float2 f3 = __half22float2(hp[3]);
                        aA.x = fmaf(wt, f0.x, aA.x);
                        aA.y = fmaf(wt, f0.y, aA.y);
                        aA.z = fmaf(wt, f1.x, aA.z);
                        aA.w = fmaf(wt, f1.y, aA.w);
                        aB.x = fmaf(wt, f2.x, aB.x);
                        aB.y = fmaf(wt, f2.y, aB.y);
                        aB.z = fmaf(wt, f3.x, aB.z);
                        aB.w = fmaf(wt, f3.y, aB.w);
                    }
                }
            }
        }
        // reduce over dx (xor 1)
        aA.x += __shfl_xor_sync(0xffffffffu, aA.x, 1);
        aA.y += __shfl_xor_sync(0xffffffffu, aA.y, 1);
        aA.z += __shfl_xor_sync(0xffffffffu, aA.z, 1);
        aA.w += __shfl_xor_sync(0xffffffffu, aA.w, 1);
        aB.x += __shfl_xor_sync(0xffffffffu, aB.x, 1);
        aB.y += __shfl_xor_sync(0xffffffffu, aB.y, 1);
        aB.z += __shfl_xor_sync(0xffffffffu, aB.z, 1);
        aB.w += __shfl_xor_sync(0xffffffffu, aB.w, 1);
        if (dx == 0) {
            float* dst = outp + v * CC + g * GCH + q2 * 8;
            ((float4*)dst)[0] = aA;
            ((float4*)dst)[1] = aB;
        }
    }
    __syncthreads();

    // ---- phase 6: output projection (64 rows, 8 voxels), packed f32x2 ----
    {
        float4 ov[VX];
#pragma unroll
        for (int v = 0; v < VX; v++) {
            float4 a = ((const float4*)(outvA + v * CC))[hl];
            float4 b = ((const float4*)(outvB + v * CC))[hl];
            ov[v] = make_float4(a.x + b.x, a.y + b.y, a.z + b.z, a.w + b.w);
        }
#pragma unroll
        for (int i = 0; i < 4; i++) {
            int r = i * 16 + warp * 2 + half;
            float4 w = ((const float4*)(out_w + (size_t)r * CC))[hl];
            u64 wa = pk2(w.x, w.y), wb = pk2(w.z, w.w);
            float p[VX];
#pragma unroll
            for (int v = 0; v < VX; v++) {
                u64 acc = 0ull;
                fma2(acc, wa, pk2(ov[v].x, ov[v].y));
                fma2(acc, wb, pk2(ov[v].z, ov[v].w));
                float2 tv = upk2(acc);
                p[v] = tv.x + tv.y;
            }
            float tot = multi_reduce8(p, hl);
            if (hl < 8)
                res[hl * CC + r] = tot + out_b[r];
        }
    }
    __syncthreads();

    if (tid < 128)
        ((float4*)(out + (size_t)vb * CC))[tid] = ((const float4*)res)[tid];
}

extern "C" void kernel_launch(void* const* d_in, const int* in_sizes, int n_in,
                              void* d_out, int out_size)
{
    const float* input  = (const float*)d_in[0];
    const float* dw_w   = (const float*)d_in[1];
    const float* dw_b   = (const float*)d_in[2];
    const float* ln_g   = (const float*)d_in[3];
    const float* ln_b   = (const float*)d_in[4];
    const float* off_w  = (const float*)d_in[5];
    const float* off_b  = (const float*)d_in[6];
    const float* mask_w = (const float*)d_in[7];
    const float* mask_b = (const float*)d_in[8];
    const float* in_w   = (const float*)d_in[9];
    const float* in_b   = (const float*)d_in[10];
    const float* out_w  = (const float*)d_in[11];
    const float* out_b  = (const float*)d_in[12];
    float* out = (float*)d_out;

    int blocks = NB * DD * HH * WW / VX;               // 4096

    proj_pad_kernel<<<blocks, 256>>>(input, in_w, in_b, off_w, mask_w);
    dcnv3_fused_kernel<<<blocks, 256>>>(
        input, dw_w, dw_b, ln_g, ln_b,
        off_b, mask_b, out_w, out_b, out);
}

// round 12
// speedup vs baseline: 25.6454x; 1.1460x over previous
#include <cuda_runtime.h>
#include <cuda_fp16.h>
#include <math.h>

#define NB 2
#define DD 16
#define HH 32
#define WW 32
#define CC 64
#define GG 4
#define GCH 16
#define PP 27
#define DINP 18
#define HINP 34
#define WINP 34
#define VX 8          // voxels per block

typedef unsigned long long u64;

// ---- packed f32x2 helpers (sm_103a dual-FMA) ----
__device__ __forceinline__ u64 pk2(float lo, float hi) {
    u64 r; asm("mov.b64 %0, {%1, %2};" : "=l"(r) : "f"(lo), "f"(hi)); return r;
}
__device__ __forceinline__ float2 upk2(u64 v) {
    float2 r; asm("mov.b64 {%0, %1}, %2;" : "=f"(r.x), "=f"(r.y) : "l"(v)); return r;
}
__device__ __forceinline__ void fma2(u64& acc, u64 a, u64 b) {
    asm("fma.rn.f32x2 %0, %1, %2, %0;" : "+l"(acc) : "l"(a), "l"(b));
}

// padded value buffer, fp16, group-major: [n][g][z][y][x][16ch], ~5.3 MB.
// Border cells are NEVER written; they rely on static zero-initialization.
__device__ __half g_xph[(size_t)NB * GG * DINP * HINP * WINP * GCH];
// heads weights pre-packed as fp16 mma B-fragments:
// index ((nt*4+ks)*32+lane), uint2 = {w[n][k0],w[n][k0+1],w[n][k0+8],w[n][k0+9]}
// with n = nt*8 + (lane>>2), k0 = ks*16 + (lane&3)*2. Rows 0..323 = offset
// head, 324..431 = mask head. 54 n-tiles cover 432 rows exactly.
__device__ uint2 g_wB[54 * 4 * 32];

// ---------------------------------------------------------------------------
// Multi-voxel half-warp reduction (phase 6 / proj): 15 shuffles for 8 dots.
// ---------------------------------------------------------------------------
__device__ __forceinline__ float multi_reduce8(float p[VX], int hl)
{
#pragma unroll
    for (int v = 0; v < 8; v++) p[v] += __shfl_xor_sync(0xffffffffu, p[v], 8);
    float q[4];
    bool b4 = (hl & 4) != 0;
#pragma unroll
    for (int j = 0; j < 4; j++) {
        float send = b4 ? p[j] : p[j + 4];
        float recv = __shfl_xor_sync(0xffffffffu, send, 4);
        q[j] = (b4 ? p[j + 4] : p[j]) + recv;
    }
    float s[2];
    bool b2 = (hl & 2) != 0;
#pragma unroll
    for (int j = 0; j < 2; j++) {
        float send = b2 ? q[j] : q[j + 2];
        float recv = __shfl_xor_sync(0xffffffffu, send, 2);
        s[j] = (b2 ? q[j + 2] : q[j]) + recv;
    }
    bool b1 = (hl & 1) != 0;
    float send = b1 ? s[0] : s[1];
    float recv = __shfl_xor_sync(0xffffffffu, send, 1);
    return (b1 ? s[1] : s[0]) + recv;
}

// ---------------------------------------------------------------------------
// Kernel 1: value projection -> fp16 group-major padded buffer (interior
// voxels only). Blocks 0..31 also pack g_wB (consumed only by kernel 2).
// ---------------------------------------------------------------------------
__global__ void __launch_bounds__(256, 4) proj_pad_kernel(
    const float* __restrict__ input,
    const float* __restrict__ in_w,
    const float* __restrict__ in_b,
    const float* __restrict__ off_w,
    const float* __restrict__ mask_w)
{
    int tid = threadIdx.x;
    int vb = blockIdx.x * VX;              // OUTPUT voxel index (interior)
    int x0 = vb % WW; int t = vb / WW;
    int y = t % HH; t /= HH;
    int z = t % DD; int n = t / DD;

    // side duty: pack head weights into mma B-fragment layout (fp16)
    if (blockIdx.x < 32) {
        int i = blockIdx.x * 256 + tid;    // 0..8191
        if (i < 54 * 4 * 32) {
            int nt = i >> 7;
            int rem = i & 127;
            int ks = rem >> 5, ln = rem & 31;
            int g = ln >> 2, tg = ln & 3;
            int nrow = nt * 8 + g;
            int k0 = ks * 16 + tg * 2;
            const float* wr = (nrow < 324) ? off_w + (size_t)nrow * CC
                                           : mask_w + (size_t)(nrow - 324) * CC;
            __half2 lo = __floats2half2_rn(wr[k0], wr[k0 + 1]);
            __half2 hi = __floats2half2_rn(wr[k0 + 8], wr[k0 + 9]);
            uint2 u;
            ((__half2*)&u)[0] = lo;
            ((__half2*)&u)[1] = hi;
            g_wB[i] = u;
        }
    }

    __shared__ __align__(16) float shx[VX * CC];
    __shared__ __align__(16) float res[VX * CC];

    // stage 8 input voxels (always in-bounds)
    {
        const float* ip = input + ((size_t)((n * DD + z) * HH + y) * WW + x0) * CC;
        for (int o = tid; o < VX * CC / 4; o += 256)
            ((float4*)shx)[o] = ((const float4*)ip)[o];
    }
    __syncthreads();

    // GEMV: 2 rows per warp, float4 per half-warp lane, direct in_w (coalesced)
    {
        int lane = tid & 31, warp = tid >> 5;
        int half = lane >> 4, hl = lane & 15;
        float4 xv[VX];
#pragma unroll
        for (int v = 0; v < VX; v++) xv[v] = ((const float4*)shx)[v * 16 + hl];
#pragma unroll
        for (int i = 0; i < 4; i++) {
            int r = i * 16 + warp * 2 + half;
            float4 w = ((const float4*)(in_w + (size_t)r * CC))[hl];
            u64 wa = pk2(w.x, w.y), wb = pk2(w.z, w.w);
            float p[VX];
#pragma unroll
            for (int v = 0; v < VX; v++) {
                u64 acc = 0ull;
                fma2(acc, wa, pk2(xv[v].x, xv[v].y));
                fma2(acc, wb, pk2(xv[v].z, xv[v].w));
                float2 tv = upk2(acc);
                p[v] = tv.x + tv.y;
            }
            float tot = multi_reduce8(p, hl);
            if (hl < 8)
                res[hl * CC + r] = tot + in_b[r];
        }
    }
    __syncthreads();

    // write fp16 group-major at padded coords (z+1, y+1, x0+v+1)
    if (tid < VX * CC / 4) {               // 128 chunks
        int o = tid;
        int v = o >> 4, g = (o >> 2) & 3, c4 = o & 3;
        const float* s = res + v * CC + g * GCH + c4 * 4;
        __half2 h01 = __floats2half2_rn(s[0], s[1]);
        __half2 h23 = __floats2half2_rn(s[2], s[3]);
        uint2 u;
        ((__half2*)&u)[0] = h01;
        ((__half2*)&u)[1] = h23;
        size_t base = ((size_t)(((n * GG + g) * DINP + (z + 1)) * HINP + (y + 1)) * WINP
                       + (x0 + v + 1)) * GCH;
        *(uint2*)(g_xph + base + c4 * 4) = u;
    }
}

// ---------------------------------------------------------------------------
// Kernel 2: fused pipeline, 8 consecutive x-voxels per block, 256 threads.
// Shared memory overlays (48000 B total):
//   [0, 31104)      : phase 1 = slab+dwws; phase >=4.5 = packed sampling params
//   [31104, 41472)  : offs (phase 3-4.5); outvA/outvB (phase 5-6)
//   [41472, 44928)  : maskv
//   [44928, 46976)  : x1s (phase 1b-2); res (phase 6)
//   [46976, 48000)  : x1h fp16 (phase 2-3)
// ---------------------------------------------------------------------------
__global__ void __launch_bounds__(256, 4) dcnv3_fused_kernel(
    const float* __restrict__ input,
    const float* __restrict__ dw_w,
    const float* __restrict__ dw_b,
    const float* __restrict__ ln_g,
    const float* __restrict__ ln_b,
    const float* __restrict__ off_b,
    const float* __restrict__ mask_b,
    const float* __restrict__ out_w,
    const float* __restrict__ out_b,
    float* __restrict__ out)
{
    __shared__ __align__(16) char smem_raw[48000];
    float* slab   = (float*)smem_raw;              // 5760 floats
    float* dwws   = slab + 5760;                   // 1728 floats
    // packed sampling params (overlay slab region), index e = (g*27+p)*8 + v
    float2* pA = (float2*)smem_raw;                // [m*(1-fz), m*fz]
    float2* pB = pA + 864;                         // [fx, fy]
    int2*   pC = (int2*)(pB + 864);                // [base, boundbits]
    float* offs   = (float*)(smem_raw + 31104);    // 2592 floats
    float* outvA  = offs;                          // 512 floats (overlays offs)
    float* outvB  = offs + 512;                    // 512 floats
    float* maskv  = (float*)(smem_raw + 41472);    // 864 floats
    float* x1s    = (float*)(smem_raw + 44928);    // 512 floats
    float* res    = x1s;                           // 512 floats (overlays x1s)
    __half* x1h   = (__half*)(smem_raw + 46976);   // 512 halves

    int tid = threadIdx.x;
    int vb = blockIdx.x * VX;
    int x0 = vb % WW; int t = vb / WW;
    int y = t % HH; t /= HH;
    int z = t % DD; int n = t / DD;

    int lane = tid & 31, warp = tid >> 5;
    int half = lane >> 4, hl = lane & 15;

    // ---- phase 1a: stage dw weights + input slab (3 x 3 x 10 x 64) ----
    for (int e = tid; e < CC * 27 / 4; e += 256)            // 432 float4
        ((float4*)dwws)[e] = ((const float4*)dw_w)[e];
    bool interior = (z >= 1) && (z <= DD - 2) && (y >= 1) && (y <= HH - 2)
                 && (x0 >= 1) && (x0 + VX <= WW - 1);
    if (interior) {
        const float* ib = input + ((size_t)((n * DD + z - 1) * HH + y - 1) * WW
                                   + x0 - 1) * CC;
        for (int e = tid; e < 3 * 3 * 10 * 16; e += 256) {  // 1440 float4
            int c4 = e & 15;
            int xx = (e >> 4) % 10;
            int r = e / 160;
            int yy = r % 3, zz = r / 3;
            ((float4*)slab)[e] =
                ((const float4*)(ib + ((size_t)(zz * HH + yy) * WW + xx) * CC))[c4];
        }
    } else {
        for (int e = tid; e < 3 * 3 * 10 * 16; e += 256) {
            int c4 = e & 15;
            int xx = (e >> 4) % 10;
            int r = e / 160;
            int yy = r % 3, zz = r / 3;
            int gz = z + zz - 1, gy = y + yy - 1, gx = x0 + xx - 1;
            float4 val = make_float4(0.f, 0.f, 0.f, 0.f);
            if (gz >= 0 && gz < DD && gy >= 0 && gy < HH && gx >= 0 && gx < WW)
                val = ((const float4*)(input + ((size_t)((n * DD + gz) * HH + gy) * WW + gx) * CC))[c4];
            ((float4*)slab)[e] = val;
        }
    }
    __syncthreads();

    // ---- phase 1b: depthwise conv, sliding window in x ----
    {
        int c = tid & 63, pair = tid >> 6;     // pair in 0..3
        int v0 = pair * 2;
        float acc0 = dw_b[c], acc1 = acc0;
#pragma unroll
        for (int zz = 0; zz < 3; zz++) {
#pragma unroll
            for (int yy = 0; yy < 3; yy++) {
                const float* srow = slab + ((zz * 3 + yy) * 10 + v0) * CC + c;
                const float* wrow = dwws + c * 27 + zz * 9 + yy * 3;
                float s0 = srow[0];
                float s1 = srow[CC];
                float s2 = srow[2 * CC];
                float s3 = srow[3 * CC];
                float w0 = wrow[0], w1 = wrow[1], w2 = wrow[2];
                acc0 = fmaf(s0, w0, fmaf(s1, w1, fmaf(s2, w2, acc0)));
                acc1 = fmaf(s1, w0, fmaf(s2, w1, fmaf(s3, w2, acc1)));
            }
        }
        x1s[v0 * CC + c] = acc0;
        x1s[(v0 + 1) * CC + c] = acc1;
    }
    __syncthreads();

    // ---- phase 2: LayerNorm + exact GELU (warp = voxel), write fp16 x1h ----
    {
        int v = warp;
        float a = x1s[v * CC + lane];
        float b = x1s[v * CC + lane + 32];
        float s = a + b, s2 = a * a + b * b;
#pragma unroll
        for (int o = 16; o > 0; o >>= 1) {
            s  += __shfl_xor_sync(0xffffffffu, s,  o);
            s2 += __shfl_xor_sync(0xffffffffu, s2, o);
        }
        float mean = s * (1.0f / CC);
        float var  = s2 * (1.0f / CC) - mean * mean;
        float rstd = rsqrtf(var + 1e-6f);
        a = (a - mean) * rstd * ln_g[lane] + ln_b[lane];
        b = (b - mean) * rstd * ln_g[lane + 32] + ln_b[lane + 32];
        a = 0.5f * a * (1.0f + erff(a * 0.70710678118654752f));
        b = 0.5f * b * (1.0f + erff(b * 0.70710678118654752f));
        x1h[v * CC + lane]      = __float2half(a);
        x1h[v * CC + lane + 32] = __float2half(b);
    }
    __syncthreads();

    // ---- phase 3: heads GEMM on tensor cores (m16n8k16, fp16 in, fp32 acc).
    // A rows 0..7 = voxels (rows 8..15 zero); B = g_wB fragments; 54 n-tiles.
    {
        int g = lane >> 2, tg = lane & 3;
        unsigned a0[4], a2[4];
        const __half* xr = x1h + g * CC;
#pragma unroll
        for (int ks = 0; ks < 4; ks++) {
            a0[ks] = *(const unsigned*)(xr + ks * 16 + tg * 2);
            a2[ks] = *(const unsigned*)(xr + ks * 16 + 8 + tg * 2);
        }
        for (int nt = warp; nt < 54; nt += 8) {
            float c0 = 0.f, c1 = 0.f, c2 = 0.f, c3 = 0.f;
#pragma unroll
            for (int ks = 0; ks < 4; ks++) {
                uint2 wq = g_wB[(nt * 4 + ks) * 32 + lane];
                asm volatile(
                    "mma.sync.aligned.m16n8k16.row.col.f32.f16.f16.f32 "
                    "{%0,%1,%2,%3},{%4,%5,%6,%7},{%8,%9},{%0,%1,%2,%3};"
                    : "+f"(c0), "+f"(c1), "+f"(c2), "+f"(c3)
                    : "r"(a0[ks]), "r"(0u), "r"(a2[ks]), "r"(0u),
                      "r"(wq.x), "r"(wq.y));
            }
            int n0 = nt * 8 + tg * 2;              // even; n0,n0+1 same head
            if (n0 < 324) {
                float2 bb = *(const float2*)(off_b + n0);
                float2 st = make_float2(c0 + bb.x, c1 + bb.y);
                *(float2*)(offs + g * 324 + n0) = st;
            } else {
                float2 bb = *(const float2*)(mask_b + (n0 - 324));
                float2 st = make_float2(c0 + bb.x, c1 + bb.y);
                *(float2*)(maskv + g * 108 + (n0 - 324)) = st;
            }
        }
    }
    __syncthreads();

    // ---- phase 4: softmax over P per (voxel, group), warp per 4 rows ----
    {
#pragma unroll
        for (int rr = 0; rr < 4; rr++) {
            int row = warp * 4 + rr;
            float val = (lane < PP) ? maskv[row * PP + lane] : -1e30f;
            float mx = val;
#pragma unroll
            for (int o = 16; o > 0; o >>= 1)
                mx = fmaxf(mx, __shfl_xor_sync(0xffffffffu, mx, o));
            float e = (lane < PP) ? __expf(val - mx) : 0.0f;
            float s = e;
#pragma unroll
            for (int o = 16; o > 0; o >>= 1)
                s += __shfl_xor_sync(0xffffffffu, s, o);
            if (lane < PP) maskv[row * PP + lane] = __fdividef(e, s);
        }
    }
    __syncthreads();

    // ---- phase 4.5: precompute packed sampling params, e = (g*27+p)*8+v ----
    for (int e = tid; e < VX * GG * PP; e += 256) {
        int v = e & 7, gp = e >> 3;
        int g = gp / 27, p = gp % 27;
        int i0 = p / 9, i1 = (p / 3) % 3, i2 = p % 3;       // (kw, kh, kd)
        const float* ofv = offs + v * 324 + (g * 27 + p) * 3;
        float px = (float)(x0 + v + i0) + ofv[0];
        float py = (float)(y + i1) + ofv[1];
        float pz = (float)(z + i2) + ofv[2];
        float fx0 = floorf(px), fy0 = floorf(py), fz0 = floorf(pz);
        int xi = (int)fx0, yi = (int)fy0, zi = (int)fz0;
        float fz = pz - fz0;
        float m  = maskv[v * 108 + g * 27 + p];
        pA[e] = make_float2(m * (1.0f - fz), m * fz);
        pB[e] = make_float2(px - fx0, py - fy0);
        int mbits = ((unsigned)xi       < WINP ?  1 : 0)
                  | ((unsigned)(xi + 1) < WINP ?  2 : 0)
                  | ((unsigned)yi       < HINP ?  4 : 0)
                  | ((unsigned)(yi + 1) < HINP ?  8 : 0)
                  | ((unsigned)zi       < DINP ? 16 : 0)
                  | ((unsigned)(zi + 1) < DINP ? 32 : 0);
        int base = ((zi * HINP + yi) * WINP + xi) * GCH;
        pC[e] = make_int2(base, mbits);
    }
    __syncthreads();

    // ---- phase 5: deformable trilinear sampling, cross-voxel coalesced ----
    {
        int dx = lane & 1, q2 = (lane >> 1) & 1, v = lane >> 2;
        int g = warp & 3, phalf = warp >> 2;
        int pstart = phalf ? 14 : 0;
        int pend   = phalf ? 27 : 14;
        float* outp = phalf ? outvB : outvA;
        const __half* xgl = g_xph +
            (size_t)(n * GG + g) * (DINP * HINP * WINP) * GCH
            + dx * GCH + q2 * 8;                   // lane-fixed part of address
        float4 aA = make_float4(0.f, 0.f, 0.f, 0.f);
        float4 aB = make_float4(0.f, 0.f, 0.f, 0.f);
        for (int p = pstart; p < pend; p++) {
            int idx = (g * 27 + p) * 8 + v;
            float2 wzp = pA[idx];                  // mask pre-folded z weights
            float2 fxy = pB[idx];
            int2   bm  = pC[idx];
            int mb = bm.y;
            bool bxl = (mb >> dx) & 1;             // this lane's x corner
            float wxl = dx ? fxy.x : 1.0f - fxy.x;
            float wy0 = 1.0f - fxy.y, wy1 = fxy.y;
            const __half* bp = xgl + bm.x;
#pragma unroll
            for (int dz = 0; dz < 2; dz++) {
                bool bz = (mb & (16 << dz)) != 0;
                float wz = dz ? wzp.y : wzp.x;
#pragma unroll
                for (int dy = 0; dy < 2; dy++) {
                    bool ok = bxl && bz && ((mb & (4 << dy)) != 0);
                    if (ok) {
                        float wt = wz * (dy ? wy1 : wy0) * wxl;
                        uint4 raw = *(const uint4*)(bp +
                            (dz * (HINP * WINP) + dy * WINP) * GCH);
                        const __half2* hp = (const __half2*)&raw;
                        float2 f0 = __half22float2(hp[0]);
                        float2 f1 = __half22float2(hp[1]);
                        float2 f2 = __half22float2(hp[2]);
                        float2 f3 = __half22float2(hp[3]);
                        aA.x = fmaf(wt, f0.x, aA.x);
                        aA.y = fmaf(wt, f0.y, aA.y);
                        aA.z = fmaf(wt, f1.x, aA.z);
                        aA.w = fmaf(wt, f1.y, aA.w);
                        aB.x = fmaf(wt, f2.x, aB.x);
                        aB.y = fmaf(wt, f2.y, aB.y);
                        aB.z = fmaf(wt, f3.x, aB.z);
                        aB.w = fmaf(wt, f3.y, aB.w);
                    }
                }
            }
        }
        // reduce over dx (xor 1)
        aA.x += __shfl_xor_sync(0xffffffffu, aA.x, 1);
        aA.y += __shfl_xor_sync(0xffffffffu, aA.y, 1);
        aA.z += __shfl_xor_sync(0xffffffffu, aA.z, 1);
        aA.w += __shfl_xor_sync(0xffffffffu, aA.w, 1);
        aB.x += __shfl_xor_sync(0xffffffffu, aB.x, 1);
        aB.y += __shfl_xor_sync(0xffffffffu, aB.y, 1);
        aB.z += __shfl_xor_sync(0xffffffffu, aB.z, 1);
        aB.w += __shfl_xor_sync(0xffffffffu, aB.w, 1);
        if (dx == 0) {
            float* dst = outp + v * CC + g * GCH + q2 * 8;
            ((float4*)dst)[0] = aA;
            ((float4*)dst)[1] = aB;
        }
    }
    __syncthreads();

    // ---- phase 6: output projection (64 rows, 8 voxels), packed f32x2 ----
    {
        float4 ov[VX];
#pragma unroll
        for (int v = 0; v < VX; v++) {
            float4 a = ((const float4*)(outvA + v * CC))[hl];
            float4 b = ((const float4*)(outvB + v * CC))[hl];
            ov[v] = make_float4(a.x + b.x, a.y + b.y, a.z + b.z, a.w + b.w);
        }
#pragma unroll
        for (int i = 0; i < 4; i++) {
            int r = i * 16 + warp * 2 + half;
            float4 w = ((const float4*)(out_w + (size_t)r * CC))[hl];
            u64 wa = pk2(w.x, w.y), wb = pk2(w.z, w.w);
            float p[VX];
#pragma unroll
            for (int v = 0; v < VX; v++) {
                u64 acc = 0ull;
                fma2(acc, wa, pk2(ov[v].x, ov[v].y));
                fma2(acc, wb, pk2(ov[v].z, ov[v].w));
                float2 tv = upk2(acc);
                p[v] = tv.x + tv.y;
            }
            float tot = multi_reduce8(p, hl);
            if (hl < 8)
                res[hl * CC + r] = tot + out_b[r];
        }
    }
    __syncthreads();

    if (tid < 128)
        ((float4*)(out + (size_t)vb * CC))[tid] = ((const float4*)res)[tid];
}

extern "C" void kernel_launch(void* const* d_in, const int* in_sizes, int n_in,
                              void* d_out, int out_size)
{
    const float* input  = (const float*)d_in[0];
    const float* dw_w   = (const float*)d_in[1];
    const float* dw_b   = (const float*)d_in[2];
    const float* ln_g   = (const float*)d_in[3];
    const float* ln_b   = (const float*)d_in[4];
    const float* off_w  = (const float*)d_in[5];
    const float* off_b  = (const float*)d_in[6];
    const float* mask_w = (const float*)d_in[7];
    const float* mask_b = (const float*)d_in[8];
    const float* in_w   = (const float*)d_in[9];
    const float* in_b   = (const float*)d_in[10];
    const float* out_w  = (const float*)d_in[11];
    const float* out_b  = (const float*)d_in[12];
    float* out = (float*)d_out;

    int blocks = NB * DD * HH * WW / VX;               // 4096

    proj_pad_kernel<<<blocks, 256>>>(input, in_w, in_b, off_w, mask_w);
    dcnv3_fused_kernel<<<blocks, 256>>>(
        input, dw_w, dw_b, ln_g, ln_b,
        off_b, mask_b, out_w, out_b, out);
}

// round 13
// speedup vs baseline: 26.9520x; 1.0509x over previous
#include <cuda_runtime.h>
#include <cuda_fp16.h>
#include <math.h>

#define NB 2
#define DD 16
#define HH 32
#define WW 32
#define CC 64
#define GG 4
#define GCH 16
#define PP 27
#define DINP 18
#define HINP 34
#define WINP 34
#define VX 8          // voxels per block

typedef unsigned long long u64;

// ---- packed f32x2 helpers (sm_103a dual-FMA) ----
__device__ __forceinline__ u64 pk2(float lo, float hi) {
    u64 r; asm("mov.b64 %0, {%1, %2};" : "=l"(r) : "f"(lo), "f"(hi)); return r;
}
__device__ __forceinline__ float2 upk2(u64 v) {
    float2 r; asm("mov.b64 {%0, %1}, %2;" : "=f"(r.x), "=f"(r.y) : "l"(v)); return r;
}
__device__ __forceinline__ void fma2(u64& acc, u64 a, u64 b) {
    asm("fma.rn.f32x2 %0, %1, %2, %0;" : "+l"(acc) : "l"(a), "l"(b));
}

// padded value buffer, fp16, group-major: [n][g][z][y][x][16ch], ~5.3 MB.
// Border cells are NEVER written; they rely on static zero-initialization.
__device__ __half g_xph[(size_t)NB * GG * DINP * HINP * WINP * GCH];
// heads weights pre-packed as fp16 mma B-fragments:
// index ((nt*4+ks)*32+lane), uint2 = {w[n][k0],w[n][k0+1],w[n][k0+8],w[n][k0+9]}
// with n = nt*8 + (lane>>2), k0 = ks*16 + (lane&3)*2. Rows 0..323 = offset
// head, 324..431 = mask head. 54 n-tiles cover 432 rows exactly.
__device__ uint2 g_wB[54 * 4 * 32];
// out_w pre-packed the same way: 8 n-tiles cover 64 rows.
__device__ uint2 g_wO[8 * 4 * 32];

// ---------------------------------------------------------------------------
// Multi-voxel half-warp reduction (proj kernel): 15 shuffles for 8 dots.
// ---------------------------------------------------------------------------
__device__ __forceinline__ float multi_reduce8(float p[VX], int hl)
{
#pragma unroll
    for (int v = 0; v < 8; v++) p[v] += __shfl_xor_sync(0xffffffffu, p[v], 8);
    float q[4];
    bool b4 = (hl & 4) != 0;
#pragma unroll
    for (int j = 0; j < 4; j++) {
        float send = b4 ? p[j] : p[j + 4];
        float recv = __shfl_xor_sync(0xffffffffu, send, 4);
        q[j] = (b4 ? p[j + 4] : p[j]) + recv;
    }
    float s[2];
    bool b2 = (hl & 2) != 0;
#pragma unroll
    for (int j = 0; j < 2; j++) {
        float send = b2 ? q[j] : q[j + 2];
        float recv = __shfl_xor_sync(0xffffffffu, send, 2);
        s[j] = (b2 ? q[j + 2] : q[j]) + recv;
    }
    bool b1 = (hl & 1) != 0;
    float send = b1 ? s[0] : s[1];
    float recv = __shfl_xor_sync(0xffffffffu, send, 1);
    return (b1 ? s[1] : s[0]) + recv;
}

// ---------------------------------------------------------------------------
// Kernel 1: value projection -> fp16 group-major padded buffer (interior
// voxels only). Blocks 0..31 also pack g_wB/g_wO (consumed only by kernel 2).
// ---------------------------------------------------------------------------
__global__ void __launch_bounds__(256, 4) proj_pad_kernel(
    const float* __restrict__ input,
    const float* __restrict__ in_w,
    const float* __restrict__ in_b,
    const float* __restrict__ off_w,
    const float* __restrict__ mask_w,
    const float* __restrict__ out_w)
{
    int tid = threadIdx.x;
    int vb = blockIdx.x * VX;              // OUTPUT voxel index (interior)
    int x0 = vb % WW; int t = vb / WW;
    int y = t % HH; t /= HH;
    int z = t % DD; int n = t / DD;

    // side duty: pack head + out_w weights into mma B-fragment layout (fp16)
    if (blockIdx.x < 32) {
        int i = blockIdx.x * 256 + tid;    // 0..8191
        if (i < 54 * 4 * 32) {
            int nt = i >> 7;
            int rem = i & 127;
            int ks = rem >> 5, ln = rem & 31;
            int g = ln >> 2, tg = ln & 3;
            int nrow = nt * 8 + g;
            int k0 = ks * 16 + tg * 2;
            const float* wr = (nrow < 324) ? off_w + (size_t)nrow * CC
                                           : mask_w + (size_t)(nrow - 324) * CC;
            __half2 lo = __floats2half2_rn(wr[k0], wr[k0 + 1]);
            __half2 hi = __floats2half2_rn(wr[k0 + 8], wr[k0 + 9]);
            uint2 u;
            ((__half2*)&u)[0] = lo;
            ((__half2*)&u)[1] = hi;
            g_wB[i] = u;
        } else if (i < 54 * 4 * 32 + 8 * 4 * 32) {
            int j = i - 54 * 4 * 32;
            int nt = j >> 7;
            int rem = j & 127;
            int ks = rem >> 5, ln = rem & 31;
            int g = ln >> 2, tg = ln & 3;
            int nrow = nt * 8 + g;
            int k0 = ks * 16 + tg * 2;
            const float* wr = out_w + (size_t)nrow * CC;
            __half2 lo = __floats2half2_rn(wr[k0], wr[k0 + 1]);
            __half2 hi = __floats2half2_rn(wr[k0 + 8], wr[k0 + 9]);
            uint2 u;
            ((__half2*)&u)[0] = lo;
            ((__half2*)&u)[1] = hi;
            g_wO[j] = u;
        }
    }

    __shared__ __align__(16) float shx[VX * CC];
    __shared__ __align__(16) float res[VX * CC];

    // stage 8 input voxels (always in-bounds)
    {
        const float* ip = input + ((size_t)((n * DD + z) * HH + y) * WW + x0) * CC;
        for (int o = tid; o < VX * CC / 4; o += 256)
            ((float4*)shx)[o] = ((const float4*)ip)[o];
    }
    __syncthreads();

    // GEMV: 2 rows per warp, float4 per half-warp lane, direct in_w (coalesced)
    {
        int lane = tid & 31, warp = tid >> 5;
        int half = lane >> 4, hl = lane & 15;
        float4 xv[VX];
#pragma unroll
        for (int v = 0; v < VX; v++) xv[v] = ((const float4*)shx)[v * 16 + hl];
#pragma unroll
        for (int i = 0; i < 4; i++) {
            int r = i * 16 + warp * 2 + half;
            float4 w = ((const float4*)(in_w + (size_t)r * CC))[hl];
            u64 wa = pk2(w.x, w.y), wb = pk2(w.z, w.w);
            float p[VX];
#pragma unroll
            for (int v = 0; v < VX; v++) {
                u64 acc = 0ull;
                fma2(acc, wa, pk2(xv[v].x, xv[v].y));
                fma2(acc, wb, pk2(xv[v].z, xv[v].w));
                float2 tv = upk2(acc);
                p[v] = tv.x + tv.y;
            }
            float tot = multi_reduce8(p, hl);
            if (hl < 8)
                res[hl * CC + r] = tot + in_b[r];
        }
    }
    __syncthreads();

    // write fp16 group-major at padded coords (z+1, y+1, x0+v+1)
    if (tid < VX * CC / 4) {               // 128 chunks
        int o = tid;
        int v = o >> 4, g = (o >> 2) & 3, c4 = o & 3;
        const float* s = res + v * CC + g * GCH + c4 * 4;
        __half2 h01 = __floats2half2_rn(s[0], s[1]);
        __half2 h23 = __floats2half2_rn(s[2], s[3]);
        uint2 u;
        ((__half2*)&u)[0] = h01;
        ((__half2*)&u)[1] = h23;
        size_t base = ((size_t)(((n * GG + g) * DINP + (z + 1)) * HINP + (y + 1)) * WINP
                       + (x0 + v + 1)) * GCH;
        *(uint2*)(g_xph + base + c4 * 4) = u;
    }
}

// ---------------------------------------------------------------------------
// Kernel 2: fused pipeline, 8 consecutive x-voxels per block, 256 threads.
// Shared memory overlays (48000 B total):
//   [0, 31104)      : phase 1 = slab+dwws; phase >=4.5 = packed sampling params
//   [31104, 41472)  : offs (phase 3-4.5); outhA/outhB fp16 (phase 5-6)
//   [41472, 44928)  : maskv
//   [44928, 46976)  : x1s (phase 1b-2); res (phase 6)
//   [46976, 48000)  : x1h fp16 (phase 2-3)
// ---------------------------------------------------------------------------
__global__ void __launch_bounds__(256, 4) dcnv3_fused_kernel(
    const float* __restrict__ input,
    const float* __restrict__ dw_w,
    const float* __restrict__ dw_b,
    const float* __restrict__ ln_g,
    const float* __restrict__ ln_b,
    const float* __restrict__ off_b,
    const float* __restrict__ mask_b,
    const float* __restrict__ out_b,
    float* __restrict__ out)
{
    __shared__ __align__(16) char smem_raw[48000];
    float* slab   = (float*)smem_raw;              // 5760 floats
    float* dwws   = slab + 5760;                   // 1728 floats
    // packed sampling params (overlay slab region), index e = (g*27+p)*8 + v
    float2* pA = (float2*)smem_raw;                // [m*(1-fz), m*fz]
    float2* pB = pA + 864;                         // [fx, fy]
    int2*   pC = (int2*)(pB + 864);                // [base, boundbits]
    float* offs   = (float*)(smem_raw + 31104);    // 2592 floats
    __half* outhA = (__half*)offs;                 // 512 halves (overlays offs)
    __half* outhB = outhA + 512;                   // 512 halves
    float* maskv  = (float*)(smem_raw + 41472);    // 864 floats
    float* x1s    = (float*)(smem_raw + 44928);    // 512 floats
    float* res    = x1s;                           // 512 floats (overlays x1s)
    __half* x1h   = (__half*)(smem_raw + 46976);   // 512 halves

    int tid = threadIdx.x;
    int vb = blockIdx.x * VX;
    int x0 = vb % WW; int t = vb / WW;
    int y = t % HH; t /= HH;
    int z = t % DD; int n = t / DD;

    int lane = tid & 31, warp = tid >> 5;

    // ---- phase 1a: stage dw weights + input slab (3 x 3 x 10 x 64) ----
    for (int e = tid; e < CC * 27 / 4; e += 256)            // 432 float4
        ((float4*)dwws)[e] = ((const float4*)dw_w)[e];
    bool interior = (z >= 1) && (z <= DD - 2) && (y >= 1) && (y <= HH - 2)
                 && (x0 >= 1) && (x0 + VX <= WW - 1);
    if (interior) {
        const float* ib = input + ((size_t)((n * DD + z - 1) * HH + y - 1) * WW
                                   + x0 - 1) * CC;
        for (int e = tid; e < 3 * 3 * 10 * 16; e += 256) {  // 1440 float4
            int c4 = e & 15;
            int xx = (e >> 4) % 10;
            int r = e / 160;
            int yy = r % 3, zz = r / 3;
            ((float4*)slab)[e] =
                ((const float4*)(ib + ((size_t)(zz * HH + yy) * WW + xx) * CC))[c4];
        }
    } else {
        for (int e = tid; e < 3 * 3 * 10 * 16; e += 256) {
            int c4 = e & 15;
            int xx = (e >> 4) % 10;
            int r = e / 160;
            int yy = r % 3, zz = r / 3;
            int gz = z + zz - 1, gy = y + yy - 1, gx = x0 + xx - 1;
            float4 val = make_float4(0.f, 0.f, 0.f, 0.f);
            if (gz >= 0 && gz < DD && gy >= 0 && gy < HH && gx >= 0 && gx < WW)
                val = ((const float4*)(input + ((size_t)((n * DD + gz) * HH + gy) * WW + gx) * CC))[c4];
            ((float4*)slab)[e] = val;
        }
    }
    __syncthreads();

    // ---- phase 1b: depthwise conv, sliding window in x ----
    {
        int c = tid & 63, pair = tid >> 6;     // pair in 0..3
        int v0 = pair * 2;
        float acc0 = dw_b[c], acc1 = acc0;
#pragma unroll
        for (int zz = 0; zz < 3; zz++) {
#pragma unroll
            for (int yy = 0; yy < 3; yy++) {
                const float* srow = slab + ((zz * 3 + yy) * 10 + v0) * CC + c;
                const float* wrow = dwws + c * 27 + zz * 9 + yy * 3;
                float s0 = srow[0];
                float s1 = srow[CC];
                float s2 = srow[2 * CC];
                float s3 = srow[3 * CC];
                float w0 = wrow[0], w1 = wrow[1], w2 = wrow[2];
                acc0 = fmaf(s0, w0, fmaf(s1, w1, fmaf(s2, w2, acc0)));
                acc1 = fmaf(s1, w0, fmaf(s2, w1, fmaf(s3, w2, acc1)));
            }
        }
        x1s[v0 * CC + c] = acc0;
        x1s[(v0 + 1) * CC + c] = acc1;
    }
    __syncthreads();

    // ---- phase 2: LayerNorm + exact GELU (warp = voxel), write fp16 x1h ----
    {
        int v = warp;
        float a = x1s[v * CC + lane];
        float b = x1s[v * CC + lane + 32];
        float s = a + b, s2 = a * a + b * b;
#pragma unroll
        for (int o = 16; o > 0; o >>= 1) {
            s  += __shfl_xor_sync(0xffffffffu, s,  o);
            s2 += __shfl_xor_sync(0xffffffffu, s2, o);
        }
        float mean = s * (1.0f / CC);
        float var  = s2 * (1.0f / CC) - mean * mean;
        float rstd = rsqrtf(var + 1e-6f);
        a = (a - mean) * rstd * ln_g[lane] + ln_b[lane];
        b = (b - mean) * rstd * ln_g[lane + 32] + ln_b[lane + 32];
        a = 0.5f * a * (1.0f + erff(a * 0.70710678118654752f));
        b = 0.5f * b * (1.0f + erff(b * 0.70710678118654752f));
        x1h[v * CC + lane]      = __float2half(a);
        x1h[v * CC + lane + 32] = __float2half(b);
    }
    __syncthreads();

    // ---- phase 3: heads GEMM on tensor cores (m16n8k16, fp16 in, fp32 acc).
    {
        int g = lane >> 2, tg = lane & 3;
        unsigned a0[4], a2[4];
        const __half* xr = x1h + g * CC;
#pragma unroll
        for (int ks = 0; ks < 4; ks++) {
            a0[ks] = *(const unsigned*)(xr + ks * 16 + tg * 2);
            a2[ks] = *(const unsigned*)(xr + ks * 16 + 8 + tg * 2);
        }
        for (int nt = warp; nt < 54; nt += 8) {
            float c0 = 0.f, c1 = 0.f, c2 = 0.f, c3 = 0.f;
#pragma unroll
            for (int ks = 0; ks < 4; ks++) {
                uint2 wq = g_wB[(nt * 4 + ks) * 32 + lane];
                asm volatile(
                    "mma.sync.aligned.m16n8k16.row.col.f32.f16.f16.f32 "
                    "{%0,%1,%2,%3},{%4,%5,%6,%7},{%8,%9},{%0,%1,%2,%3};"
                    : "+f"(c0), "+f"(c1), "+f"(c2), "+f"(c3)
                    : "r"(a0[ks]), "r"(0u), "r"(a2[ks]), "r"(0u),
                      "r"(wq.x), "r"(wq.y));
            }
            int n0 = nt * 8 + tg * 2;              // even; n0,n0+1 same head
            if (n0 < 324) {
                float2 bb = *(const float2*)(off_b + n0);
                float2 st = make_float2(c0 + bb.x, c1 + bb.y);
                *(float2*)(offs + g * 324 + n0) = st;
            } else {
                float2 bb = *(const float2*)(mask_b + (n0 - 324));
                float2 st = make_float2(c0 + bb.x, c1 + bb.y);
                *(float2*)(maskv + g * 108 + (n0 - 324)) = st;
            }
        }
    }
    __syncthreads();

    // ---- phase 4: softmax over P per (voxel, group), warp per 4 rows ----
    {
#pragma unroll
        for (int rr = 0; rr < 4; rr++) {
            int row = warp * 4 + rr;
            float val = (lane < PP) ? maskv[row * PP + lane] : -1e30f;
            float mx = val;
#pragma unroll
            for (int o = 16; o > 0; o >>= 1)
                mx = fmaxf(mx, __shfl_xor_sync(0xffffffffu, mx, o));
            float e = (lane < PP) ? __expf(val - mx) : 0.0f;
            float s = e;
#pragma unroll
            for (int o = 16; o > 0; o >>= 1)
                s += __shfl_xor_sync(0xffffffffu, s, o);
            if (lane < PP) maskv[row * PP + lane] = __fdividef(e, s);
        }
    }
    __syncthreads();

    // ---- phase 4.5: precompute packed sampling params, e = (g*27+p)*8+v ----
    for (int e = tid; e < VX * GG * PP; e += 256) {
        int v = e & 7, gp = e >> 3;
        int g = gp / 27, p = gp % 27;
        int i0 = p / 9, i1 = (p / 3) % 3, i2 = p % 3;       // (kw, kh, kd)
        const float* ofv = offs + v * 324 + (g * 27 + p) * 3;
        float px = (float)(x0 + v + i0) + ofv[0];
        float py = (float)(y + i1) + ofv[1];
        float pz = (float)(z + i2) + ofv[2];
        float fx0 = floorf(px), fy0 = floorf(py), fz0 = floorf(pz);
        int xi = (int)fx0, yi = (int)fy0, zi = (int)fz0;
        float fz = pz - fz0;
        float m  = maskv[v * 108 + g * 27 + p];
        pA[e] = make_float2(m * (1.0f - fz), m * fz);
        pB[e] = make_float2(px - fx0, py - fy0);
        int mbits = ((unsigned)xi       < WINP ?  1 : 0)
                  | ((unsigned)(xi + 1) < WINP ?  2 : 0)
                  | ((unsigned)yi       < HINP ?  4 : 0)
                  | ((unsigned)(yi + 1) < HINP ?  8 : 0)
                  | ((unsigned)zi       < DINP ? 16 : 0)
                  | ((unsigned)(zi + 1) < DINP ? 32 : 0);
        int base = ((zi * HINP + yi) * WINP + xi) * GCH;
        pC[e] = make_int2(base, mbits);
    }
    __syncthreads();

    // ---- phase 5: deformable trilinear sampling, cross-voxel coalesced.
    // Output written as fp16 (consumed by phase-6 tensor-core projection).
    {
        int dx = lane & 1, q2 = (lane >> 1) & 1, v = lane >> 2;
        int g = warp & 3, phalf = warp >> 2;
        int pstart = phalf ? 14 : 0;
        int pend   = phalf ? 27 : 14;
        __half* outp = phalf ? outhB : outhA;
        const __half* xgl = g_xph +
            (size_t)(n * GG + g) * (DINP * HINP * WINP) * GCH
            + dx * GCH + q2 * 8;                   // lane-fixed part of address
        float4 aA = make_float4(0.f, 0.f, 0.f, 0.f);
        float4 aB = make_float4(0.f, 0.f, 0.f, 0.f);
        for (int p = pstart; p < pend; p++) {
            int idx = (g * 27 + p) * 8 + v;
            float2 wzp = pA[idx];                  // mask pre-folded z weights
            float2 fxy = pB[idx];
            int2   bm  = pC[idx];
            int mb = bm.y;
            bool bxl = (mb >> dx) & 1;             // this lane's x corner
            float wxl = dx ? fxy.x : 1.0f - fxy.x;
            float wy0 = 1.0f - fxy.y, wy1 = fxy.y;
            const __half* bp = xgl + bm.x;
#pragma unroll
            for (int dz = 0; dz < 2; dz++) {
                bool bz = (mb & (16 << dz)) != 0;
                float wz = dz ? wzp.y : wzp.x;
#pragma unroll
                for (int dy = 0; dy < 2; dy++) {
                    bool ok = bxl && bz && ((mb & (4 << dy)) != 0);
                    if (ok) {
                        float wt = wz * (dy ? wy1 : wy0) * wxl;
                        uint4 raw = *(const uint4*)(bp +
                            (dz * (HINP * WINP) + dy * WINP) * GCH);
                        const __half2* hp = (const __half2*)&raw;
                        float2 f0 = __half22float2(hp[0]);
                        float2 f1 = __half22float2(hp[1]);
                        float2 f2 = __half22float2(hp[2]);
                        float2 f3 = __half22float2(hp[3]);
                        aA.x = fmaf(wt, f0.x, aA.x);
                        aA.y = fmaf(wt, f0.y, aA.y);
                        aA.z = fmaf(wt, f1.x, aA.z);
                        aA.w = fmaf(wt, f1.y, aA.w);
                        aB.x = fmaf(wt, f2.x, aB.x);
                        aB.y = fmaf(wt, f2.y, aB.y);
                        aB.z = fmaf(wt, f3.x, aB.z);
                        aB.w = fmaf(wt, f3.y, aB.w);
                    }
                }
            }
        }
        // reduce over dx (xor 1)
        aA.x += __shfl_xor_sync(0xffffffffu, aA.x, 1);
        aA.y += __shfl_xor_sync(0xffffffffu, aA.y, 1);
        aA.z += __shfl_xor_sync(0xffffffffu, aA.z, 1);
        aA.w += __shfl_xor_sync(0xffffffffu, aA.w, 1);
        aB.x += __shfl_xor_sync(0xffffffffu, aB.x, 1);
        aB.y += __shfl_xor_sync(0xffffffffu, aB.y, 1);
        aB.z += __shfl_xor_sync(0xffffffffu, aB.z, 1);
        aB.w += __shfl_xor_sync(0xffffffffu, aB.w, 1);
        if (dx == 0) {
            uint4 u;
            ((__half2*)&u)[0] = __floats2half2_rn(aA.x, aA.y);
            ((__half2*)&u)[1] = __floats2half2_rn(aA.z, aA.w);
            ((__half2*)&u)[2] = __floats2half2_rn(aB.x, aB.y);
            ((__half2*)&u)[3] = __floats2half2_rn(aB.z, aB.w);
            *(uint4*)(outp + v * CC + g * GCH + q2 * 8) = u;
        }
    }
    __syncthreads();

    // ---- phase 6: output projection on tensor cores (m16n8k16).
    // A rows 0..7 = voxels (outhA + outhB, fp16); 8 n-tiles, warp = tile.
    {
        int g = lane >> 2, tg = lane & 3;
        unsigned a0[4], a2[4];
        const __half* xa = outhA + g * CC;
        const __half* xb = outhB + g * CC;
#pragma unroll
        for (int ks = 0; ks < 4; ks++) {
            __half2 lo = __hadd2(*(const __half2*)(xa + ks * 16 + tg * 2),
                                 *(const __half2*)(xb + ks * 16 + tg * 2));
            __half2 hi = __hadd2(*(const __half2*)(xa + ks * 16 + 8 + tg * 2),
                                 *(const __half2*)(xb + ks * 16 + 8 + tg * 2));
            a0[ks] = *(unsigned*)&lo;
            a2[ks] = *(unsigned*)&hi;
        }
        int nt = warp;                             // 8 warps, 8 n-tiles
        float c0 = 0.f, c1 = 0.f, c2 = 0.f, c3 = 0.f;
#pragma unroll
        for (int ks = 0; ks < 4; ks++) {
            uint2 wq = g_wO[(nt * 4 + ks) * 32 + lane];
            asm volatile(
                "mma.sync.aligned.m16n8k16.row.col.f32.f16.f16.f32 "
                "{%0,%1,%2,%3},{%4,%5,%6,%7},{%8,%9},{%0,%1,%2,%3};"
                : "+f"(c0), "+f"(c1), "+f"(c2), "+f"(c3)
                : "r"(a0[ks]), "r"(0u), "r"(a2[ks]), "r"(0u),
                  "r"(wq.x), "r"(wq.y));
        }
        int n0 = nt * 8 + tg * 2;
        float2 bb = *(const float2*)(out_b + n0);
        *(float2*)(res + g * CC + n0) = make_float2(c0 + bb.x, c1 + bb.y);
    }
    __syncthreads();

    if (tid < 128)
        ((float4*)(out + (size_t)vb * CC))[tid] = ((const float4*)res)[tid];
}

extern "C" void kernel_launch(void* const* d_in, const int* in_sizes, int n_in,
                              void* d_out, int out_size)
{
    const float* input  = (const float*)d_in[0];
    const float* dw_w   = (const float*)d_in[1];
    const float* dw_b   = (const float*)d_in[2];
    const float* ln_g   = (const float*)d_in[3];
    const float* ln_b   = (const float*)d_in[4];
    const float* off_w  = (const float*)d_in[5];
    const float* off_b  = (const float*)d_in[6];
    const float* mask_w = (const float*)d_in[7];
    const float* mask_b = (const float*)d_in[8];
    const float* in_w   = (const float*)d_in[9];
    const float* in_b   = (const float*)d_in[10];
    const float* out_w  = (const float*)d_in[11];
    const float* out_b  = (const float*)d_in[12];
    float* out = (float*)d_out;

    int blocks = NB * DD * HH * WW / VX;               // 4096

    proj_pad_kernel<<<blocks, 256>>>(input, in_w, in_b, off_w, mask_w, out_w);
    dcnv3_fused_kernel<<<blocks, 256>>>(
        input, dw_w, dw_b, ln_g, ln_b,
        off_b, mask_b, out_b, out);
}